// round 2
// baseline (speedup 1.0000x reference)
#include <cuda_runtime.h>
#include <math.h>

#define NBATCH 2
#define TSEQ   2048
#define EMB    1024
#define NHEAD  16
#define HDIM   64
#define NTOK   (NBATCH*TSEQ)   // 4096

// Scratch (allocation-free): Q,K,V as [B,H,T,D]; C (attn combined) as [B,T,E]
__device__ float g_q[NBATCH*NHEAD*TSEQ*HDIM];
__device__ float g_k[NBATCH*NHEAD*TSEQ*HDIM];
__device__ float g_v[NBATCH*NHEAD*TSEQ*HDIM];
__device__ float g_c[NBATCH*TSEQ*EMB];

__device__ __forceinline__ void fma4x4(float acc[4][4], float4 a, float4 b) {
    float av[4] = {a.x, a.y, a.z, a.w};
    float bv[4] = {b.x, b.y, b.z, b.w};
    #pragma unroll
    for (int i = 0; i < 4; i++)
        #pragma unroll
        for (int j = 0; j < 4; j++)
            acc[i][j] = fmaf(av[i], bv[j], acc[i][j]);
}

// ---------------------------------------------------------------------------
// Kernel 1: QKV projection. grid = (NTOK/64, NHEAD, 3), 256 threads.
// Output tile: 64 tokens x 64 dims (full head dim), K = 1024 in chunks of 32.
// ---------------------------------------------------------------------------
__global__ __launch_bounds__(256) void qkv_kernel(
    const float* __restrict__ x, const float* __restrict__ Wq,
    const float* __restrict__ Wk, const float* __restrict__ Wv)
{
    __shared__ float As[32][68];   // x tile transposed: [k][token]
    __shared__ float Bs[32][68];   // W tile direct:     [k][n]
    const int mt = blockIdx.x, h = blockIdx.y, which = blockIdx.z;
    const float* W = (which == 0 ? Wq : which == 1 ? Wk : Wv) + (size_t)h * EMB * HDIM;
    float* out = (which == 0 ? g_q : which == 1 ? g_k : g_v);
    const int tid = threadIdx.x, ty = tid >> 4, tx = tid & 15;
    const int m0 = mt * 64;
    float acc[4][4] = {};
    for (int k0 = 0; k0 < EMB; k0 += 32) {
        #pragma unroll
        for (int i = tid; i < 64 * 32; i += 256) {
            int t = i >> 5, k = i & 31;
            As[k][t] = x[(size_t)(m0 + t) * EMB + k0 + k];
        }
        #pragma unroll
        for (int i = tid; i < 32 * 64; i += 256) {
            int k = i >> 6, n = i & 63;
            Bs[k][n] = W[(size_t)(k0 + k) * HDIM + n];
        }
        __syncthreads();
        #pragma unroll 8
        for (int kk = 0; kk < 32; kk++) {
            float4 a = *(const float4*)&As[kk][ty * 4];
            float4 b = *(const float4*)&Bs[kk][tx * 4];
            fma4x4(acc, a, b);
        }
        __syncthreads();
    }
    #pragma unroll
    for (int i = 0; i < 4; i++) {
        int m = m0 + ty * 4 + i;
        int b = m >> 11, t = m & (TSEQ - 1);
        float4 v4 = make_float4(acc[i][0], acc[i][1], acc[i][2], acc[i][3]);
        *(float4*)&out[((size_t)((b * NHEAD + h) * TSEQ + t)) * HDIM + tx * 4] = v4;
    }
}

// ---------------------------------------------------------------------------
// Kernel 2: flash attention. grid = (TSEQ/64, NHEAD, NBATCH), 256 threads.
// Dynamic smem: Qts[64][68] + Kts[64][68] + Vs[64][68] + Pts[64][68] = 69632 B
// ---------------------------------------------------------------------------
__global__ __launch_bounds__(256) void attn_kernel()
{
    extern __shared__ float sm[];
    float (*Qts)[68] = (float(*)[68])(sm);               // [d][row]
    float (*Kts)[68] = (float(*)[68])(sm + 64 * 68);     // [d][key]
    float (*Vs )[68] = (float(*)[68])(sm + 2 * 64 * 68); // [key][d]
    float (*Pts)[68] = (float(*)[68])(sm + 3 * 64 * 68); // [key][row]

    const int qt = blockIdx.x, h = blockIdx.y, b = blockIdx.z;
    const size_t base = (size_t)((b * NHEAD + h) * TSEQ) * HDIM;
    const float* Q = g_q + base;
    const float* K = g_k + base;
    const float* V = g_v + base;
    const int tid = threadIdx.x, ty = tid >> 4, tx = tid & 15;

    // Q tile transposed (covered by the first in-loop barrier)
    for (int i = tid; i < 64 * 64; i += 256) {
        int r = i >> 6, d = i & 63;
        Qts[d][r] = Q[(size_t)(qt * 64 + r) * HDIM + d];
    }

    float m_r[4], l_r[4], o[4][4];
    #pragma unroll
    for (int i = 0; i < 4; i++) {
        m_r[i] = -INFINITY; l_r[i] = 0.f;
        #pragma unroll
        for (int j = 0; j < 4; j++) o[i][j] = 0.f;
    }

    for (int kt = 0; kt < TSEQ / 64; kt++) {
        for (int i = tid; i < 64 * 64; i += 256) {
            int c = i >> 6, d = i & 63;
            size_t g = (size_t)(kt * 64 + c) * HDIM + d;
            Kts[d][c] = K[g];
            Vs[c][d]  = V[g];
        }
        __syncthreads();

        // S = (Q K^T) * scale
        float s[4][4] = {};
        #pragma unroll 8
        for (int d = 0; d < 64; d++) {
            float4 a = *(const float4*)&Qts[d][ty * 4];
            float4 bb = *(const float4*)&Kts[d][tx * 4];
            fma4x4(s, a, bb);
        }

        // online softmax update (16-lane row-group shuffle reductions)
        #pragma unroll
        for (int i = 0; i < 4; i++) {
            #pragma unroll
            for (int j = 0; j < 4; j++) s[i][j] *= 0.125f;  // 1/sqrt(64)
            float tm = fmaxf(fmaxf(s[i][0], s[i][1]), fmaxf(s[i][2], s[i][3]));
            tm = fmaxf(tm, __shfl_xor_sync(0xffffffffu, tm, 1));
            tm = fmaxf(tm, __shfl_xor_sync(0xffffffffu, tm, 2));
            tm = fmaxf(tm, __shfl_xor_sync(0xffffffffu, tm, 4));
            tm = fmaxf(tm, __shfl_xor_sync(0xffffffffu, tm, 8));
            float mnew = fmaxf(m_r[i], tm);
            float alpha = __expf(m_r[i] - mnew);
            float rs = 0.f;
            #pragma unroll
            for (int j = 0; j < 4; j++) {
                float p = __expf(s[i][j] - mnew);
                s[i][j] = p; rs += p;
            }
            rs += __shfl_xor_sync(0xffffffffu, rs, 1);
            rs += __shfl_xor_sync(0xffffffffu, rs, 2);
            rs += __shfl_xor_sync(0xffffffffu, rs, 4);
            rs += __shfl_xor_sync(0xffffffffu, rs, 8);
            l_r[i] = l_r[i] * alpha + rs;
            m_r[i] = mnew;
            #pragma unroll
            for (int j = 0; j < 4; j++) o[i][j] *= alpha;
        }

        // P -> shared (transposed: [key][row])
        #pragma unroll
        for (int i = 0; i < 4; i++)
            #pragma unroll
            for (int j = 0; j < 4; j++)
                Pts[tx * 4 + j][ty * 4 + i] = s[i][j];
        __syncthreads();

        // O += P @ V
        #pragma unroll 8
        for (int j = 0; j < 64; j++) {
            float4 a = *(const float4*)&Pts[j][ty * 4];
            float4 bv = *(const float4*)&Vs[j][tx * 4];
            fma4x4(o, a, bv);
        }
        __syncthreads();
    }

    // epilogue: normalize, write combined [B,T, h*64+d]
    #pragma unroll
    for (int i = 0; i < 4; i++) {
        int t = qt * 64 + ty * 4 + i;
        float inv = 1.f / l_r[i];
        float4 v4 = make_float4(o[i][0] * inv, o[i][1] * inv, o[i][2] * inv, o[i][3] * inv);
        *(float4*)&g_c[((size_t)(b * TSEQ + t)) * EMB + h * HDIM + tx * 4] = v4;
    }
}

// ---------------------------------------------------------------------------
// Kernel 3: out = x + C @ Wo^T. grid = (NTOK/64, EMB/64), 256 threads.
// ---------------------------------------------------------------------------
__global__ __launch_bounds__(256) void outproj_kernel(
    const float* __restrict__ x, const float* __restrict__ Wo,
    float* __restrict__ out)
{
    __shared__ float As[32][68];   // C tile transposed:  [k][token]
    __shared__ float Bs[32][68];   // Wo tile transposed: [k][outdim]
    const int mt = blockIdx.x, nt = blockIdx.y;
    const int tid = threadIdx.x, ty = tid >> 4, tx = tid & 15;
    const int m0 = mt * 64, n0 = nt * 64;
    float acc[4][4] = {};
    for (int k0 = 0; k0 < EMB; k0 += 32) {
        #pragma unroll
        for (int i = tid; i < 64 * 32; i += 256) {
            int t = i >> 5, k = i & 31;
            As[k][t] = g_c[(size_t)(m0 + t) * EMB + k0 + k];
            Bs[k][t] = Wo[(size_t)(n0 + t) * EMB + k0 + k];
        }
        __syncthreads();
        #pragma unroll 8
        for (int kk = 0; kk < 32; kk++) {
            float4 a = *(const float4*)&As[kk][ty * 4];
            float4 b = *(const float4*)&Bs[kk][tx * 4];
            fma4x4(acc, a, b);
        }
        __syncthreads();
    }
    #pragma unroll
    for (int i = 0; i < 4; i++) {
        size_t row = (size_t)(m0 + ty * 4 + i) * EMB + n0 + tx * 4;
        float4 xv = *(const float4*)&x[row];
        float4 v4 = make_float4(acc[i][0] + xv.x, acc[i][1] + xv.y,
                                acc[i][2] + xv.z, acc[i][3] + xv.w);
        *(float4*)&out[row] = v4;
    }
}

extern "C" void kernel_launch(void* const* d_in, const int* in_sizes, int n_in,
                              void* d_out, int out_size)
{
    const float* x  = (const float*)d_in[0];
    const float* Wq = (const float*)d_in[1];
    const float* Wk = (const float*)d_in[2];
    const float* Wv = (const float*)d_in[3];
    const float* Wo = (const float*)d_in[4];
    float* out = (float*)d_out;

    dim3 g1(NTOK / 64, NHEAD, 3);
    qkv_kernel<<<g1, 256>>>(x, Wq, Wk, Wv);

    const int attn_smem = 4 * 64 * 68 * sizeof(float);  // 69632 B
    cudaFuncSetAttribute(attn_kernel, cudaFuncAttributeMaxDynamicSharedMemorySize, attn_smem);
    dim3 g2(TSEQ / 64, NHEAD, NBATCH);
    attn_kernel<<<g2, 256, attn_smem>>>();

    dim3 g3(NTOK / 64, EMB / 64);
    outproj_kernel<<<g3, 256>>>(x, Wo, out);
}

// round 9
// speedup vs baseline: 1.1954x; 1.1954x over previous
#include <cuda_runtime.h>
#include <math.h>
#include <stdint.h>

#define NBATCH 2
#define TSEQ   2048
#define EMB    1024
#define NHEAD  16
#define HDIM   64
#define NTOK   (NBATCH*TSEQ)   // 4096

// Scratch (allocation-free): Q,K,V as [B,H,T,D]; C (attn combined) as [B,T,E]
__device__ float g_q[NBATCH*NHEAD*TSEQ*HDIM];
__device__ float g_k[NBATCH*NHEAD*TSEQ*HDIM];
__device__ float g_v[NBATCH*NHEAD*TSEQ*HDIM];
__device__ float g_c[NBATCH*TSEQ*EMB];

// ===========================================================================
// Helpers (sm_80-base ISA only: mma.sync tf32, cp.async, cvt.rna.tf32)
// ===========================================================================
__device__ __forceinline__ uint32_t smem_u32(const void* p) {
    uint32_t a;
    asm("{ .reg .u64 t; cvta.to.shared.u64 t, %1; cvt.u32.u64 %0, t; }" : "=r"(a) : "l"(p));
    return a;
}
__device__ __forceinline__ float tf32_hi(float x) {
    uint32_t u;
    asm("cvt.rna.tf32.f32 %0, %1;" : "=r"(u) : "f"(x));
    return __uint_as_float(u);
}
#define CP_ASYNC16(dst, src) asm volatile("cp.async.cg.shared.global [%0], [%1], 16;" :: "r"(dst), "l"(src))
#define CP_COMMIT()          asm volatile("cp.async.commit_group;" ::: "memory")
#define CP_WAIT0()           asm volatile("cp.async.wait_group 0;" ::: "memory")
#define CP_WAIT1()           asm volatile("cp.async.wait_group 1;" ::: "memory")

// m16n8k8 tf32 MMA, D += A*B (row.col), accumulate in place
__device__ __forceinline__ void mma_tf32(float* d, const uint32_t* a, const uint32_t* b) {
    asm volatile("mma.sync.aligned.m16n8k8.row.col.f32.tf32.tf32.f32 "
        "{%0,%1,%2,%3}, {%4,%5,%6,%7}, {%8,%9}, {%0,%1,%2,%3};"
        : "+f"(d[0]), "+f"(d[1]), "+f"(d[2]), "+f"(d[3])
        : "r"(a[0]), "r"(a[1]), "r"(a[2]), "r"(a[3]), "r"(b[0]), "r"(b[1]));
}

// hi/lo split of an f32 into two tf32 values (3-pass: AhBh + AhBl + AlBh)
__device__ __forceinline__ void split_tf32(float v, uint32_t& hi, uint32_t& lo) {
    float h = tf32_hi(v);
    hi = __float_as_uint(h);
    lo = __float_as_uint(tf32_hi(v - h));
}

#define KCHUNK 32
#define NCHUNK (EMB / KCHUNK)   // 32

// ---------------------------------------------------------------------------
// Kernel 1: QKV projection via mma.sync tf32 3-pass.
// grid = (NTOK/128, NHEAD, 3), 256 threads (8 warps), block tile 128x64.
// smem per buffer: A raw [128][36] (4608 f) + W raw [32][68] (2176 f) = 27136 B
// ---------------------------------------------------------------------------
#define QKV_BUF_F   6784
#define QKV_BUF_B   (QKV_BUF_F * 4)          // 27136
#define QKV_SMEM    (2 * QKV_BUF_B)          // 54272

__device__ __forceinline__ void qkv_stage(uint32_t sbuf, const float* x, const float* W,
                                          int m0, int k0, int tid) {
    #pragma unroll
    for (int j = 0; j < 4; j++) {            // A: 1024 quads
        int idx = j * 256 + tid;
        int r = idx >> 3, q = idx & 7;
        CP_ASYNC16(sbuf + (uint32_t)(r * 36 + q * 4) * 4u,
                   &x[(size_t)(m0 + r) * EMB + k0 + q * 4]);
    }
    #pragma unroll
    for (int j = 0; j < 2; j++) {            // B: 512 quads ([k][n], 32x64)
        int idx = j * 256 + tid;
        int k = idx >> 4, q = idx & 15;
        CP_ASYNC16(sbuf + (uint32_t)(4608 + k * 68 + q * 4) * 4u,
                   &W[(size_t)(k0 + k) * HDIM + q * 4]);
    }
    CP_COMMIT();
}

__global__ __launch_bounds__(256) void qkv_mma_kernel(
    const float* __restrict__ x, const float* __restrict__ Wq,
    const float* __restrict__ Wk, const float* __restrict__ Wv)
{
    extern __shared__ __align__(16) float sm[];
    const uint32_t sb = smem_u32(sm);
    const int tid = threadIdx.x;
    const int lane = tid & 31, wid = tid >> 5;
    const int gid = lane >> 2, tig = lane & 3;
    const int warp_m = wid >> 1, warp_n = wid & 1;
    const int m0 = blockIdx.x * 128, h = blockIdx.y, which = blockIdx.z;
    const float* W = (which == 0 ? Wq : which == 1 ? Wk : Wv) + (size_t)h * EMB * HDIM;
    float* out = (which == 0 ? g_q : which == 1 ? g_k : g_v);

    float acc[2][4][4];
    #pragma unroll
    for (int mt = 0; mt < 2; mt++)
        #pragma unroll
        for (int nt = 0; nt < 4; nt++)
            #pragma unroll
            for (int e = 0; e < 4; e++) acc[mt][nt][e] = 0.f;

    qkv_stage(sb, x, W, m0, 0, tid);

    for (int ch = 0; ch < NCHUNK; ch++) {
        if (ch + 1 < NCHUNK) {
            qkv_stage(sb + ((ch + 1) & 1) * QKV_BUF_B, x, W, m0, (ch + 1) * KCHUNK, tid);
            CP_WAIT1();
        } else {
            CP_WAIT0();
        }
        __syncthreads();

        const float* As = sm + (ch & 1) * QKV_BUF_F;
        const float* Bs = As + 4608;

        #pragma unroll
        for (int ks = 0; ks < 4; ks++) {
            uint32_t ah[2][4], al[2][4], bh[4][2], bl[4][2];
            #pragma unroll
            for (int mt = 0; mt < 2; mt++) {
                int r = warp_m * 32 + mt * 16 + gid;
                int c = ks * 8 + tig;
                split_tf32(As[r * 36 + c],           ah[mt][0], al[mt][0]);
                split_tf32(As[(r + 8) * 36 + c],     ah[mt][1], al[mt][1]);
                split_tf32(As[r * 36 + c + 4],       ah[mt][2], al[mt][2]);
                split_tf32(As[(r + 8) * 36 + c + 4], ah[mt][3], al[mt][3]);
            }
            #pragma unroll
            for (int nt = 0; nt < 4; nt++) {
                int nn = warp_n * 32 + nt * 8 + gid;
                int kk = ks * 8 + tig;
                split_tf32(Bs[kk * 68 + nn],       bh[nt][0], bl[nt][0]);
                split_tf32(Bs[(kk + 4) * 68 + nn], bh[nt][1], bl[nt][1]);
            }
            #pragma unroll
            for (int mt = 0; mt < 2; mt++)
                #pragma unroll
                for (int nt = 0; nt < 4; nt++) {
                    mma_tf32(acc[mt][nt], ah[mt], bh[nt]);
                    mma_tf32(acc[mt][nt], ah[mt], bl[nt]);
                    mma_tf32(acc[mt][nt], al[mt], bh[nt]);
                }
        }
        __syncthreads();
    }

    // epilogue -> out[(b*H+h)*T + t][d]
    #pragma unroll
    for (int mt = 0; mt < 2; mt++)
        #pragma unroll
        for (int nt = 0; nt < 4; nt++) {
            int n = warp_n * 32 + nt * 8 + tig * 2;
            int m = m0 + warp_m * 32 + mt * 16 + gid;
            int b = m >> 11, t = m & (TSEQ - 1);
            float2 v0 = make_float2(acc[mt][nt][0], acc[mt][nt][1]);
            *(float2*)&out[((size_t)((b * NHEAD + h) * TSEQ + t)) * HDIM + n] = v0;
            int m2 = m + 8;
            b = m2 >> 11; t = m2 & (TSEQ - 1);
            float2 v1 = make_float2(acc[mt][nt][2], acc[mt][nt][3]);
            *(float2*)&out[((size_t)((b * NHEAD + h) * TSEQ + t)) * HDIM + n] = v1;
        }
}

// ---------------------------------------------------------------------------
// Kernel 3: out = x + C @ Wo^T via mma.sync tf32 3-pass.
// grid = (NTOK/128, EMB/64), 256 threads. Wo [N=1024][K=1024] K-contiguous.
// smem per buffer: A [128][36] (4608 f) + B [64][36] (2304 f) = 27648 B
// ---------------------------------------------------------------------------
#define OP_BUF_F   6912
#define OP_BUF_B   (OP_BUF_F * 4)            // 27648
#define OP_SMEM    (2 * OP_BUF_B)            // 55296

__device__ __forceinline__ void op_stage(uint32_t sbuf, const float* Wo,
                                         int m0, int n0, int k0, int tid) {
    #pragma unroll
    for (int j = 0; j < 4; j++) {            // A: 1024 quads from g_c
        int idx = j * 256 + tid;
        int r = idx >> 3, q = idx & 7;
        CP_ASYNC16(sbuf + (uint32_t)(r * 36 + q * 4) * 4u,
                   &g_c[(size_t)(m0 + r) * EMB + k0 + q * 4]);
    }
    #pragma unroll
    for (int j = 0; j < 2; j++) {            // B: 512 quads ([n][k], 64x32)
        int idx = j * 256 + tid;
        int n = idx >> 3, q = idx & 7;
        CP_ASYNC16(sbuf + (uint32_t)(4608 + n * 36 + q * 4) * 4u,
                   &Wo[(size_t)(n0 + n) * EMB + k0 + q * 4]);
    }
    CP_COMMIT();
}

__global__ __launch_bounds__(256) void outproj_mma_kernel(
    const float* __restrict__ x, const float* __restrict__ Wo,
    float* __restrict__ out)
{
    extern __shared__ __align__(16) float sm[];
    const uint32_t sb = smem_u32(sm);
    const int tid = threadIdx.x;
    const int lane = tid & 31, wid = tid >> 5;
    const int gid = lane >> 2, tig = lane & 3;
    const int warp_m = wid >> 1, warp_n = wid & 1;
    const int m0 = blockIdx.x * 128, n0 = blockIdx.y * 64;

    float acc[2][4][4];
    #pragma unroll
    for (int mt = 0; mt < 2; mt++)
        #pragma unroll
        for (int nt = 0; nt < 4; nt++)
            #pragma unroll
            for (int e = 0; e < 4; e++) acc[mt][nt][e] = 0.f;

    op_stage(sb, Wo, m0, n0, 0, tid);

    for (int ch = 0; ch < NCHUNK; ch++) {
        if (ch + 1 < NCHUNK) {
            op_stage(sb + ((ch + 1) & 1) * OP_BUF_B, Wo, m0, n0, (ch + 1) * KCHUNK, tid);
            CP_WAIT1();
        } else {
            CP_WAIT0();
        }
        __syncthreads();

        const float* As = sm + (ch & 1) * OP_BUF_F;
        const float* Bs = As + 4608;

        #pragma unroll
        for (int ks = 0; ks < 4; ks++) {
            uint32_t ah[2][4], al[2][4], bh[4][2], bl[4][2];
            #pragma unroll
            for (int mt = 0; mt < 2; mt++) {
                int r = warp_m * 32 + mt * 16 + gid;
                int c = ks * 8 + tig;
                split_tf32(As[r * 36 + c],           ah[mt][0], al[mt][0]);
                split_tf32(As[(r + 8) * 36 + c],     ah[mt][1], al[mt][1]);
                split_tf32(As[r * 36 + c + 4],       ah[mt][2], al[mt][2]);
                split_tf32(As[(r + 8) * 36 + c + 4], ah[mt][3], al[mt][3]);
            }
            #pragma unroll
            for (int nt = 0; nt < 4; nt++) {
                int nn = warp_n * 32 + nt * 8 + gid;
                int kk = ks * 8 + tig;
                split_tf32(Bs[nn * 36 + kk],     bh[nt][0], bl[nt][0]);
                split_tf32(Bs[nn * 36 + kk + 4], bh[nt][1], bl[nt][1]);
            }
            #pragma unroll
            for (int mt = 0; mt < 2; mt++)
                #pragma unroll
                for (int nt = 0; nt < 4; nt++) {
                    mma_tf32(acc[mt][nt], ah[mt], bh[nt]);
                    mma_tf32(acc[mt][nt], ah[mt], bl[nt]);
                    mma_tf32(acc[mt][nt], al[mt], bh[nt]);
                }
        }
        __syncthreads();
    }

    // epilogue: residual add + store
    #pragma unroll
    for (int mt = 0; mt < 2; mt++)
        #pragma unroll
        for (int nt = 0; nt < 4; nt++) {
            int n = n0 + warp_n * 32 + nt * 8 + tig * 2;
            int m = m0 + warp_m * 32 + mt * 16 + gid;
            {
                size_t off = (size_t)m * EMB + n;
                float2 xv = *(const float2*)&x[off];
                *(float2*)&out[off] = make_float2(acc[mt][nt][0] + xv.x, acc[mt][nt][1] + xv.y);
            }
            {
                size_t off = (size_t)(m + 8) * EMB + n;
                float2 xv = *(const float2*)&x[off];
                *(float2*)&out[off] = make_float2(acc[mt][nt][2] + xv.x, acc[mt][nt][3] + xv.y);
            }
        }
}

// ---------------------------------------------------------------------------
// Kernel 2: flash attention (unchanged, known-passing).
// grid = (TSEQ/64, NHEAD, NBATCH), 256 threads, 69632 B dynamic smem.
// ---------------------------------------------------------------------------
__device__ __forceinline__ void fma4x4(float acc[4][4], float4 a, float4 b) {
    float av[4] = {a.x, a.y, a.z, a.w};
    float bv[4] = {b.x, b.y, b.z, b.w};
    #pragma unroll
    for (int i = 0; i < 4; i++)
        #pragma unroll
        for (int j = 0; j < 4; j++)
            acc[i][j] = fmaf(av[i], bv[j], acc[i][j]);
}

__global__ __launch_bounds__(256) void attn_kernel()
{
    extern __shared__ float smf[];
    float (*Qts)[68] = (float(*)[68])(smf);
    float (*Kts)[68] = (float(*)[68])(smf + 64 * 68);
    float (*Vs )[68] = (float(*)[68])(smf + 2 * 64 * 68);
    float (*Pts)[68] = (float(*)[68])(smf + 3 * 64 * 68);

    const int qt = blockIdx.x, h = blockIdx.y, b = blockIdx.z;
    const size_t base = (size_t)((b * NHEAD + h) * TSEQ) * HDIM;
    const float* Q = g_q + base;
    const float* K = g_k + base;
    const float* V = g_v + base;
    const int tid = threadIdx.x, ty = tid >> 4, tx = tid & 15;

    for (int i = tid; i < 64 * 64; i += 256) {
        int r = i >> 6, d = i & 63;
        Qts[d][r] = Q[(size_t)(qt * 64 + r) * HDIM + d];
    }

    float m_r[4], l_r[4], o[4][4];
    #pragma unroll
    for (int i = 0; i < 4; i++) {
        m_r[i] = -INFINITY; l_r[i] = 0.f;
        #pragma unroll
        for (int j = 0; j < 4; j++) o[i][j] = 0.f;
    }

    for (int kt = 0; kt < TSEQ / 64; kt++) {
        for (int i = tid; i < 64 * 64; i += 256) {
            int c = i >> 6, d = i & 63;
            size_t g = (size_t)(kt * 64 + c) * HDIM + d;
            Kts[d][c] = K[g];
            Vs[c][d]  = V[g];
        }
        __syncthreads();

        float s[4][4] = {};
        #pragma unroll 8
        for (int d = 0; d < 64; d++) {
            float4 a = *(const float4*)&Qts[d][ty * 4];
            float4 bb = *(const float4*)&Kts[d][tx * 4];
            fma4x4(s, a, bb);
        }

        #pragma unroll
        for (int i = 0; i < 4; i++) {
            #pragma unroll
            for (int j = 0; j < 4; j++) s[i][j] *= 0.125f;
            float tm = fmaxf(fmaxf(s[i][0], s[i][1]), fmaxf(s[i][2], s[i][3]));
            tm = fmaxf(tm, __shfl_xor_sync(0xffffffffu, tm, 1));
            tm = fmaxf(tm, __shfl_xor_sync(0xffffffffu, tm, 2));
            tm = fmaxf(tm, __shfl_xor_sync(0xffffffffu, tm, 4));
            tm = fmaxf(tm, __shfl_xor_sync(0xffffffffu, tm, 8));
            float mnew = fmaxf(m_r[i], tm);
            float alpha = __expf(m_r[i] - mnew);
            float rs = 0.f;
            #pragma unroll
            for (int j = 0; j < 4; j++) {
                float p = __expf(s[i][j] - mnew);
                s[i][j] = p; rs += p;
            }
            rs += __shfl_xor_sync(0xffffffffu, rs, 1);
            rs += __shfl_xor_sync(0xffffffffu, rs, 2);
            rs += __shfl_xor_sync(0xffffffffu, rs, 4);
            rs += __shfl_xor_sync(0xffffffffu, rs, 8);
            l_r[i] = l_r[i] * alpha + rs;
            m_r[i] = mnew;
            #pragma unroll
            for (int j = 0; j < 4; j++) o[i][j] *= alpha;
        }

        #pragma unroll
        for (int i = 0; i < 4; i++)
            #pragma unroll
            for (int j = 0; j < 4; j++)
                Pts[tx * 4 + j][ty * 4 + i] = s[i][j];
        __syncthreads();

        #pragma unroll 8
        for (int j = 0; j < 64; j++) {
            float4 a = *(const float4*)&Pts[j][ty * 4];
            float4 bv = *(const float4*)&Vs[j][tx * 4];
            fma4x4(o, a, bv);
        }
        __syncthreads();
    }

    #pragma unroll
    for (int i = 0; i < 4; i++) {
        int t = qt * 64 + ty * 4 + i;
        float inv = 1.f / l_r[i];
        float4 v4 = make_float4(o[i][0] * inv, o[i][1] * inv, o[i][2] * inv, o[i][3] * inv);
        *(float4*)&g_c[((size_t)(b * TSEQ + t)) * EMB + h * HDIM + tx * 4] = v4;
    }
}

extern "C" void kernel_launch(void* const* d_in, const int* in_sizes, int n_in,
                              void* d_out, int out_size)
{
    const float* x  = (const float*)d_in[0];
    const float* Wq = (const float*)d_in[1];
    const float* Wk = (const float*)d_in[2];
    const float* Wv = (const float*)d_in[3];
    const float* Wo = (const float*)d_in[4];
    float* out = (float*)d_out;

    cudaFuncSetAttribute(qkv_mma_kernel, cudaFuncAttributeMaxDynamicSharedMemorySize, QKV_SMEM);
    cudaFuncSetAttribute(outproj_mma_kernel, cudaFuncAttributeMaxDynamicSharedMemorySize, OP_SMEM);

    dim3 g1(NTOK / 128, NHEAD, 3);
    qkv_mma_kernel<<<g1, 256, QKV_SMEM>>>(x, Wq, Wk, Wv);

    const int attn_smem = 4 * 64 * 68 * sizeof(float);  // 69632 B
    cudaFuncSetAttribute(attn_kernel, cudaFuncAttributeMaxDynamicSharedMemorySize, attn_smem);
    dim3 g2(TSEQ / 64, NHEAD, NBATCH);
    attn_kernel<<<g2, 256, attn_smem>>>();

    dim3 g3(NTOK / 128, EMB / 64);
    outproj_mma_kernel<<<g3, 256, OP_SMEM>>>(x, Wo, out);
}

// round 10
// speedup vs baseline: 1.3875x; 1.1607x over previous
#include <cuda_runtime.h>
#include <math.h>
#include <stdint.h>

#define NBATCH 2
#define TSEQ   2048
#define EMB    1024
#define NHEAD  16
#define HDIM   64
#define NTOK   (NBATCH*TSEQ)   // 4096

// Scratch (allocation-free): Q,K,V as [B,H,T,D]; C (attn combined) as [B,T,E]
__device__ float g_q[NBATCH*NHEAD*TSEQ*HDIM];
__device__ float g_k[NBATCH*NHEAD*TSEQ*HDIM];
__device__ float g_v[NBATCH*NHEAD*TSEQ*HDIM];
__device__ float g_c[NBATCH*TSEQ*EMB];

// ===========================================================================
// Helpers (sm_80-base ISA: mma.sync tf32, cp.async, cvt.rna.tf32)
// ===========================================================================
__device__ __forceinline__ uint32_t smem_u32(const void* p) {
    uint32_t a;
    asm("{ .reg .u64 t; cvta.to.shared.u64 t, %1; cvt.u32.u64 %0, t; }" : "=r"(a) : "l"(p));
    return a;
}
__device__ __forceinline__ float tf32_hi(float x) {
    uint32_t u;
    asm("cvt.rna.tf32.f32 %0, %1;" : "=r"(u) : "f"(x));
    return __uint_as_float(u);
}
#define CP_ASYNC16(dst, src) asm volatile("cp.async.cg.shared.global [%0], [%1], 16;" :: "r"(dst), "l"(src))
#define CP_COMMIT()          asm volatile("cp.async.commit_group;" ::: "memory")
#define CP_WAIT0()           asm volatile("cp.async.wait_group 0;" ::: "memory")
#define CP_WAIT1()           asm volatile("cp.async.wait_group 1;" ::: "memory")

__device__ __forceinline__ void mma_tf32(float* d, const uint32_t* a, const uint32_t* b) {
    asm volatile("mma.sync.aligned.m16n8k8.row.col.f32.tf32.tf32.f32 "
        "{%0,%1,%2,%3}, {%4,%5,%6,%7}, {%8,%9}, {%0,%1,%2,%3};"
        : "+f"(d[0]), "+f"(d[1]), "+f"(d[2]), "+f"(d[3])
        : "r"(a[0]), "r"(a[1]), "r"(a[2]), "r"(a[3]), "r"(b[0]), "r"(b[1]));
}
__device__ __forceinline__ void split_tf32(float v, uint32_t& hi, uint32_t& lo) {
    float h = tf32_hi(v);
    hi = __float_as_uint(h);
    lo = __float_as_uint(tf32_hi(v - h));
}

// exp2 via degree-5 polynomial, all on the fma/alu pipes (no MUFU).
// Valid for y <= ~0 (softmax arguments); clamps at -126 for denormal safety.
__device__ __forceinline__ float exp2p(float y) {
    y = fmaxf(y, -126.f);
    float r = rintf(y);
    float f = y - r;                         // f in [-0.5, 0.5]
    float p = fmaf(f, 1.3333558146e-3f, 9.6181291076e-3f);
    p = fmaf(f, p, 5.5504108664e-2f);
    p = fmaf(f, p, 2.4022650696e-1f);
    p = fmaf(f, p, 6.9314718056e-1f);
    p = fmaf(f, p, 1.0f);
    int n = (int)r;
    return p * __int_as_float((n + 127) << 23);
}

#define KCHUNK 32
#define NCHUNK (EMB / KCHUNK)   // 32

// ---------------------------------------------------------------------------
// Kernel 1: QKV projection via mma.sync tf32 3-pass (unchanged from R9).
// ---------------------------------------------------------------------------
#define QKV_BUF_F   6784
#define QKV_BUF_B   (QKV_BUF_F * 4)
#define QKV_SMEM    (2 * QKV_BUF_B)

__device__ __forceinline__ void qkv_stage(uint32_t sbuf, const float* x, const float* W,
                                          int m0, int k0, int tid) {
    #pragma unroll
    for (int j = 0; j < 4; j++) {
        int idx = j * 256 + tid;
        int r = idx >> 3, q = idx & 7;
        CP_ASYNC16(sbuf + (uint32_t)(r * 36 + q * 4) * 4u,
                   &x[(size_t)(m0 + r) * EMB + k0 + q * 4]);
    }
    #pragma unroll
    for (int j = 0; j < 2; j++) {
        int idx = j * 256 + tid;
        int k = idx >> 4, q = idx & 15;
        CP_ASYNC16(sbuf + (uint32_t)(4608 + k * 68 + q * 4) * 4u,
                   &W[(size_t)(k0 + k) * HDIM + q * 4]);
    }
    CP_COMMIT();
}

__global__ __launch_bounds__(256) void qkv_mma_kernel(
    const float* __restrict__ x, const float* __restrict__ Wq,
    const float* __restrict__ Wk, const float* __restrict__ Wv)
{
    extern __shared__ __align__(16) float sm[];
    const uint32_t sb = smem_u32(sm);
    const int tid = threadIdx.x;
    const int lane = tid & 31, wid = tid >> 5;
    const int gid = lane >> 2, tig = lane & 3;
    const int warp_m = wid >> 1, warp_n = wid & 1;
    const int m0 = blockIdx.x * 128, h = blockIdx.y, which = blockIdx.z;
    const float* W = (which == 0 ? Wq : which == 1 ? Wk : Wv) + (size_t)h * EMB * HDIM;
    float* out = (which == 0 ? g_q : which == 1 ? g_k : g_v);

    float acc[2][4][4];
    #pragma unroll
    for (int mt = 0; mt < 2; mt++)
        #pragma unroll
        for (int nt = 0; nt < 4; nt++)
            #pragma unroll
            for (int e = 0; e < 4; e++) acc[mt][nt][e] = 0.f;

    qkv_stage(sb, x, W, m0, 0, tid);

    for (int ch = 0; ch < NCHUNK; ch++) {
        if (ch + 1 < NCHUNK) {
            qkv_stage(sb + ((ch + 1) & 1) * QKV_BUF_B, x, W, m0, (ch + 1) * KCHUNK, tid);
            CP_WAIT1();
        } else {
            CP_WAIT0();
        }
        __syncthreads();

        const float* As = sm + (ch & 1) * QKV_BUF_F;
        const float* Bs = As + 4608;

        #pragma unroll
        for (int ks = 0; ks < 4; ks++) {
            uint32_t ah[2][4], al[2][4], bh[4][2], bl[4][2];
            #pragma unroll
            for (int mt = 0; mt < 2; mt++) {
                int r = warp_m * 32 + mt * 16 + gid;
                int c = ks * 8 + tig;
                split_tf32(As[r * 36 + c],           ah[mt][0], al[mt][0]);
                split_tf32(As[(r + 8) * 36 + c],     ah[mt][1], al[mt][1]);
                split_tf32(As[r * 36 + c + 4],       ah[mt][2], al[mt][2]);
                split_tf32(As[(r + 8) * 36 + c + 4], ah[mt][3], al[mt][3]);
            }
            #pragma unroll
            for (int nt = 0; nt < 4; nt++) {
                int nn = warp_n * 32 + nt * 8 + gid;
                int kk = ks * 8 + tig;
                split_tf32(Bs[kk * 68 + nn],       bh[nt][0], bl[nt][0]);
                split_tf32(Bs[(kk + 4) * 68 + nn], bh[nt][1], bl[nt][1]);
            }
            #pragma unroll
            for (int mt = 0; mt < 2; mt++)
                #pragma unroll
                for (int nt = 0; nt < 4; nt++) {
                    mma_tf32(acc[mt][nt], ah[mt], bh[nt]);
                    mma_tf32(acc[mt][nt], ah[mt], bl[nt]);
                    mma_tf32(acc[mt][nt], al[mt], bh[nt]);
                }
        }
        __syncthreads();
    }

    #pragma unroll
    for (int mt = 0; mt < 2; mt++)
        #pragma unroll
        for (int nt = 0; nt < 4; nt++) {
            int n = warp_n * 32 + nt * 8 + tig * 2;
            int m = m0 + warp_m * 32 + mt * 16 + gid;
            int b = m >> 11, t = m & (TSEQ - 1);
            float2 v0 = make_float2(acc[mt][nt][0], acc[mt][nt][1]);
            *(float2*)&out[((size_t)((b * NHEAD + h) * TSEQ + t)) * HDIM + n] = v0;
            int m2 = m + 8;
            b = m2 >> 11; t = m2 & (TSEQ - 1);
            float2 v1 = make_float2(acc[mt][nt][2], acc[mt][nt][3]);
            *(float2*)&out[((size_t)((b * NHEAD + h) * TSEQ + t)) * HDIM + n] = v1;
        }
}

// ---------------------------------------------------------------------------
// Kernel 2: tensorized flash attention. grid=(TSEQ/128, NHEAD, NBATCH), 256 thr.
// 8 warps × 16 query rows each; K/V double-buffered; P aliases the Q region.
// QK^T and PV both mma.sync tf32 3-pass; exp on fma pipe (exp2p).
// ---------------------------------------------------------------------------
#define APS 68   // Q/P smem stride (floats)
#define AKS 68   // K smem stride
#define AVS 72   // V smem stride
#define A_QP   0
#define A_K0   (128 * APS)                 // 8704
#define A_V0   (A_K0 + 2 * 64 * AKS)       // 17408
#define A_TOTF (A_V0 + 2 * 64 * AVS)       // 26624 floats
#define ATTN_SMEM (A_TOTF * 4)             // 106496 B

__device__ __forceinline__ void attn_stage(uint32_t sb, const float* K, const float* V,
                                           int kt, int tid) {
    uint32_t kb = sb + (uint32_t)(A_K0 + (kt & 1) * 64 * AKS) * 4u;
    uint32_t vb = sb + (uint32_t)(A_V0 + (kt & 1) * 64 * AVS) * 4u;
    #pragma unroll
    for (int j = 0; j < 4; j++) {
        int idx = j * 256 + tid;
        int r = idx >> 4, q = idx & 15;
        CP_ASYNC16(kb + (uint32_t)(r * AKS + q * 4) * 4u,
                   &K[(size_t)(kt * 64 + r) * HDIM + q * 4]);
    }
    #pragma unroll
    for (int j = 0; j < 4; j++) {
        int idx = j * 256 + tid;
        int r = idx >> 4, q = idx & 15;
        CP_ASYNC16(vb + (uint32_t)(r * AVS + q * 4) * 4u,
                   &V[(size_t)(kt * 64 + r) * HDIM + q * 4]);
    }
    CP_COMMIT();
}

__global__ __launch_bounds__(256, 1) void attn_mma_kernel()
{
    extern __shared__ __align__(16) float sm[];
    const uint32_t sb = smem_u32(sm);
    const int tid = threadIdx.x;
    const int lane = tid & 31, wid = tid >> 5;
    const int gid = lane >> 2, tig = lane & 3;
    const int qt = blockIdx.x, h = blockIdx.y, b = blockIdx.z;
    const size_t base = (size_t)((b * NHEAD + h) * TSEQ) * HDIM;
    const float* Qg = g_q + base;
    const float* Kg = g_k + base;
    const float* Vg = g_v + base;

    // stage Q (128x64) and first K/V tile
    #pragma unroll
    for (int j = 0; j < 8; j++) {
        int idx = j * 256 + tid;
        int r = idx >> 4, q = idx & 15;
        CP_ASYNC16(sb + (uint32_t)(A_QP + r * APS + q * 4) * 4u,
                   &Qg[(size_t)(qt * 128 + r) * HDIM + q * 4]);
    }
    CP_COMMIT();
    attn_stage(sb, Kg, Vg, 0, tid);
    CP_WAIT0();
    __syncthreads();

    // extract Q fragments, scaled by 0.125 * log2(e) (softmax runs in log2 units)
    const float QSC = 0.18033688011112042f;
    const int r0 = wid * 16 + gid;           // warp-local row (block row = qt*128 + r0)
    uint32_t qh[8][4], ql[8][4];
    {
        const float* Qs = sm + A_QP;
        #pragma unroll
        for (int ks = 0; ks < 8; ks++) {
            int c = ks * 8 + tig;
            split_tf32(Qs[r0 * APS + c] * QSC,           qh[ks][0], ql[ks][0]);
            split_tf32(Qs[(r0 + 8) * APS + c] * QSC,     qh[ks][1], ql[ks][1]);
            split_tf32(Qs[r0 * APS + c + 4] * QSC,       qh[ks][2], ql[ks][2]);
            split_tf32(Qs[(r0 + 8) * APS + c + 4] * QSC, qh[ks][3], ql[ks][3]);
        }
    }
    __syncthreads();   // Q region may now be reused as P

    float o[8][4];
    #pragma unroll
    for (int nt = 0; nt < 8; nt++)
        #pragma unroll
        for (int e = 0; e < 4; e++) o[nt][e] = 0.f;
    float m0 = -1e30f, m1 = -1e30f, l0 = 0.f, l1 = 0.f;

    for (int kt = 0; kt < TSEQ / 64; kt++) {
        if (kt + 1 < TSEQ / 64) {
            attn_stage(sb, Kg, Vg, kt + 1, tid);
            CP_WAIT1();
        } else {
            CP_WAIT0();
        }
        __syncthreads();

        const float* Ks = sm + A_K0 + (kt & 1) * 64 * AKS;
        const float* Vs = sm + A_V0 + (kt & 1) * 64 * AVS;

        // S = Q K^T (3-pass tf32), S in log2-units (scale folded into Q)
        float s[8][4];
        #pragma unroll
        for (int nt = 0; nt < 8; nt++)
            #pragma unroll
            for (int e = 0; e < 4; e++) s[nt][e] = 0.f;

        #pragma unroll
        for (int ks = 0; ks < 8; ks++) {
            #pragma unroll
            for (int nt = 0; nt < 8; nt++) {
                uint32_t bh[2], bl[2];
                split_tf32(Ks[(nt * 8 + gid) * AKS + ks * 8 + tig],     bh[0], bl[0]);
                split_tf32(Ks[(nt * 8 + gid) * AKS + ks * 8 + tig + 4], bh[1], bl[1]);
                mma_tf32(s[nt], qh[ks], bh);
                mma_tf32(s[nt], qh[ks], bl);
                mma_tf32(s[nt], ql[ks], bh);
            }
        }

        // online softmax (rows gid and gid+8), 4-lane tig-group reductions
        float tm0 = -1e30f, tm1 = -1e30f;
        #pragma unroll
        for (int nt = 0; nt < 8; nt++) {
            tm0 = fmaxf(tm0, fmaxf(s[nt][0], s[nt][1]));
            tm1 = fmaxf(tm1, fmaxf(s[nt][2], s[nt][3]));
        }
        tm0 = fmaxf(tm0, __shfl_xor_sync(0xffffffffu, tm0, 1));
        tm0 = fmaxf(tm0, __shfl_xor_sync(0xffffffffu, tm0, 2));
        tm1 = fmaxf(tm1, __shfl_xor_sync(0xffffffffu, tm1, 1));
        tm1 = fmaxf(tm1, __shfl_xor_sync(0xffffffffu, tm1, 2));
        float mn0 = fmaxf(m0, tm0), mn1 = fmaxf(m1, tm1);
        float al0 = exp2p(m0 - mn0), al1 = exp2p(m1 - mn1);
        m0 = mn0; m1 = mn1;

        float rs0 = 0.f, rs1 = 0.f;
        #pragma unroll
        for (int nt = 0; nt < 8; nt++) {
            s[nt][0] = exp2p(s[nt][0] - mn0);
            s[nt][1] = exp2p(s[nt][1] - mn0);
            s[nt][2] = exp2p(s[nt][2] - mn1);
            s[nt][3] = exp2p(s[nt][3] - mn1);
            rs0 += s[nt][0] + s[nt][1];
            rs1 += s[nt][2] + s[nt][3];
        }
        rs0 += __shfl_xor_sync(0xffffffffu, rs0, 1);
        rs0 += __shfl_xor_sync(0xffffffffu, rs0, 2);
        rs1 += __shfl_xor_sync(0xffffffffu, rs1, 1);
        rs1 += __shfl_xor_sync(0xffffffffu, rs1, 2);
        l0 = l0 * al0 + rs0;
        l1 = l1 * al1 + rs1;
        #pragma unroll
        for (int nt = 0; nt < 8; nt++) {
            o[nt][0] *= al0; o[nt][1] *= al0;
            o[nt][2] *= al1; o[nt][3] *= al1;
        }

        // P -> smem (warp-private rows), then reload as A fragments
        float* Ps = sm + A_QP;
        #pragma unroll
        for (int nt = 0; nt < 8; nt++) {
            *(float2*)&Ps[r0 * APS + nt * 8 + 2 * tig]       = make_float2(s[nt][0], s[nt][1]);
            *(float2*)&Ps[(r0 + 8) * APS + nt * 8 + 2 * tig] = make_float2(s[nt][2], s[nt][3]);
        }
        __syncwarp();

        // O += P V (3-pass tf32)
        #pragma unroll
        for (int ks = 0; ks < 8; ks++) {
            uint32_t ah[4], aL[4];
            split_tf32(Ps[r0 * APS + ks * 8 + tig],           ah[0], aL[0]);
            split_tf32(Ps[(r0 + 8) * APS + ks * 8 + tig],     ah[1], aL[1]);
            split_tf32(Ps[r0 * APS + ks * 8 + tig + 4],       ah[2], aL[2]);
            split_tf32(Ps[(r0 + 8) * APS + ks * 8 + tig + 4], ah[3], aL[3]);
            #pragma unroll
            for (int nt = 0; nt < 8; nt++) {
                uint32_t bh[2], bl[2];
                split_tf32(Vs[(ks * 8 + tig) * AVS + nt * 8 + gid],     bh[0], bl[0]);
                split_tf32(Vs[(ks * 8 + tig + 4) * AVS + nt * 8 + gid], bh[1], bl[1]);
                mma_tf32(o[nt], ah, bh);
                mma_tf32(o[nt], ah, bl);
                mma_tf32(o[nt], aL, bh);
            }
        }
        __syncthreads();   // all warps done with this K/V buffer before restaging
    }

    // epilogue: normalize, write combined heads to g_c
    float inv0 = 1.f / l0, inv1 = 1.f / l1;
    int t0 = qt * 128 + r0;
    #pragma unroll
    for (int nt = 0; nt < 8; nt++) {
        int col = h * HDIM + nt * 8 + 2 * tig;
        *(float2*)&g_c[(size_t)(b * TSEQ + t0) * EMB + col] =
            make_float2(o[nt][0] * inv0, o[nt][1] * inv0);
        *(float2*)&g_c[(size_t)(b * TSEQ + t0 + 8) * EMB + col] =
            make_float2(o[nt][2] * inv1, o[nt][3] * inv1);
    }
}

// ---------------------------------------------------------------------------
// Kernel 3: out = x + C @ Wo^T via mma.sync tf32 3-pass (unchanged from R9).
// ---------------------------------------------------------------------------
#define OP_BUF_F   6912
#define OP_BUF_B   (OP_BUF_F * 4)
#define OP_SMEM    (2 * OP_BUF_B)

__device__ __forceinline__ void op_stage(uint32_t sbuf, const float* Wo,
                                         int m0, int n0, int k0, int tid) {
    #pragma unroll
    for (int j = 0; j < 4; j++) {
        int idx = j * 256 + tid;
        int r = idx >> 3, q = idx & 7;
        CP_ASYNC16(sbuf + (uint32_t)(r * 36 + q * 4) * 4u,
                   &g_c[(size_t)(m0 + r) * EMB + k0 + q * 4]);
    }
    #pragma unroll
    for (int j = 0; j < 2; j++) {
        int idx = j * 256 + tid;
        int n = idx >> 3, q = idx & 7;
        CP_ASYNC16(sbuf + (uint32_t)(4608 + n * 36 + q * 4) * 4u,
                   &Wo[(size_t)(n0 + n) * EMB + k0 + q * 4]);
    }
    CP_COMMIT();
}

__global__ __launch_bounds__(256) void outproj_mma_kernel(
    const float* __restrict__ x, const float* __restrict__ Wo,
    float* __restrict__ out)
{
    extern __shared__ __align__(16) float sm[];
    const uint32_t sb = smem_u32(sm);
    const int tid = threadIdx.x;
    const int lane = tid & 31, wid = tid >> 5;
    const int gid = lane >> 2, tig = lane & 3;
    const int warp_m = wid >> 1, warp_n = wid & 1;
    const int m0 = blockIdx.x * 128, n0 = blockIdx.y * 64;

    float acc[2][4][4];
    #pragma unroll
    for (int mt = 0; mt < 2; mt++)
        #pragma unroll
        for (int nt = 0; nt < 4; nt++)
            #pragma unroll
            for (int e = 0; e < 4; e++) acc[mt][nt][e] = 0.f;

    op_stage(sb, Wo, m0, n0, 0, tid);

    for (int ch = 0; ch < NCHUNK; ch++) {
        if (ch + 1 < NCHUNK) {
            op_stage(sb + ((ch + 1) & 1) * OP_BUF_B, Wo, m0, n0, (ch + 1) * KCHUNK, tid);
            CP_WAIT1();
        } else {
            CP_WAIT0();
        }
        __syncthreads();

        const float* As = sm + (ch & 1) * OP_BUF_F;
        const float* Bs = As + 4608;

        #pragma unroll
        for (int ks = 0; ks < 4; ks++) {
            uint32_t ah[2][4], al[2][4], bh[4][2], bl[4][2];
            #pragma unroll
            for (int mt = 0; mt < 2; mt++) {
                int r = warp_m * 32 + mt * 16 + gid;
                int c = ks * 8 + tig;
                split_tf32(As[r * 36 + c],           ah[mt][0], al[mt][0]);
                split_tf32(As[(r + 8) * 36 + c],     ah[mt][1], al[mt][1]);
                split_tf32(As[r * 36 + c + 4],       ah[mt][2], al[mt][2]);
                split_tf32(As[(r + 8) * 36 + c + 4], ah[mt][3], al[mt][3]);
            }
            #pragma unroll
            for (int nt = 0; nt < 4; nt++) {
                int nn = warp_n * 32 + nt * 8 + gid;
                int kk = ks * 8 + tig;
                split_tf32(Bs[nn * 36 + kk],     bh[nt][0], bl[nt][0]);
                split_tf32(Bs[nn * 36 + kk + 4], bh[nt][1], bl[nt][1]);
            }
            #pragma unroll
            for (int mt = 0; mt < 2; mt++)
                #pragma unroll
                for (int nt = 0; nt < 4; nt++) {
                    mma_tf32(acc[mt][nt], ah[mt], bh[nt]);
                    mma_tf32(acc[mt][nt], ah[mt], bl[nt]);
                    mma_tf32(acc[mt][nt], al[mt], bh[nt]);
                }
        }
        __syncthreads();
    }

    #pragma unroll
    for (int mt = 0; mt < 2; mt++)
        #pragma unroll
        for (int nt = 0; nt < 4; nt++) {
            int n = n0 + warp_n * 32 + nt * 8 + tig * 2;
            int m = m0 + warp_m * 32 + mt * 16 + gid;
            {
                size_t off = (size_t)m * EMB + n;
                float2 xv = *(const float2*)&x[off];
                *(float2*)&out[off] = make_float2(acc[mt][nt][0] + xv.x, acc[mt][nt][1] + xv.y);
            }
            {
                size_t off = (size_t)(m + 8) * EMB + n;
                float2 xv = *(const float2*)&x[off];
                *(float2*)&out[off] = make_float2(acc[mt][nt][2] + xv.x, acc[mt][nt][3] + xv.y);
            }
        }
}

extern "C" void kernel_launch(void* const* d_in, const int* in_sizes, int n_in,
                              void* d_out, int out_size)
{
    const float* x  = (const float*)d_in[0];
    const float* Wq = (const float*)d_in[1];
    const float* Wk = (const float*)d_in[2];
    const float* Wv = (const float*)d_in[3];
    const float* Wo = (const float*)d_in[4];
    float* out = (float*)d_out;

    cudaFuncSetAttribute(qkv_mma_kernel, cudaFuncAttributeMaxDynamicSharedMemorySize, QKV_SMEM);
    cudaFuncSetAttribute(attn_mma_kernel, cudaFuncAttributeMaxDynamicSharedMemorySize, ATTN_SMEM);
    cudaFuncSetAttribute(outproj_mma_kernel, cudaFuncAttributeMaxDynamicSharedMemorySize, OP_SMEM);

    dim3 g1(NTOK / 128, NHEAD, 3);
    qkv_mma_kernel<<<g1, 256, QKV_SMEM>>>(x, Wq, Wk, Wv);

    dim3 g2(TSEQ / 128, NHEAD, NBATCH);
    attn_mma_kernel<<<g2, 256, ATTN_SMEM>>>();

    dim3 g3(NTOK / 128, EMB / 64);
    outproj_mma_kernel<<<g3, 256, OP_SMEM>>>(x, Wo, out);
}

// round 11
// speedup vs baseline: 1.8290x; 1.3182x over previous
#include <cuda_runtime.h>
#include <cuda_fp16.h>
#include <math.h>
#include <stdint.h>

#define NBATCH 2
#define TSEQ   2048
#define EMB    1024
#define NHEAD  16
#define HDIM   64
#define NTOK   (NBATCH*TSEQ)   // 4096

// Scratch (allocation-free): Q,K,V as [B,H,T,D]; C (attn combined) as [B,T,E]
__device__ float g_q[NBATCH*NHEAD*TSEQ*HDIM];
__device__ float g_k[NBATCH*NHEAD*TSEQ*HDIM];
__device__ float g_v[NBATCH*NHEAD*TSEQ*HDIM];
__device__ float g_c[NBATCH*TSEQ*EMB];

// ===========================================================================
// Helpers (sm_80-base ISA: mma.sync f16 m16n8k16, cp.async)
// ===========================================================================
__device__ __forceinline__ uint32_t smem_u32(const void* p) {
    uint32_t a;
    asm("{ .reg .u64 t; cvta.to.shared.u64 t, %1; cvt.u32.u64 %0, t; }" : "=r"(a) : "l"(p));
    return a;
}
#define CP_ASYNC16(dst, src) asm volatile("cp.async.cg.shared.global [%0], [%1], 16;" :: "r"(dst), "l"(src))
#define CP_COMMIT()          asm volatile("cp.async.commit_group;" ::: "memory")
#define CP_WAIT0()           asm volatile("cp.async.wait_group 0;" ::: "memory")
#define CP_WAIT1()           asm volatile("cp.async.wait_group 1;" ::: "memory")

// m16n8k16 f16 MMA with fp32 accumulate
__device__ __forceinline__ void mma_f16(float* d, const uint32_t* a, const uint32_t* b) {
    asm volatile("mma.sync.aligned.m16n8k16.row.col.f32.f16.f16.f32 "
        "{%0,%1,%2,%3}, {%4,%5,%6,%7}, {%8,%9}, {%0,%1,%2,%3};"
        : "+f"(d[0]), "+f"(d[1]), "+f"(d[2]), "+f"(d[3])
        : "r"(a[0]), "r"(a[1]), "r"(a[2]), "r"(a[3]), "r"(b[0]), "r"(b[1]));
}
// split two floats into packed f16x2 hi + lo (3-pass split: v = hi + lo, lo error ~2^-24 rel)
__device__ __forceinline__ void split_pair(float a, float b, uint32_t& hi, uint32_t& lo) {
    __half ha = __float2half_rn(a), hb = __float2half_rn(b);
    __half la = __float2half_rn(a - __half2float(ha));
    __half lb = __float2half_rn(b - __half2float(hb));
    hi = ((uint32_t)__half_as_ushort(hb) << 16) | (uint32_t)__half_as_ushort(ha);
    lo = ((uint32_t)__half_as_ushort(lb) << 16) | (uint32_t)__half_as_ushort(la);
}
__device__ __forceinline__ void split_store(float v, __half* ph, __half* pl) {
    __half h = __float2half_rn(v);
    *ph = h;
    *pl = __float2half_rn(v - __half2float(h));
}
// exp2 via degree-5 polynomial on fma pipe (no MUFU); valid for y <= 0
__device__ __forceinline__ float exp2p(float y) {
    y = fmaxf(y, -126.f);
    float r = rintf(y);
    float f = y - r;
    float p = fmaf(f, 1.3333558146e-3f, 9.6181291076e-3f);
    p = fmaf(f, p, 5.5504108664e-2f);
    p = fmaf(f, p, 2.4022650696e-1f);
    p = fmaf(f, p, 6.9314718056e-1f);
    p = fmaf(f, p, 1.0f);
    int n = (int)r;
    return p * __int_as_float((n + 127) << 23);
}

#define KCHUNK 32
#define NCHUNK (EMB / KCHUNK)   // 32

// ---------------------------------------------------------------------------
// Kernel 1: QKV projection, f16 3-pass, pre-split hi/lo smem.
// grid=(32,16,3), 256 thr, block tile 128x64, warp 32x32.
// smem: raw double-buf (A[128][36]f + B[32][68]f) + half arrays Ah/Al[128][36], Bh/Bl[64][36]
// ---------------------------------------------------------------------------
#define QK_RAWF      6784                    // floats per raw buffer
#define QK_RAW_BYTES (QK_RAWF * 4)           // 27136
#define QK_HILO      (2 * QK_RAW_BYTES)      // 54272 byte offset of half region
#define QK_AH 0
#define QK_AL 4608
#define QK_BH 9216
#define QK_BL 11520
#define QKV_SMEM (QK_HILO + 13824 * 2)       // 81920 B

__device__ __forceinline__ void qkv_stage(uint32_t sbuf, const float* x, const float* W,
                                          int m0, int k0, int tid) {
    #pragma unroll
    for (int j = 0; j < 4; j++) {            // A: 1024 quads
        int idx = j * 256 + tid;
        int r = idx >> 3, q = idx & 7;
        CP_ASYNC16(sbuf + (uint32_t)(r * 36 + q * 4) * 4u,
                   &x[(size_t)(m0 + r) * EMB + k0 + q * 4]);
    }
    #pragma unroll
    for (int j = 0; j < 2; j++) {            // B: 512 quads ([k][n], 32x64)
        int idx = j * 256 + tid;
        int k = idx >> 4, q = idx & 15;
        CP_ASYNC16(sbuf + (uint32_t)(4608 + k * 68 + q * 4) * 4u,
                   &W[(size_t)(k0 + k) * HDIM + q * 4]);
    }
    CP_COMMIT();
}

__global__ __launch_bounds__(256) void qkv_mma_kernel(
    const float* __restrict__ x, const float* __restrict__ Wq,
    const float* __restrict__ Wk, const float* __restrict__ Wv)
{
    extern __shared__ __align__(16) float sm[];
    const uint32_t sb = smem_u32(sm);
    const int tid = threadIdx.x;
    const int lane = tid & 31, wid = tid >> 5;
    const int gid = lane >> 2, tig = lane & 3;
    const int warp_m = wid >> 1, warp_n = wid & 1;
    const int m0 = blockIdx.x * 128, h = blockIdx.y, which = blockIdx.z;
    const float* W = (which == 0 ? Wq : which == 1 ? Wk : Wv) + (size_t)h * EMB * HDIM;
    float* out = (which == 0 ? g_q : which == 1 ? g_k : g_v);

    __half* Hb  = (__half*)((char*)sm + QK_HILO);
    __half* AhP = Hb + QK_AH;
    __half* AlP = Hb + QK_AL;
    __half* BhP = Hb + QK_BH;
    __half* BlP = Hb + QK_BL;

    float acc[2][4][4];
    #pragma unroll
    for (int mt = 0; mt < 2; mt++)
        #pragma unroll
        for (int nt = 0; nt < 4; nt++)
            #pragma unroll
            for (int e = 0; e < 4; e++) acc[mt][nt][e] = 0.f;

    qkv_stage(sb, x, W, m0, 0, tid);

    for (int ch = 0; ch < NCHUNK; ch++) {
        if (ch + 1 < NCHUNK) {
            qkv_stage(sb + ((ch + 1) & 1) * QK_RAW_BYTES, x, W, m0, (ch + 1) * KCHUNK, tid);
            CP_WAIT1();
        } else {
            CP_WAIT0();
        }
        __syncthreads();    // raw ch ready; prior mma done with hi/lo region

        const float* Araw = sm + (ch & 1) * QK_RAWF;
        const float* Braw = Araw + 4608;
        #pragma unroll
        for (int j = 0; j < 16; j++) {       // A: 4096 elements
            int el = j * 256 + tid;
            int r = el >> 5, c = el & 31;
            split_store(Araw[r * 36 + c], AhP + r * 36 + c, AlP + r * 36 + c);
        }
        #pragma unroll
        for (int j = 0; j < 8; j++) {        // B: 2048 elements, transpose [k][n]->[n][k]
            int el = j * 256 + tid;
            int k = el >> 6, n = el & 63;
            split_store(Braw[k * 68 + n], BhP + n * 36 + k, BlP + n * 36 + k);
        }
        __syncthreads();

        #pragma unroll
        for (int ks = 0; ks < 2; ks++) {
            const int c = ks * 16 + 2 * tig;
            uint32_t ah[2][4], al[2][4], bh[4][2], bl[4][2];
            #pragma unroll
            for (int mt = 0; mt < 2; mt++) {
                int r = warp_m * 32 + mt * 16 + gid;
                ah[mt][0] = *(const uint32_t*)(AhP + r * 36 + c);
                ah[mt][1] = *(const uint32_t*)(AhP + (r + 8) * 36 + c);
                ah[mt][2] = *(const uint32_t*)(AhP + r * 36 + c + 8);
                ah[mt][3] = *(const uint32_t*)(AhP + (r + 8) * 36 + c + 8);
                al[mt][0] = *(const uint32_t*)(AlP + r * 36 + c);
                al[mt][1] = *(const uint32_t*)(AlP + (r + 8) * 36 + c);
                al[mt][2] = *(const uint32_t*)(AlP + r * 36 + c + 8);
                al[mt][3] = *(const uint32_t*)(AlP + (r + 8) * 36 + c + 8);
            }
            #pragma unroll
            for (int nt = 0; nt < 4; nt++) {
                int nn = warp_n * 32 + nt * 8 + gid;
                bh[nt][0] = *(const uint32_t*)(BhP + nn * 36 + c);
                bh[nt][1] = *(const uint32_t*)(BhP + nn * 36 + c + 8);
                bl[nt][0] = *(const uint32_t*)(BlP + nn * 36 + c);
                bl[nt][1] = *(const uint32_t*)(BlP + nn * 36 + c + 8);
            }
            #pragma unroll
            for (int mt = 0; mt < 2; mt++)
                #pragma unroll
                for (int nt = 0; nt < 4; nt++) {
                    mma_f16(acc[mt][nt], ah[mt], bh[nt]);
                    mma_f16(acc[mt][nt], ah[mt], bl[nt]);
                    mma_f16(acc[mt][nt], al[mt], bh[nt]);
                }
        }
    }

    #pragma unroll
    for (int mt = 0; mt < 2; mt++)
        #pragma unroll
        for (int nt = 0; nt < 4; nt++) {
            int n = warp_n * 32 + nt * 8 + tig * 2;
            int m = m0 + warp_m * 32 + mt * 16 + gid;
            int b = m >> 11, t = m & (TSEQ - 1);
            *(float2*)&out[((size_t)((b * NHEAD + h) * TSEQ + t)) * HDIM + n] =
                make_float2(acc[mt][nt][0], acc[mt][nt][1]);
            int m2 = m + 8;
            b = m2 >> 11; t = m2 & (TSEQ - 1);
            *(float2*)&out[((size_t)((b * NHEAD + h) * TSEQ + t)) * HDIM + n] =
                make_float2(acc[mt][nt][2], acc[mt][nt][3]);
        }
}

// ---------------------------------------------------------------------------
// Kernel 2: flash attention, f16 3-pass, pre-split K/V smem, P stays in regs.
// grid=(16,16,2), 256 thr (8 warps x 16 query rows).
// smem: region0 = Q raw (34816 B) aliased by Khi/Klo/Vthi/Vtlo halves (36864 B);
//       raw K/V double-buffered at 36864 (2 x 34816). Total 106496 B.
// ---------------------------------------------------------------------------
#define AT_HS   72        // hi/lo half stride
#define AT_KHI  0
#define AT_KLO  4608      // half offsets within region0
#define AT_VHI  9216
#define AT_VLO  13824
#define AT_RAW0 36864     // byte offset of raw KV buffers
#define AT_RAWB 34816     // bytes per raw KV buffer (K 17408 + V 17408)
#define ATTN_SMEM (AT_RAW0 + 2 * AT_RAWB)   // 106496

__device__ __forceinline__ void attn_stage(uint32_t sb, const float* K, const float* V,
                                           int kt, int tid) {
    uint32_t kb = sb + AT_RAW0 + (uint32_t)(kt & 1) * AT_RAWB;
    uint32_t vb = kb + 17408;
    #pragma unroll
    for (int j = 0; j < 4; j++) {
        int idx = j * 256 + tid;
        int r = idx >> 4, q = idx & 15;
        CP_ASYNC16(kb + (uint32_t)(r * 68 + q * 4) * 4u,
                   &K[(size_t)(kt * 64 + r) * HDIM + q * 4]);
    }
    #pragma unroll
    for (int j = 0; j < 4; j++) {
        int idx = j * 256 + tid;
        int r = idx >> 4, q = idx & 15;
        CP_ASYNC16(vb + (uint32_t)(r * 68 + q * 4) * 4u,
                   &V[(size_t)(kt * 64 + r) * HDIM + q * 4]);
    }
    CP_COMMIT();
}

__global__ __launch_bounds__(256, 1) void attn_mma_kernel()
{
    extern __shared__ __align__(16) float sm[];
    const uint32_t sb = smem_u32(sm);
    const int tid = threadIdx.x;
    const int lane = tid & 31, wid = tid >> 5;
    const int gid = lane >> 2, tig = lane & 3;
    const int qt = blockIdx.x, h = blockIdx.y, b = blockIdx.z;
    const size_t base = (size_t)((b * NHEAD + h) * TSEQ) * HDIM;
    const float* Qg = g_q + base;
    const float* Kg = g_k + base;
    const float* Vg = g_v + base;

    // stage Q raw into region0, and first K/V tile
    #pragma unroll
    for (int j = 0; j < 8; j++) {
        int idx = j * 256 + tid;
        int r = idx >> 4, q = idx & 15;
        CP_ASYNC16(sb + (uint32_t)(r * 68 + q * 4) * 4u,
                   &Qg[(size_t)(qt * 128 + r) * HDIM + q * 4]);
    }
    CP_COMMIT();
    attn_stage(sb, Kg, Vg, 0, tid);
    CP_WAIT0();
    __syncthreads();

    // extract Q fragments (scaled by 0.125*log2e), hi/lo f16 split, 4 k16-steps
    const float QSC = 0.18033688011112042f;
    const int r0 = wid * 16 + gid;
    uint32_t qh[4][4], ql[4][4];
    {
        const float* Qs = sm;
        #pragma unroll
        for (int ks = 0; ks < 4; ks++) {
            int c = ks * 16 + 2 * tig;
            split_pair(Qs[r0 * 68 + c] * QSC,           Qs[r0 * 68 + c + 1] * QSC,       qh[ks][0], ql[ks][0]);
            split_pair(Qs[(r0 + 8) * 68 + c] * QSC,     Qs[(r0 + 8) * 68 + c + 1] * QSC, qh[ks][1], ql[ks][1]);
            split_pair(Qs[r0 * 68 + c + 8] * QSC,       Qs[r0 * 68 + c + 9] * QSC,       qh[ks][2], ql[ks][2]);
            split_pair(Qs[(r0 + 8) * 68 + c + 8] * QSC, Qs[(r0 + 8) * 68 + c + 9] * QSC, qh[ks][3], ql[ks][3]);
        }
    }
    __syncthreads();    // Q raw region now reusable as K/V hi/lo

    __half* Hb = (__half*)sm;
    float o[8][4];
    #pragma unroll
    for (int nt = 0; nt < 8; nt++)
        #pragma unroll
        for (int e = 0; e < 4; e++) o[nt][e] = 0.f;
    float m0 = -1e30f, m1 = -1e30f, l0 = 0.f, l1 = 0.f;

    for (int kt = 0; kt < TSEQ / 64; kt++) {
        if (kt + 1 < TSEQ / 64) {
            attn_stage(sb, Kg, Vg, kt + 1, tid);
            CP_WAIT1();
        } else {
            CP_WAIT0();
        }
        __syncthreads();    // raw kt ready; prior mma done with hi/lo

        // convert raw K/V -> hi/lo halves (K natural [key][d], V transposed [d][key])
        const float* Kraw = (const float*)((const char*)sm + AT_RAW0 + (kt & 1) * AT_RAWB);
        const float* Vraw = Kraw + 64 * 68;
        #pragma unroll
        for (int j = 0; j < 16; j++) {
            int el = j * 256 + tid;
            int key = el >> 6, d = el & 63;
            split_store(Kraw[key * 68 + d], Hb + AT_KHI + key * AT_HS + d,
                                            Hb + AT_KLO + key * AT_HS + d);
        }
        #pragma unroll
        for (int j = 0; j < 16; j++) {
            int el = j * 256 + tid;
            int key = el >> 6, d = el & 63;
            split_store(Vraw[key * 68 + d], Hb + AT_VHI + d * AT_HS + key,
                                            Hb + AT_VLO + d * AT_HS + key);
        }
        __syncthreads();

        // S = Q K^T (3-pass f16), in log2 units
        float s[8][4];
        #pragma unroll
        for (int nt = 0; nt < 8; nt++)
            #pragma unroll
            for (int e = 0; e < 4; e++) s[nt][e] = 0.f;

        #pragma unroll
        for (int ks = 0; ks < 4; ks++) {
            const int c = ks * 16 + 2 * tig;
            #pragma unroll
            for (int nt = 0; nt < 8; nt++) {
                int key = nt * 8 + gid;
                uint32_t bh[2], bl[2];
                bh[0] = *(const uint32_t*)(Hb + AT_KHI + key * AT_HS + c);
                bh[1] = *(const uint32_t*)(Hb + AT_KHI + key * AT_HS + c + 8);
                bl[0] = *(const uint32_t*)(Hb + AT_KLO + key * AT_HS + c);
                bl[1] = *(const uint32_t*)(Hb + AT_KLO + key * AT_HS + c + 8);
                mma_f16(s[nt], qh[ks], bh);
                mma_f16(s[nt], qh[ks], bl);
                mma_f16(s[nt], ql[ks], bh);
            }
        }

        // online softmax (rows gid, gid+8), 4-lane reductions
        float tm0 = -1e30f, tm1 = -1e30f;
        #pragma unroll
        for (int nt = 0; nt < 8; nt++) {
            tm0 = fmaxf(tm0, fmaxf(s[nt][0], s[nt][1]));
            tm1 = fmaxf(tm1, fmaxf(s[nt][2], s[nt][3]));
        }
        tm0 = fmaxf(tm0, __shfl_xor_sync(0xffffffffu, tm0, 1));
        tm0 = fmaxf(tm0, __shfl_xor_sync(0xffffffffu, tm0, 2));
        tm1 = fmaxf(tm1, __shfl_xor_sync(0xffffffffu, tm1, 1));
        tm1 = fmaxf(tm1, __shfl_xor_sync(0xffffffffu, tm1, 2));
        float mn0 = fmaxf(m0, tm0), mn1 = fmaxf(m1, tm1);
        float al0 = exp2p(m0 - mn0), al1 = exp2p(m1 - mn1);
        m0 = mn0; m1 = mn1;

        float rs0 = 0.f, rs1 = 0.f;
        #pragma unroll
        for (int nt = 0; nt < 8; nt++) {
            s[nt][0] = exp2p(s[nt][0] - mn0);
            s[nt][1] = exp2p(s[nt][1] - mn0);
            s[nt][2] = exp2p(s[nt][2] - mn1);
            s[nt][3] = exp2p(s[nt][3] - mn1);
            rs0 += s[nt][0] + s[nt][1];
            rs1 += s[nt][2] + s[nt][3];
        }
        rs0 += __shfl_xor_sync(0xffffffffu, rs0, 1);
        rs0 += __shfl_xor_sync(0xffffffffu, rs0, 2);
        rs1 += __shfl_xor_sync(0xffffffffu, rs1, 1);
        rs1 += __shfl_xor_sync(0xffffffffu, rs1, 2);
        l0 = l0 * al0 + rs0;
        l1 = l1 * al1 + rs1;
        #pragma unroll
        for (int nt = 0; nt < 8; nt++) {
            o[nt][0] *= al0; o[nt][1] *= al0;
            o[nt][2] *= al1; o[nt][3] *= al1;
        }

        // O += P V: P repacked register->register (C-frag layout == A-frag layout)
        #pragma unroll
        for (int ks = 0; ks < 4; ks++) {
            uint32_t ah[4], aL[4];
            split_pair(s[2 * ks][0],     s[2 * ks][1],     ah[0], aL[0]);
            split_pair(s[2 * ks][2],     s[2 * ks][3],     ah[1], aL[1]);
            split_pair(s[2 * ks + 1][0], s[2 * ks + 1][1], ah[2], aL[2]);
            split_pair(s[2 * ks + 1][2], s[2 * ks + 1][3], ah[3], aL[3]);
            const int c = ks * 16 + 2 * tig;
            #pragma unroll
            for (int nt = 0; nt < 8; nt++) {
                int d = nt * 8 + gid;
                uint32_t bh[2], bl[2];
                bh[0] = *(const uint32_t*)(Hb + AT_VHI + d * AT_HS + c);
                bh[1] = *(const uint32_t*)(Hb + AT_VHI + d * AT_HS + c + 8);
                bl[0] = *(const uint32_t*)(Hb + AT_VLO + d * AT_HS + c);
                bl[1] = *(const uint32_t*)(Hb + AT_VLO + d * AT_HS + c + 8);
                mma_f16(o[nt], ah, bh);
                mma_f16(o[nt], ah, bl);
                mma_f16(o[nt], aL, bh);
            }
        }
    }

    // epilogue: normalize, write combined heads to g_c
    float inv0 = 1.f / l0, inv1 = 1.f / l1;
    int t0 = qt * 128 + r0;
    #pragma unroll
    for (int nt = 0; nt < 8; nt++) {
        int col = h * HDIM + nt * 8 + 2 * tig;
        *(float2*)&g_c[(size_t)(b * TSEQ + t0) * EMB + col] =
            make_float2(o[nt][0] * inv0, o[nt][1] * inv0);
        *(float2*)&g_c[(size_t)(b * TSEQ + t0 + 8) * EMB + col] =
            make_float2(o[nt][2] * inv1, o[nt][3] * inv1);
    }
}

// ---------------------------------------------------------------------------
// Kernel 3: out = x + C @ Wo^T, f16 3-pass, pre-split hi/lo smem.
// grid=(32,16), 256 thr. Wo [N][K] K-contiguous (no transpose in convert).
// ---------------------------------------------------------------------------
#define OP_RAWF      6912
#define OP_RAW_BYTES (OP_RAWF * 4)           // 27648
#define OP_HILO      (2 * OP_RAW_BYTES)      // 55296
#define OP_AH 0
#define OP_AL 4608
#define OP_BH 9216
#define OP_BL 11520
#define OP_SMEM (OP_HILO + 13824 * 2)        // 82944

__device__ __forceinline__ void op_stage(uint32_t sbuf, const float* Wo,
                                         int m0, int n0, int k0, int tid) {
    #pragma unroll
    for (int j = 0; j < 4; j++) {            // A: 1024 quads from g_c
        int idx = j * 256 + tid;
        int r = idx >> 3, q = idx & 7;
        CP_ASYNC16(sbuf + (uint32_t)(r * 36 + q * 4) * 4u,
                   &g_c[(size_t)(m0 + r) * EMB + k0 + q * 4]);
    }
    #pragma unroll
    for (int j = 0; j < 2; j++) {            // B: 512 quads ([n][k], 64x32)
        int idx = j * 256 + tid;
        int n = idx >> 3, q = idx & 7;
        CP_ASYNC16(sbuf + (uint32_t)(4608 + n * 36 + q * 4) * 4u,
                   &Wo[(size_t)(n0 + n) * EMB + k0 + q * 4]);
    }
    CP_COMMIT();
}

__global__ __launch_bounds__(256) void outproj_mma_kernel(
    const float* __restrict__ x, const float* __restrict__ Wo,
    float* __restrict__ out)
{
    extern __shared__ __align__(16) float sm[];
    const uint32_t sb = smem_u32(sm);
    const int tid = threadIdx.x;
    const int lane = tid & 31, wid = tid >> 5;
    const int gid = lane >> 2, tig = lane & 3;
    const int warp_m = wid >> 1, warp_n = wid & 1;
    const int m0 = blockIdx.x * 128, n0 = blockIdx.y * 64;

    __half* Hb  = (__half*)((char*)sm + OP_HILO);
    __half* AhP = Hb + OP_AH;
    __half* AlP = Hb + OP_AL;
    __half* BhP = Hb + OP_BH;
    __half* BlP = Hb + OP_BL;

    float acc[2][4][4];
    #pragma unroll
    for (int mt = 0; mt < 2; mt++)
        #pragma unroll
        for (int nt = 0; nt < 4; nt++)
            #pragma unroll
            for (int e = 0; e < 4; e++) acc[mt][nt][e] = 0.f;

    op_stage(sb, Wo, m0, n0, 0, tid);

    for (int ch = 0; ch < NCHUNK; ch++) {
        if (ch + 1 < NCHUNK) {
            op_stage(sb + ((ch + 1) & 1) * OP_RAW_BYTES, Wo, m0, n0, (ch + 1) * KCHUNK, tid);
            CP_WAIT1();
        } else {
            CP_WAIT0();
        }
        __syncthreads();

        const float* Araw = sm + (ch & 1) * OP_RAWF;
        const float* Braw = Araw + 4608;
        #pragma unroll
        for (int j = 0; j < 16; j++) {
            int el = j * 256 + tid;
            int r = el >> 5, c = el & 31;
            split_store(Araw[r * 36 + c], AhP + r * 36 + c, AlP + r * 36 + c);
        }
        #pragma unroll
        for (int j = 0; j < 8; j++) {
            int el = j * 256 + tid;
            int n = el >> 5, k = el & 31;
            split_store(Braw[n * 36 + k], BhP + n * 36 + k, BlP + n * 36 + k);
        }
        __syncthreads();

        #pragma unroll
        for (int ks = 0; ks < 2; ks++) {
            const int c = ks * 16 + 2 * tig;
            uint32_t ah[2][4], al[2][4], bh[4][2], bl[4][2];
            #pragma unroll
            for (int mt = 0; mt < 2; mt++) {
                int r = warp_m * 32 + mt * 16 + gid;
                ah[mt][0] = *(const uint32_t*)(AhP + r * 36 + c);
                ah[mt][1] = *(const uint32_t*)(AhP + (r + 8) * 36 + c);
                ah[mt][2] = *(const uint32_t*)(AhP + r * 36 + c + 8);
                ah[mt][3] = *(const uint32_t*)(AhP + (r + 8) * 36 + c + 8);
                al[mt][0] = *(const uint32_t*)(AlP + r * 36 + c);
                al[mt][1] = *(const uint32_t*)(AlP + (r + 8) * 36 + c);
                al[mt][2] = *(const uint32_t*)(AlP + r * 36 + c + 8);
                al[mt][3] = *(const uint32_t*)(AlP + (r + 8) * 36 + c + 8);
            }
            #pragma unroll
            for (int nt = 0; nt < 4; nt++) {
                int nn = warp_n * 32 + nt * 8 + gid;
                bh[nt][0] = *(const uint32_t*)(BhP + nn * 36 + c);
                bh[nt][1] = *(const uint32_t*)(BhP + nn * 36 + c + 8);
                bl[nt][0] = *(const uint32_t*)(BlP + nn * 36 + c);
                bl[nt][1] = *(const uint32_t*)(BlP + nn * 36 + c + 8);
            }
            #pragma unroll
            for (int mt = 0; mt < 2; mt++)
                #pragma unroll
                for (int nt = 0; nt < 4; nt++) {
                    mma_f16(acc[mt][nt], ah[mt], bh[nt]);
                    mma_f16(acc[mt][nt], ah[mt], bl[nt]);
                    mma_f16(acc[mt][nt], al[mt], bh[nt]);
                }
        }
    }

    #pragma unroll
    for (int mt = 0; mt < 2; mt++)
        #pragma unroll
        for (int nt = 0; nt < 4; nt++) {
            int n = n0 + warp_n * 32 + nt * 8 + tig * 2;
            int m = m0 + warp_m * 32 + mt * 16 + gid;
            {
                size_t off = (size_t)m * EMB + n;
                float2 xv = *(const float2*)&x[off];
                *(float2*)&out[off] = make_float2(acc[mt][nt][0] + xv.x, acc[mt][nt][1] + xv.y);
            }
            {
                size_t off = (size_t)(m + 8) * EMB + n;
                float2 xv = *(const float2*)&x[off];
                *(float2*)&out[off] = make_float2(acc[mt][nt][2] + xv.x, acc[mt][nt][3] + xv.y);
            }
        }
}

extern "C" void kernel_launch(void* const* d_in, const int* in_sizes, int n_in,
                              void* d_out, int out_size)
{
    const float* x  = (const float*)d_in[0];
    const float* Wq = (const float*)d_in[1];
    const float* Wk = (const float*)d_in[2];
    const float* Wv = (const float*)d_in[3];
    const float* Wo = (const float*)d_in[4];
    float* out = (float*)d_out;

    cudaFuncSetAttribute(qkv_mma_kernel, cudaFuncAttributeMaxDynamicSharedMemorySize, QKV_SMEM);
    cudaFuncSetAttribute(attn_mma_kernel, cudaFuncAttributeMaxDynamicSharedMemorySize, ATTN_SMEM);
    cudaFuncSetAttribute(outproj_mma_kernel, cudaFuncAttributeMaxDynamicSharedMemorySize, OP_SMEM);

    dim3 g1(NTOK / 128, NHEAD, 3);
    qkv_mma_kernel<<<g1, 256, QKV_SMEM>>>(x, Wq, Wk, Wv);

    dim3 g2(TSEQ / 128, NHEAD, NBATCH);
    attn_mma_kernel<<<g2, 256, ATTN_SMEM>>>();

    dim3 g3(NTOK / 128, EMB / 64);
    outproj_mma_kernel<<<g3, 256, OP_SMEM>>>(x, Wo, out);
}

// round 12
// speedup vs baseline: 2.5380x; 1.3876x over previous
#include <cuda_runtime.h>
#include <cuda_fp16.h>
#include <math.h>
#include <stdint.h>

#define NBATCH 2
#define TSEQ   2048
#define EMB    1024
#define NHEAD  16
#define HDIM   64
#define NTOK   (NBATCH*TSEQ)   // 4096

// ---------------------------------------------------------------------------
// Persistent hi/lo half scratch (allocation-free)
// ---------------------------------------------------------------------------
__device__ __half g_xh[NTOK*EMB],  g_xl[NTOK*EMB];                 // x split
__device__ __half g_wh[3*NHEAD*EMB*HDIM], g_wl[3*NHEAD*EMB*HDIM]; // Wq|Wk|Wv split
__device__ __half g_woh[EMB*EMB], g_wol[EMB*EMB];                 // Wo split
__device__ __half g_qh[NBATCH*NHEAD*TSEQ*HDIM], g_ql[NBATCH*NHEAD*TSEQ*HDIM];
__device__ __half g_kh[NBATCH*NHEAD*TSEQ*HDIM], g_kl[NBATCH*NHEAD*TSEQ*HDIM];
__device__ __half g_vh[NBATCH*NHEAD*TSEQ*HDIM], g_vl[NBATCH*NHEAD*TSEQ*HDIM];
__device__ __half g_ch[NTOK*EMB],  g_cl[NTOK*EMB];                 // attn combined

// ===========================================================================
// Helpers
// ===========================================================================
__device__ __forceinline__ uint32_t smem_u32(const void* p) {
    uint32_t a;
    asm("{ .reg .u64 t; cvta.to.shared.u64 t, %1; cvt.u32.u64 %0, t; }" : "=r"(a) : "l"(p));
    return a;
}
#define CP_ASYNC16(dst, src) asm volatile("cp.async.cg.shared.global [%0], [%1], 16;" :: "r"(dst), "l"(src))
#define CP_COMMIT()          asm volatile("cp.async.commit_group;" ::: "memory")
#define CP_WAIT0()           asm volatile("cp.async.wait_group 0;" ::: "memory")
#define CP_WAIT1()           asm volatile("cp.async.wait_group 1;" ::: "memory")

__device__ __forceinline__ void mma_f16(float* d, const uint32_t* a, const uint32_t* b) {
    asm volatile("mma.sync.aligned.m16n8k16.row.col.f32.f16.f16.f32 "
        "{%0,%1,%2,%3}, {%4,%5,%6,%7}, {%8,%9}, {%0,%1,%2,%3};"
        : "+f"(d[0]), "+f"(d[1]), "+f"(d[2]), "+f"(d[3])
        : "r"(a[0]), "r"(a[1]), "r"(a[2]), "r"(a[3]), "r"(b[0]), "r"(b[1]));
}
__device__ __forceinline__ void ldsm4(uint32_t* r, uint32_t a) {
    asm volatile("ldmatrix.sync.aligned.m8n8.x4.shared.b16 {%0,%1,%2,%3}, [%4];"
        : "=r"(r[0]), "=r"(r[1]), "=r"(r[2]), "=r"(r[3]) : "r"(a));
}
__device__ __forceinline__ void ldsm4t(uint32_t* r, uint32_t a) {
    asm volatile("ldmatrix.sync.aligned.m8n8.x4.trans.shared.b16 {%0,%1,%2,%3}, [%4];"
        : "=r"(r[0]), "=r"(r[1]), "=r"(r[2]), "=r"(r[3]) : "r"(a));
}
__device__ __forceinline__ void split_pair(float a, float b, uint32_t& hi, uint32_t& lo) {
    __half ha = __float2half_rn(a), hb = __float2half_rn(b);
    __half la = __float2half_rn(a - __half2float(ha));
    __half lb = __float2half_rn(b - __half2float(hb));
    hi = ((uint32_t)__half_as_ushort(hb) << 16) | (uint32_t)__half_as_ushort(ha);
    lo = ((uint32_t)__half_as_ushort(lb) << 16) | (uint32_t)__half_as_ushort(la);
}
__device__ __forceinline__ void split_wr2(float a, float b, __half* ph, __half* pl) {
    uint32_t hi, lo;
    split_pair(a, b, hi, lo);
    *(uint32_t*)ph = hi;
    *(uint32_t*)pl = lo;
}
// exp2 on fma pipe (no MUFU); valid for y <= 0
__device__ __forceinline__ float exp2p(float y) {
    y = fmaxf(y, -126.f);
    float r = rintf(y);
    float f = y - r;
    float p = fmaf(f, 1.3333558146e-3f, 9.6181291076e-3f);
    p = fmaf(f, p, 5.5504108664e-2f);
    p = fmaf(f, p, 2.4022650696e-1f);
    p = fmaf(f, p, 6.9314718056e-1f);
    p = fmaf(f, p, 1.0f);
    int n = (int)r;
    return p * __int_as_float((n + 127) << 23);
}

#define KCHUNK 32
#define NCHUNK (EMB / KCHUNK)   // 32
#define QSC 0.18033688011112042f  // 0.125 * log2(e)

// ---------------------------------------------------------------------------
// Kernel 0: prep — split x, Wq/Wk/Wv, Wo into hi/lo halves (float2-vectorized)
// ---------------------------------------------------------------------------
#define PREP_NX2  (NTOK*EMB/2)          // 2097152
#define PREP_NW2  (NHEAD*EMB*HDIM/2)    // 524288
#define PREP_NWO2 (EMB*EMB/2)           // 524288
#define PREP_TOT  (PREP_NX2 + 3*PREP_NW2 + PREP_NWO2)  // 4194304

__device__ __forceinline__ void split2_store(const float* s, __half* h, __half* l, int i2) {
    float2 v = ((const float2*)s)[i2];
    __half2 hv = __floats2half2_rn(v.x, v.y);
    float2 hr = __half22float2(hv);
    __half2 lv = __floats2half2_rn(v.x - hr.x, v.y - hr.y);
    ((__half2*)h)[i2] = hv;
    ((__half2*)l)[i2] = lv;
}

__global__ __launch_bounds__(256) void prep_kernel(
    const float* __restrict__ x, const float* __restrict__ Wq,
    const float* __restrict__ Wk, const float* __restrict__ Wv,
    const float* __restrict__ Wo)
{
    int idx = blockIdx.x * 256 + threadIdx.x;
    if (idx < PREP_NX2) { split2_store(x, g_xh, g_xl, idx); return; }
    idx -= PREP_NX2;
    if (idx < PREP_NW2) { split2_store(Wq, g_wh, g_wl, idx); return; }
    idx -= PREP_NW2;
    if (idx < PREP_NW2) { split2_store(Wk, g_wh + NHEAD*EMB*HDIM, g_wl + NHEAD*EMB*HDIM, idx); return; }
    idx -= PREP_NW2;
    if (idx < PREP_NW2) { split2_store(Wv, g_wh + 2*NHEAD*EMB*HDIM, g_wl + 2*NHEAD*EMB*HDIM, idx); return; }
    idx -= PREP_NW2;
    if (idx < PREP_NWO2) split2_store(Wo, g_woh, g_wol, idx);
}

// ---------------------------------------------------------------------------
// Kernel 1: QKV projection. grid=(32,16,3), 256 thr, block 128x64, warp 32x32.
// A = x halves [m][k]; B = W halves [k][n] (ldmatrix.trans). All pre-split.
// ---------------------------------------------------------------------------
#define QS_A 40
#define QS_B 72
#define QK_BUFH 14848            // halves per buffer
#define QK_AL   5120
#define QK_BH   10240
#define QK_BL   12544
#define QKV_SMEM (2*QK_BUFH*2)   // 59392 B

__device__ __forceinline__ void qkv_stage(uint32_t sbuf,
                                          const __half* wh, const __half* wl,
                                          int m0, int k0, int tid) {
    #pragma unroll
    for (int j = 0; j < 2; j++) {           // A hi: 512 cp (128 rows x 4)
        int idx = j * 256 + tid;
        int r = idx >> 2, q = idx & 3;
        CP_ASYNC16(sbuf + (uint32_t)(r*QS_A + q*8)*2,
                   g_xh + (size_t)(m0 + r)*EMB + k0 + q*8);
    }
    #pragma unroll
    for (int j = 0; j < 2; j++) {           // A lo
        int idx = j * 256 + tid;
        int r = idx >> 2, q = idx & 3;
        CP_ASYNC16(sbuf + (uint32_t)(QK_AL + r*QS_A + q*8)*2,
                   g_xl + (size_t)(m0 + r)*EMB + k0 + q*8);
    }
    {
        int k = tid >> 3, q = tid & 7;      // B: 32 rows x 8 chunks
        CP_ASYNC16(sbuf + (uint32_t)(QK_BH + k*QS_B + q*8)*2,
                   wh + (size_t)(k0 + k)*HDIM + q*8);
        CP_ASYNC16(sbuf + (uint32_t)(QK_BL + k*QS_B + q*8)*2,
                   wl + (size_t)(k0 + k)*HDIM + q*8);
    }
    CP_COMMIT();
}

__global__ __launch_bounds__(256, 2) void qkv_mma_kernel()
{
    extern __shared__ __align__(16) char sm[];
    const uint32_t sb = smem_u32(sm);
    const int tid = threadIdx.x;
    const int lane = tid & 31, wid = tid >> 5;
    const int gid = lane >> 2, tig = lane & 3;
    const int warp_m = wid >> 1, warp_n = wid & 1;
    const int m0 = blockIdx.x * 128, h = blockIdx.y, which = blockIdx.z;

    const __half* wh = g_wh + (size_t)(which*NHEAD + h)*EMB*HDIM;
    const __half* wl = g_wl + (size_t)(which*NHEAD + h)*EMB*HDIM;

    // per-lane fragment offsets (halves)
    const int offA  = ((lane & 7) + ((lane >> 3) & 1) * 8) * QS_A + (lane >> 4) * 8;
    const int offBt = ((lane & 7) + ((lane >> 3) & 1) * 8) * QS_B + (lane >> 4) * 8;

    float acc[2][4][4];
    #pragma unroll
    for (int mt = 0; mt < 2; mt++)
        #pragma unroll
        for (int nt = 0; nt < 4; nt++)
            #pragma unroll
            for (int e = 0; e < 4; e++) acc[mt][nt][e] = 0.f;

    qkv_stage(sb, wh, wl, m0, 0, tid);

    for (int ch = 0; ch < NCHUNK; ch++) {
        if (ch + 1 < NCHUNK) {
            qkv_stage(sb + ((ch + 1) & 1) * QK_BUFH * 2, wh, wl, m0, (ch + 1) * KCHUNK, tid);
            CP_WAIT1();
        } else {
            CP_WAIT0();
        }
        __syncthreads();

        const uint32_t bb = sb + (ch & 1) * QK_BUFH * 2;
        #pragma unroll
        for (int ks = 0; ks < 2; ks++) {
            uint32_t ahf[2][4], alf[2][4];
            #pragma unroll
            for (int mt = 0; mt < 2; mt++) {
                uint32_t ao = (uint32_t)(offA + (warp_m*32 + mt*16)*QS_A + ks*16) * 2;
                ldsm4(ahf[mt], bb + ao);
                ldsm4(alf[mt], bb + QK_AL*2 + ao);
            }
            #pragma unroll
            for (int ntp = 0; ntp < 2; ntp++) {
                uint32_t bhf[4], blf[4];
                uint32_t bo = (uint32_t)(offBt + (ks*16)*QS_B + warp_n*32 + ntp*16) * 2;
                ldsm4t(bhf, bb + QK_BH*2 + bo);
                ldsm4t(blf, bb + QK_BL*2 + bo);
                #pragma unroll
                for (int mt = 0; mt < 2; mt++) {
                    mma_f16(acc[mt][ntp*2],   ahf[mt], bhf);
                    mma_f16(acc[mt][ntp*2],   ahf[mt], blf);
                    mma_f16(acc[mt][ntp*2],   alf[mt], bhf);
                    mma_f16(acc[mt][ntp*2+1], ahf[mt], bhf + 2);
                    mma_f16(acc[mt][ntp*2+1], ahf[mt], blf + 2);
                    mma_f16(acc[mt][ntp*2+1], alf[mt], bhf + 2);
                }
            }
        }
        __syncthreads();
    }

    // epilogue: split into hi/lo half arrays (Q pre-scaled by QSC)
    __half *oh, *ol;
    if (which == 0)      { oh = g_qh; ol = g_ql; }
    else if (which == 1) { oh = g_kh; ol = g_kl; }
    else                 { oh = g_vh; ol = g_vl; }
    const float scale = (which == 0) ? QSC : 1.0f;

    #pragma unroll
    for (int mt = 0; mt < 2; mt++)
        #pragma unroll
        for (int nt = 0; nt < 4; nt++) {
            int n = warp_n * 32 + nt * 8 + 2 * tig;
            int m = m0 + warp_m * 32 + mt * 16 + gid;
            int b = m >> 11, t = m & (TSEQ - 1);
            size_t o0 = ((size_t)((b * NHEAD + h) * TSEQ + t)) * HDIM + n;
            split_wr2(acc[mt][nt][0] * scale, acc[mt][nt][1] * scale, oh + o0, ol + o0);
            int m2 = m + 8;
            b = m2 >> 11; t = m2 & (TSEQ - 1);
            size_t o1 = ((size_t)((b * NHEAD + h) * TSEQ + t)) * HDIM + n;
            split_wr2(acc[mt][nt][2] * scale, acc[mt][nt][3] * scale, oh + o1, ol + o1);
        }
}

// ---------------------------------------------------------------------------
// Kernel 2: flash attention. grid=(16,16,2), 256 thr (8 warps x 16 rows).
// K/V/Q pre-split halves; all frags via ldmatrix; exp on fma pipe.
// ---------------------------------------------------------------------------
#define AS 72
#define AT_BUFB 36864     // bytes per KV buffer (Kh|Kl|Vh|Vl @ 9216 each)
#define ATTN_SMEM (2 * AT_BUFB)   // 73728; Q staged in buffer-1 region pre-loop

__device__ __forceinline__ void attn_stage_kv(uint32_t sb,
    const __half* Kh, const __half* Kl, const __half* Vh, const __half* Vl,
    int kt, int tid)
{
    uint32_t bbuf = sb + (uint32_t)(kt & 1) * AT_BUFB;
    #pragma unroll
    for (int j = 0; j < 2; j++) {
        int idx = j * 256 + tid;           // 512 per array (64 rows x 8)
        int r = idx >> 3, q = idx & 7;
        uint32_t d = (uint32_t)(r * AS + q * 8) * 2;
        size_t s = (size_t)(kt * 64 + r) * HDIM + q * 8;
        CP_ASYNC16(bbuf + d,         Kh + s);
        CP_ASYNC16(bbuf + 9216 + d,  Kl + s);
        CP_ASYNC16(bbuf + 18432 + d, Vh + s);
        CP_ASYNC16(bbuf + 27648 + d, Vl + s);
    }
    CP_COMMIT();
}

__global__ __launch_bounds__(256) void attn_mma_kernel()
{
    extern __shared__ __align__(16) char sm[];
    const uint32_t sb = smem_u32(sm);
    const int tid = threadIdx.x;
    const int lane = tid & 31, wid = tid >> 5;
    const int gid = lane >> 2, tig = lane & 3;
    const int qt = blockIdx.x, h = blockIdx.y, b = blockIdx.z;
    const size_t base = (size_t)((b * NHEAD + h) * TSEQ) * HDIM;
    const __half* Qh = g_qh + base; const __half* Ql = g_ql + base;
    const __half* Kh = g_kh + base; const __half* Kl = g_kl + base;
    const __half* Vh = g_vh + base; const __half* Vl = g_vl + base;

    // per-lane fragment offsets (halves, stride AS)
    const int offQ = ((lane & 7) + ((lane >> 3) & 1) * 8) * AS + (lane >> 4) * 8; // A & trans-B
    const int offK = ((lane & 7) + (lane >> 4) * 8) * AS + ((lane >> 3) & 1) * 8; // non-trans B

    // stage Q halves into buffer-1 region, first KV tile into buffer 0
    #pragma unroll
    for (int j = 0; j < 4; j++) {
        int idx = j * 256 + tid;           // 1024 per array (128 rows x 8)
        int r = idx >> 3, q = idx & 7;
        uint32_t d = (uint32_t)(r * AS + q * 8) * 2;
        size_t s = (size_t)(qt * 128 + r) * HDIM + q * 8;
        CP_ASYNC16(sb + AT_BUFB + d,         Qh + s);
        CP_ASYNC16(sb + AT_BUFB + 18432 + d, Ql + s);
    }
    CP_COMMIT();
    attn_stage_kv(sb, Kh, Kl, Vh, Vl, 0, tid);
    CP_WAIT0();
    __syncthreads();

    // extract resident Q fragments (already scaled by QSC at producer)
    uint32_t qf_h[4][4], qf_l[4][4];
    #pragma unroll
    for (int ks = 0; ks < 4; ks++) {
        uint32_t ao = (uint32_t)(offQ + (wid * 16) * AS + ks * 16) * 2;
        ldsm4(qf_h[ks], sb + AT_BUFB + ao);
        ldsm4(qf_l[ks], sb + AT_BUFB + 18432 + ao);
    }
    __syncthreads();   // buffer-1 region free for KV reuse

    float o[8][4];
    #pragma unroll
    for (int nt = 0; nt < 8; nt++)
        #pragma unroll
        for (int e = 0; e < 4; e++) o[nt][e] = 0.f;
    float mr0 = -1e30f, mr1 = -1e30f, l0 = 0.f, l1 = 0.f;

    for (int kt = 0; kt < TSEQ / 64; kt++) {
        if (kt + 1 < TSEQ / 64) {
            attn_stage_kv(sb, Kh, Kl, Vh, Vl, kt + 1, tid);
            CP_WAIT1();
        } else {
            CP_WAIT0();
        }
        __syncthreads();

        const uint32_t kb = sb + (kt & 1) * AT_BUFB;

        // S = Q K^T (3-pass f16), log2 units
        float s[8][4];
        #pragma unroll
        for (int nt = 0; nt < 8; nt++)
            #pragma unroll
            for (int e = 0; e < 4; e++) s[nt][e] = 0.f;

        #pragma unroll
        for (int ks = 0; ks < 4; ks++) {
            #pragma unroll
            for (int ntp = 0; ntp < 4; ntp++) {
                uint32_t bh[4], bl[4];
                uint32_t ao = (uint32_t)(offK + (ntp * 16) * AS + ks * 16) * 2;
                ldsm4(bh, kb + ao);
                ldsm4(bl, kb + 9216 + ao);
                mma_f16(s[ntp*2],   qf_h[ks], bh);
                mma_f16(s[ntp*2],   qf_h[ks], bl);
                mma_f16(s[ntp*2],   qf_l[ks], bh);
                mma_f16(s[ntp*2+1], qf_h[ks], bh + 2);
                mma_f16(s[ntp*2+1], qf_h[ks], bl + 2);
                mma_f16(s[ntp*2+1], qf_l[ks], bh + 2);
            }
        }

        // online softmax (rows gid, gid+8)
        float tm0 = -1e30f, tm1 = -1e30f;
        #pragma unroll
        for (int nt = 0; nt < 8; nt++) {
            tm0 = fmaxf(tm0, fmaxf(s[nt][0], s[nt][1]));
            tm1 = fmaxf(tm1, fmaxf(s[nt][2], s[nt][3]));
        }
        tm0 = fmaxf(tm0, __shfl_xor_sync(0xffffffffu, tm0, 1));
        tm0 = fmaxf(tm0, __shfl_xor_sync(0xffffffffu, tm0, 2));
        tm1 = fmaxf(tm1, __shfl_xor_sync(0xffffffffu, tm1, 1));
        tm1 = fmaxf(tm1, __shfl_xor_sync(0xffffffffu, tm1, 2));
        float mn0 = fmaxf(mr0, tm0), mn1 = fmaxf(mr1, tm1);
        float al0 = exp2p(mr0 - mn0), al1 = exp2p(mr1 - mn1);
        mr0 = mn0; mr1 = mn1;

        float rs0 = 0.f, rs1 = 0.f;
        #pragma unroll
        for (int nt = 0; nt < 8; nt++) {
            s[nt][0] = exp2p(s[nt][0] - mn0);
            s[nt][1] = exp2p(s[nt][1] - mn0);
            s[nt][2] = exp2p(s[nt][2] - mn1);
            s[nt][3] = exp2p(s[nt][3] - mn1);
            rs0 += s[nt][0] + s[nt][1];
            rs1 += s[nt][2] + s[nt][3];
        }
        rs0 += __shfl_xor_sync(0xffffffffu, rs0, 1);
        rs0 += __shfl_xor_sync(0xffffffffu, rs0, 2);
        rs1 += __shfl_xor_sync(0xffffffffu, rs1, 1);
        rs1 += __shfl_xor_sync(0xffffffffu, rs1, 2);
        l0 = l0 * al0 + rs0;
        l1 = l1 * al1 + rs1;
        #pragma unroll
        for (int nt = 0; nt < 8; nt++) {
            o[nt][0] *= al0; o[nt][1] *= al0;
            o[nt][2] *= al1; o[nt][3] *= al1;
        }

        // O += P V (3-pass); P repacked in registers; V frags via ldmatrix.trans
        #pragma unroll
        for (int ks = 0; ks < 4; ks++) {
            uint32_t ah[4], aL[4];
            split_pair(s[2*ks][0],   s[2*ks][1],   ah[0], aL[0]);
            split_pair(s[2*ks][2],   s[2*ks][3],   ah[1], aL[1]);
            split_pair(s[2*ks+1][0], s[2*ks+1][1], ah[2], aL[2]);
            split_pair(s[2*ks+1][2], s[2*ks+1][3], ah[3], aL[3]);
            #pragma unroll
            for (int dtp = 0; dtp < 4; dtp++) {
                uint32_t bh[4], bl[4];
                uint32_t ao = (uint32_t)(offQ + (ks * 16) * AS + dtp * 16) * 2;
                ldsm4t(bh, kb + 18432 + ao);
                ldsm4t(bl, kb + 27648 + ao);
                mma_f16(o[dtp*2],   ah, bh);
                mma_f16(o[dtp*2],   ah, bl);
                mma_f16(o[dtp*2],   aL, bh);
                mma_f16(o[dtp*2+1], ah, bh + 2);
                mma_f16(o[dtp*2+1], ah, bl + 2);
                mma_f16(o[dtp*2+1], aL, bh + 2);
            }
        }
        __syncthreads();
    }

    // epilogue: normalize, split, write combined halves to g_ch/g_cl
    float inv0 = 1.f / l0, inv1 = 1.f / l1;
    int t0 = qt * 128 + wid * 16 + gid;
    #pragma unroll
    for (int nt = 0; nt < 8; nt++) {
        int col = h * HDIM + nt * 8 + 2 * tig;
        size_t o0 = (size_t)(b * TSEQ + t0) * EMB + col;
        size_t o1 = (size_t)(b * TSEQ + t0 + 8) * EMB + col;
        split_wr2(o[nt][0] * inv0, o[nt][1] * inv0, g_ch + o0, g_cl + o0);
        split_wr2(o[nt][2] * inv1, o[nt][3] * inv1, g_ch + o1, g_cl + o1);
    }
}

// ---------------------------------------------------------------------------
// Kernel 3: out = x + C @ Wo^T. grid=(32,16), 256 thr, block 128x64.
// A = C halves [m][k]; B = Wo halves [n][k] (non-trans). Pre-split.
// ---------------------------------------------------------------------------
#define OP_BUFH 15360
#define OP_AL   5120
#define OP_BH   10240
#define OP_BL   12800
#define OP_SMEM (2*OP_BUFH*2)    // 61440

__device__ __forceinline__ void op_stage(uint32_t sbuf, int m0, int n0, int k0, int tid) {
    #pragma unroll
    for (int j = 0; j < 2; j++) {           // A hi
        int idx = j * 256 + tid;
        int r = idx >> 2, q = idx & 3;
        CP_ASYNC16(sbuf + (uint32_t)(r*QS_A + q*8)*2,
                   g_ch + (size_t)(m0 + r)*EMB + k0 + q*8);
    }
    #pragma unroll
    for (int j = 0; j < 2; j++) {           // A lo
        int idx = j * 256 + tid;
        int r = idx >> 2, q = idx & 3;
        CP_ASYNC16(sbuf + (uint32_t)(OP_AL + r*QS_A + q*8)*2,
                   g_cl + (size_t)(m0 + r)*EMB + k0 + q*8);
    }
    {
        int n = tid >> 2, q = tid & 3;      // B: 64 rows x 4 chunks
        CP_ASYNC16(sbuf + (uint32_t)(OP_BH + n*QS_A + q*8)*2,
                   g_woh + (size_t)(n0 + n)*EMB + k0 + q*8);
        CP_ASYNC16(sbuf + (uint32_t)(OP_BL + n*QS_A + q*8)*2,
                   g_wol + (size_t)(n0 + n)*EMB + k0 + q*8);
    }
    CP_COMMIT();
}

__global__ __launch_bounds__(256, 2) void outproj_mma_kernel(
    const float* __restrict__ x, float* __restrict__ out)
{
    extern __shared__ __align__(16) char sm[];
    const uint32_t sb = smem_u32(sm);
    const int tid = threadIdx.x;
    const int lane = tid & 31, wid = tid >> 5;
    const int gid = lane >> 2, tig = lane & 3;
    const int warp_m = wid >> 1, warp_n = wid & 1;
    const int m0 = blockIdx.x * 128, n0 = blockIdx.y * 64;

    const int offA = ((lane & 7) + ((lane >> 3) & 1) * 8) * QS_A + (lane >> 4) * 8;
    const int offB = ((lane & 7) + (lane >> 4) * 8) * QS_A + ((lane >> 3) & 1) * 8;

    float acc[2][4][4];
    #pragma unroll
    for (int mt = 0; mt < 2; mt++)
        #pragma unroll
        for (int nt = 0; nt < 4; nt++)
            #pragma unroll
            for (int e = 0; e < 4; e++) acc[mt][nt][e] = 0.f;

    op_stage(sb, m0, n0, 0, tid);

    for (int ch = 0; ch < NCHUNK; ch++) {
        if (ch + 1 < NCHUNK) {
            op_stage(sb + ((ch + 1) & 1) * OP_BUFH * 2, m0, n0, (ch + 1) * KCHUNK, tid);
            CP_WAIT1();
        } else {
            CP_WAIT0();
        }
        __syncthreads();

        const uint32_t bb = sb + (ch & 1) * OP_BUFH * 2;
        #pragma unroll
        for (int ks = 0; ks < 2; ks++) {
            uint32_t ahf[2][4], alf[2][4];
            #pragma unroll
            for (int mt = 0; mt < 2; mt++) {
                uint32_t ao = (uint32_t)(offA + (warp_m*32 + mt*16)*QS_A + ks*16) * 2;
                ldsm4(ahf[mt], bb + ao);
                ldsm4(alf[mt], bb + OP_AL*2 + ao);
            }
            #pragma unroll
            for (int ntp = 0; ntp < 2; ntp++) {
                uint32_t bhf[4], blf[4];
                uint32_t bo = (uint32_t)(offB + (warp_n*32 + ntp*16)*QS_A + ks*16) * 2;
                ldsm4(bhf, bb + OP_BH*2 + bo);
                ldsm4(blf, bb + OP_BL*2 + bo);
                #pragma unroll
                for (int mt = 0; mt < 2; mt++) {
                    mma_f16(acc[mt][ntp*2],   ahf[mt], bhf);
                    mma_f16(acc[mt][ntp*2],   ahf[mt], blf);
                    mma_f16(acc[mt][ntp*2],   alf[mt], bhf);
                    mma_f16(acc[mt][ntp*2+1], ahf[mt], bhf + 2);
                    mma_f16(acc[mt][ntp*2+1], ahf[mt], blf + 2);
                    mma_f16(acc[mt][ntp*2+1], alf[mt], bhf + 2);
                }
            }
        }
        __syncthreads();
    }

    #pragma unroll
    for (int mt = 0; mt < 2; mt++)
        #pragma unroll
        for (int nt = 0; nt < 4; nt++) {
            int n = n0 + warp_n * 32 + nt * 8 + tig * 2;
            int m = m0 + warp_m * 32 + mt * 16 + gid;
            {
                size_t off = (size_t)m * EMB + n;
                float2 xv = *(const float2*)&x[off];
                *(float2*)&out[off] = make_float2(acc[mt][nt][0] + xv.x, acc[mt][nt][1] + xv.y);
            }
            {
                size_t off = (size_t)(m + 8) * EMB + n;
                float2 xv = *(const float2*)&x[off];
                *(float2*)&out[off] = make_float2(acc[mt][nt][2] + xv.x, acc[mt][nt][3] + xv.y);
            }
        }
}

extern "C" void kernel_launch(void* const* d_in, const int* in_sizes, int n_in,
                              void* d_out, int out_size)
{
    const float* x  = (const float*)d_in[0];
    const float* Wq = (const float*)d_in[1];
    const float* Wk = (const float*)d_in[2];
    const float* Wv = (const float*)d_in[3];
    const float* Wo = (const float*)d_in[4];
    float* out = (float*)d_out;

    cudaFuncSetAttribute(qkv_mma_kernel, cudaFuncAttributeMaxDynamicSharedMemorySize, QKV_SMEM);
    cudaFuncSetAttribute(attn_mma_kernel, cudaFuncAttributeMaxDynamicSharedMemorySize, ATTN_SMEM);
    cudaFuncSetAttribute(outproj_mma_kernel, cudaFuncAttributeMaxDynamicSharedMemorySize, OP_SMEM);

    prep_kernel<<<PREP_TOT / 256, 256>>>(x, Wq, Wk, Wv, Wo);

    dim3 g1(NTOK / 128, NHEAD, 3);
    qkv_mma_kernel<<<g1, 256, QKV_SMEM>>>();

    dim3 g2(TSEQ / 128, NHEAD, NBATCH);
    attn_mma_kernel<<<g2, 256, ATTN_SMEM>>>();

    dim3 g3(NTOK / 128, EMB / 64);
    outproj_mma_kernel<<<g3, 256, OP_SMEM>>>(x, out);
}

// round 13
// speedup vs baseline: 2.9691x; 1.1699x over previous
#include <cuda_runtime.h>
#include <cuda_fp16.h>
#include <math.h>
#include <stdint.h>

#define NBATCH 2
#define TSEQ   2048
#define EMB    1024
#define NHEAD  16
#define HDIM   64
#define NTOK   (NBATCH*TSEQ)   // 4096

// ---------------------------------------------------------------------------
// Persistent hi/lo half scratch (allocation-free)
// ---------------------------------------------------------------------------
__device__ __half g_xh[NTOK*EMB],  g_xl[NTOK*EMB];                 // x split
__device__ __half g_wh[3*NHEAD*EMB*HDIM], g_wl[3*NHEAD*EMB*HDIM]; // Wq|Wk|Wv split
__device__ __half g_woh[EMB*EMB], g_wol[EMB*EMB];                 // Wo split
__device__ __half g_qh[NBATCH*NHEAD*TSEQ*HDIM], g_ql[NBATCH*NHEAD*TSEQ*HDIM];
__device__ __half g_kh[NBATCH*NHEAD*TSEQ*HDIM], g_kl[NBATCH*NHEAD*TSEQ*HDIM];
__device__ __half g_vh[NBATCH*NHEAD*TSEQ*HDIM], g_vl[NBATCH*NHEAD*TSEQ*HDIM];
__device__ __half g_ch[NTOK*EMB];                                  // attn combined (f16 only)

// ===========================================================================
// Helpers
// ===========================================================================
__device__ __forceinline__ uint32_t smem_u32(const void* p) {
    uint32_t a;
    asm("{ .reg .u64 t; cvta.to.shared.u64 t, %1; cvt.u32.u64 %0, t; }" : "=r"(a) : "l"(p));
    return a;
}
#define CP_ASYNC16(dst, src) asm volatile("cp.async.cg.shared.global [%0], [%1], 16;" :: "r"(dst), "l"(src))
#define CP_COMMIT()          asm volatile("cp.async.commit_group;" ::: "memory")
#define CP_WAIT0()           asm volatile("cp.async.wait_group 0;" ::: "memory")
#define CP_WAIT1()           asm volatile("cp.async.wait_group 1;" ::: "memory")

__device__ __forceinline__ void mma_f16(float* d, const uint32_t* a, const uint32_t* b) {
    asm volatile("mma.sync.aligned.m16n8k16.row.col.f32.f16.f16.f32 "
        "{%0,%1,%2,%3}, {%4,%5,%6,%7}, {%8,%9}, {%0,%1,%2,%3};"
        : "+f"(d[0]), "+f"(d[1]), "+f"(d[2]), "+f"(d[3])
        : "r"(a[0]), "r"(a[1]), "r"(a[2]), "r"(a[3]), "r"(b[0]), "r"(b[1]));
}
__device__ __forceinline__ void ldsm4(uint32_t* r, uint32_t a) {
    asm volatile("ldmatrix.sync.aligned.m8n8.x4.shared.b16 {%0,%1,%2,%3}, [%4];"
        : "=r"(r[0]), "=r"(r[1]), "=r"(r[2]), "=r"(r[3]) : "r"(a));
}
__device__ __forceinline__ void ldsm4t(uint32_t* r, uint32_t a) {
    asm volatile("ldmatrix.sync.aligned.m8n8.x4.trans.shared.b16 {%0,%1,%2,%3}, [%4];"
        : "=r"(r[0]), "=r"(r[1]), "=r"(r[2]), "=r"(r[3]) : "r"(a));
}
__device__ __forceinline__ uint32_t pack_h2(float a, float b) {
    __half2 h = __floats2half2_rn(a, b);
    return *(uint32_t*)&h;
}
__device__ __forceinline__ void split_wr2(float a, float b, __half* ph, __half* pl) {
    __half ha = __float2half_rn(a), hb = __float2half_rn(b);
    __half la = __float2half_rn(a - __half2float(ha));
    __half lb = __float2half_rn(b - __half2float(hb));
    *(uint32_t*)ph = ((uint32_t)__half_as_ushort(hb) << 16) | (uint32_t)__half_as_ushort(ha);
    *(uint32_t*)pl = ((uint32_t)__half_as_ushort(lb) << 16) | (uint32_t)__half_as_ushort(la);
}
// exp2 on fma pipe (no MUFU); valid for y <= 0
__device__ __forceinline__ float exp2p(float y) {
    y = fmaxf(y, -126.f);
    float r = rintf(y);
    float f = y - r;
    float p = fmaf(f, 1.3333558146e-3f, 9.6181291076e-3f);
    p = fmaf(f, p, 5.5504108664e-2f);
    p = fmaf(f, p, 2.4022650696e-1f);
    p = fmaf(f, p, 6.9314718056e-1f);
    p = fmaf(f, p, 1.0f);
    int n = (int)r;
    return p * __int_as_float((n + 127) << 23);
}

#define KCHUNK 64
#define NCHUNK (EMB / KCHUNK)   // 16
#define QSC 0.18033688011112042f  // 0.125 * log2(e)
#define SGS 72                    // shared stride (halves) for all k-major tiles

// ---------------------------------------------------------------------------
// Kernel 0: prep — split x, Wq/Wk/Wv, Wo into hi/lo halves
// ---------------------------------------------------------------------------
#define PREP_NX2  (NTOK*EMB/2)
#define PREP_NW2  (NHEAD*EMB*HDIM/2)
#define PREP_NWO2 (EMB*EMB/2)
#define PREP_TOT  (PREP_NX2 + 3*PREP_NW2 + PREP_NWO2)

__device__ __forceinline__ void split2_store(const float* s, __half* h, __half* l, int i2) {
    float2 v = ((const float2*)s)[i2];
    __half2 hv = __floats2half2_rn(v.x, v.y);
    float2 hr = __half22float2(hv);
    __half2 lv = __floats2half2_rn(v.x - hr.x, v.y - hr.y);
    ((__half2*)h)[i2] = hv;
    ((__half2*)l)[i2] = lv;
}

__global__ __launch_bounds__(256) void prep_kernel(
    const float* __restrict__ x, const float* __restrict__ Wq,
    const float* __restrict__ Wk, const float* __restrict__ Wv,
    const float* __restrict__ Wo)
{
    int idx = blockIdx.x * 256 + threadIdx.x;
    if (idx < PREP_NX2) { split2_store(x, g_xh, g_xl, idx); return; }
    idx -= PREP_NX2;
    if (idx < PREP_NW2) { split2_store(Wq, g_wh, g_wl, idx); return; }
    idx -= PREP_NW2;
    if (idx < PREP_NW2) { split2_store(Wk, g_wh + NHEAD*EMB*HDIM, g_wl + NHEAD*EMB*HDIM, idx); return; }
    idx -= PREP_NW2;
    if (idx < PREP_NW2) { split2_store(Wv, g_wh + 2*NHEAD*EMB*HDIM, g_wl + 2*NHEAD*EMB*HDIM, idx); return; }
    idx -= PREP_NW2;
    if (idx < PREP_NWO2) split2_store(Wo, g_woh, g_wol, idx);
}

// ---------------------------------------------------------------------------
// Kernel 1: QKV projection. grid=(32,16,3), 256 thr, block 128x64, warp 32x32.
// KCHUNK=64: buffer = Ah[128x72] Al Bh[64x72] Bl (halves). 3-pass.
// ---------------------------------------------------------------------------
#define QK_AL   9216
#define QK_BH   18432
#define QK_BL   23040
#define QK_BUFH 27648
#define QKV_SMEM (2*QK_BUFH*2)   // 110592 B

__device__ __forceinline__ void qkv_stage(uint32_t sbuf,
                                          const __half* wh, const __half* wl,
                                          int m0, int k0, int tid) {
    #pragma unroll
    for (int j = 0; j < 4; j++) {           // A hi: 1024 cp (128 rows x 8)
        int idx = j * 256 + tid;
        int r = idx >> 3, q = idx & 7;
        CP_ASYNC16(sbuf + (uint32_t)(r*SGS + q*8)*2,
                   g_xh + (size_t)(m0 + r)*EMB + k0 + q*8);
    }
    #pragma unroll
    for (int j = 0; j < 4; j++) {           // A lo
        int idx = j * 256 + tid;
        int r = idx >> 3, q = idx & 7;
        CP_ASYNC16(sbuf + (uint32_t)(QK_AL + r*SGS + q*8)*2,
                   g_xl + (size_t)(m0 + r)*EMB + k0 + q*8);
    }
    #pragma unroll
    for (int j = 0; j < 2; j++) {           // B hi: 512 cp (64 k-rows x 8)
        int idx = j * 256 + tid;
        int k = idx >> 3, q = idx & 7;
        CP_ASYNC16(sbuf + (uint32_t)(QK_BH + k*SGS + q*8)*2,
                   wh + (size_t)(k0 + k)*HDIM + q*8);
    }
    #pragma unroll
    for (int j = 0; j < 2; j++) {           // B lo
        int idx = j * 256 + tid;
        int k = idx >> 3, q = idx & 7;
        CP_ASYNC16(sbuf + (uint32_t)(QK_BL + k*SGS + q*8)*2,
                   wl + (size_t)(k0 + k)*HDIM + q*8);
    }
    CP_COMMIT();
}

__global__ __launch_bounds__(256, 2) void qkv_mma_kernel()
{
    extern __shared__ __align__(16) char sm[];
    const uint32_t sb = smem_u32(sm);
    const int tid = threadIdx.x;
    const int lane = tid & 31, wid = tid >> 5;
    const int gid = lane >> 2, tig = lane & 3;
    const int warp_m = wid >> 1, warp_n = wid & 1;
    const int m0 = blockIdx.x * 128, h = blockIdx.y, which = blockIdx.z;

    const __half* wh = g_wh + (size_t)(which*NHEAD + h)*EMB*HDIM;
    const __half* wl = g_wl + (size_t)(which*NHEAD + h)*EMB*HDIM;

    const int offA  = ((lane & 7) + ((lane >> 3) & 1) * 8) * SGS + (lane >> 4) * 8;
    const int offBt = ((lane & 7) + ((lane >> 3) & 1) * 8) * SGS + (lane >> 4) * 8;

    float acc[2][4][4];
    #pragma unroll
    for (int mt = 0; mt < 2; mt++)
        #pragma unroll
        for (int nt = 0; nt < 4; nt++)
            #pragma unroll
            for (int e = 0; e < 4; e++) acc[mt][nt][e] = 0.f;

    qkv_stage(sb, wh, wl, m0, 0, tid);

    for (int ch = 0; ch < NCHUNK; ch++) {
        if (ch + 1 < NCHUNK) {
            qkv_stage(sb + ((ch + 1) & 1) * QK_BUFH * 2, wh, wl, m0, (ch + 1) * KCHUNK, tid);
            CP_WAIT1();
        } else {
            CP_WAIT0();
        }
        __syncthreads();

        const uint32_t bb = sb + (ch & 1) * QK_BUFH * 2;
        #pragma unroll
        for (int ks = 0; ks < 4; ks++) {
            uint32_t ahf[2][4], alf[2][4];
            #pragma unroll
            for (int mt = 0; mt < 2; mt++) {
                uint32_t ao = (uint32_t)(offA + (warp_m*32 + mt*16)*SGS + ks*16) * 2;
                ldsm4(ahf[mt], bb + ao);
                ldsm4(alf[mt], bb + QK_AL*2 + ao);
            }
            #pragma unroll
            for (int ntp = 0; ntp < 2; ntp++) {
                uint32_t bhf[4], blf[4];
                uint32_t bo = (uint32_t)(offBt + (ks*16)*SGS + warp_n*32 + ntp*16) * 2;
                ldsm4t(bhf, bb + QK_BH*2 + bo);
                ldsm4t(blf, bb + QK_BL*2 + bo);
                #pragma unroll
                for (int mt = 0; mt < 2; mt++) {
                    mma_f16(acc[mt][ntp*2],   ahf[mt], bhf);
                    mma_f16(acc[mt][ntp*2],   ahf[mt], blf);
                    mma_f16(acc[mt][ntp*2],   alf[mt], bhf);
                    mma_f16(acc[mt][ntp*2+1], ahf[mt], bhf + 2);
                    mma_f16(acc[mt][ntp*2+1], ahf[mt], blf + 2);
                    mma_f16(acc[mt][ntp*2+1], alf[mt], bhf + 2);
                }
            }
        }
        __syncthreads();
    }

    // epilogue: split into hi/lo half arrays (Q pre-scaled by QSC)
    __half *oh, *ol;
    if (which == 0)      { oh = g_qh; ol = g_ql; }
    else if (which == 1) { oh = g_kh; ol = g_kl; }
    else                 { oh = g_vh; ol = g_vl; }
    const float scale = (which == 0) ? QSC : 1.0f;

    #pragma unroll
    for (int mt = 0; mt < 2; mt++)
        #pragma unroll
        for (int nt = 0; nt < 4; nt++) {
            int n = warp_n * 32 + nt * 8 + 2 * tig;
            int m = m0 + warp_m * 32 + mt * 16 + gid;
            int b = m >> 11, t = m & (TSEQ - 1);
            size_t o0 = ((size_t)((b * NHEAD + h) * TSEQ + t)) * HDIM + n;
            split_wr2(acc[mt][nt][0] * scale, acc[mt][nt][1] * scale, oh + o0, ol + o0);
            int m2 = m + 8;
            b = m2 >> 11; t = m2 & (TSEQ - 1);
            size_t o1 = ((size_t)((b * NHEAD + h) * TSEQ + t)) * HDIM + n;
            split_wr2(acc[mt][nt][2] * scale, acc[mt][nt][3] * scale, oh + o1, ol + o1);
        }
}

// ---------------------------------------------------------------------------
// Kernel 2: flash attention. grid=(16,16,2), 256 thr (8 warps x 16 rows).
// QK^T 3-pass; PV 2-pass (P_hi only). exp on fma pipe.
// ---------------------------------------------------------------------------
#define AS 72
#define AT_BUFB 36864     // bytes per KV buffer (Kh|Kl|Vh|Vl @ 9216 each)
#define ATTN_SMEM (2 * AT_BUFB)   // 73728; Q staged in buffer-1 region pre-loop

__device__ __forceinline__ void attn_stage_kv(uint32_t sb,
    const __half* Kh, const __half* Kl, const __half* Vh, const __half* Vl,
    int kt, int tid)
{
    uint32_t bbuf = sb + (uint32_t)(kt & 1) * AT_BUFB;
    #pragma unroll
    for (int j = 0; j < 2; j++) {
        int idx = j * 256 + tid;           // 512 per array (64 rows x 8)
        int r = idx >> 3, q = idx & 7;
        uint32_t d = (uint32_t)(r * AS + q * 8) * 2;
        size_t s = (size_t)(kt * 64 + r) * HDIM + q * 8;
        CP_ASYNC16(bbuf + d,         Kh + s);
        CP_ASYNC16(bbuf + 9216 + d,  Kl + s);
        CP_ASYNC16(bbuf + 18432 + d, Vh + s);
        CP_ASYNC16(bbuf + 27648 + d, Vl + s);
    }
    CP_COMMIT();
}

__global__ __launch_bounds__(256) void attn_mma_kernel()
{
    extern __shared__ __align__(16) char sm[];
    const uint32_t sb = smem_u32(sm);
    const int tid = threadIdx.x;
    const int lane = tid & 31, wid = tid >> 5;
    const int gid = lane >> 2, tig = lane & 3;
    const int qt = blockIdx.x, h = blockIdx.y, b = blockIdx.z;
    const size_t base = (size_t)((b * NHEAD + h) * TSEQ) * HDIM;
    const __half* Qh = g_qh + base; const __half* Ql = g_ql + base;
    const __half* Kh = g_kh + base; const __half* Kl = g_kl + base;
    const __half* Vh = g_vh + base; const __half* Vl = g_vl + base;

    const int offQ = ((lane & 7) + ((lane >> 3) & 1) * 8) * AS + (lane >> 4) * 8; // A & trans-B
    const int offK = ((lane & 7) + (lane >> 4) * 8) * AS + ((lane >> 3) & 1) * 8; // non-trans B

    // stage Q halves into buffer-1 region, first KV tile into buffer 0
    #pragma unroll
    for (int j = 0; j < 4; j++) {
        int idx = j * 256 + tid;           // 1024 per array (128 rows x 8)
        int r = idx >> 3, q = idx & 7;
        uint32_t d = (uint32_t)(r * AS + q * 8) * 2;
        size_t s = (size_t)(qt * 128 + r) * HDIM + q * 8;
        CP_ASYNC16(sb + AT_BUFB + d,         Qh + s);
        CP_ASYNC16(sb + AT_BUFB + 18432 + d, Ql + s);
    }
    CP_COMMIT();
    attn_stage_kv(sb, Kh, Kl, Vh, Vl, 0, tid);
    CP_WAIT0();
    __syncthreads();

    // extract resident Q fragments (already scaled by QSC at producer)
    uint32_t qf_h[4][4], qf_l[4][4];
    #pragma unroll
    for (int ks = 0; ks < 4; ks++) {
        uint32_t ao = (uint32_t)(offQ + (wid * 16) * AS + ks * 16) * 2;
        ldsm4(qf_h[ks], sb + AT_BUFB + ao);
        ldsm4(qf_l[ks], sb + AT_BUFB + 18432 + ao);
    }
    __syncthreads();   // buffer-1 region free for KV reuse

    float o[8][4];
    #pragma unroll
    for (int nt = 0; nt < 8; nt++)
        #pragma unroll
        for (int e = 0; e < 4; e++) o[nt][e] = 0.f;
    float mr0 = -1e30f, mr1 = -1e30f, l0 = 0.f, l1 = 0.f;

    for (int kt = 0; kt < TSEQ / 64; kt++) {
        if (kt + 1 < TSEQ / 64) {
            attn_stage_kv(sb, Kh, Kl, Vh, Vl, kt + 1, tid);
            CP_WAIT1();
        } else {
            CP_WAIT0();
        }
        __syncthreads();

        const uint32_t kb = sb + (kt & 1) * AT_BUFB;

        // S = Q K^T (3-pass f16), log2 units
        float s[8][4];
        #pragma unroll
        for (int nt = 0; nt < 8; nt++)
            #pragma unroll
            for (int e = 0; e < 4; e++) s[nt][e] = 0.f;

        #pragma unroll
        for (int ks = 0; ks < 4; ks++) {
            #pragma unroll
            for (int ntp = 0; ntp < 4; ntp++) {
                uint32_t bh[4], bl[4];
                uint32_t ao = (uint32_t)(offK + (ntp * 16) * AS + ks * 16) * 2;
                ldsm4(bh, kb + ao);
                ldsm4(bl, kb + 9216 + ao);
                mma_f16(s[ntp*2],   qf_h[ks], bh);
                mma_f16(s[ntp*2],   qf_h[ks], bl);
                mma_f16(s[ntp*2],   qf_l[ks], bh);
                mma_f16(s[ntp*2+1], qf_h[ks], bh + 2);
                mma_f16(s[ntp*2+1], qf_h[ks], bl + 2);
                mma_f16(s[ntp*2+1], qf_l[ks], bh + 2);
            }
        }

        // online softmax (rows gid, gid+8)
        float tm0 = -1e30f, tm1 = -1e30f;
        #pragma unroll
        for (int nt = 0; nt < 8; nt++) {
            tm0 = fmaxf(tm0, fmaxf(s[nt][0], s[nt][1]));
            tm1 = fmaxf(tm1, fmaxf(s[nt][2], s[nt][3]));
        }
        tm0 = fmaxf(tm0, __shfl_xor_sync(0xffffffffu, tm0, 1));
        tm0 = fmaxf(tm0, __shfl_xor_sync(0xffffffffu, tm0, 2));
        tm1 = fmaxf(tm1, __shfl_xor_sync(0xffffffffu, tm1, 1));
        tm1 = fmaxf(tm1, __shfl_xor_sync(0xffffffffu, tm1, 2));
        float mn0 = fmaxf(mr0, tm0), mn1 = fmaxf(mr1, tm1);
        float al0 = exp2p(mr0 - mn0), al1 = exp2p(mr1 - mn1);
        mr0 = mn0; mr1 = mn1;

        float rs0 = 0.f, rs1 = 0.f;
        #pragma unroll
        for (int nt = 0; nt < 8; nt++) {
            s[nt][0] = exp2p(s[nt][0] - mn0);
            s[nt][1] = exp2p(s[nt][1] - mn0);
            s[nt][2] = exp2p(s[nt][2] - mn1);
            s[nt][3] = exp2p(s[nt][3] - mn1);
            rs0 += s[nt][0] + s[nt][1];
            rs1 += s[nt][2] + s[nt][3];
        }
        rs0 += __shfl_xor_sync(0xffffffffu, rs0, 1);
        rs0 += __shfl_xor_sync(0xffffffffu, rs0, 2);
        rs1 += __shfl_xor_sync(0xffffffffu, rs1, 1);
        rs1 += __shfl_xor_sync(0xffffffffu, rs1, 2);
        l0 = l0 * al0 + rs0;
        l1 = l1 * al1 + rs1;
        #pragma unroll
        for (int nt = 0; nt < 8; nt++) {
            o[nt][0] *= al0; o[nt][1] *= al0;
            o[nt][2] *= al1; o[nt][3] *= al1;
        }

        // O += P V (2-pass: P_hi x V_hi + P_hi x V_lo); P packed in registers
        #pragma unroll
        for (int ks = 0; ks < 4; ks++) {
            uint32_t ah[4];
            ah[0] = pack_h2(s[2*ks][0],   s[2*ks][1]);
            ah[1] = pack_h2(s[2*ks][2],   s[2*ks][3]);
            ah[2] = pack_h2(s[2*ks+1][0], s[2*ks+1][1]);
            ah[3] = pack_h2(s[2*ks+1][2], s[2*ks+1][3]);
            #pragma unroll
            for (int dtp = 0; dtp < 4; dtp++) {
                uint32_t bh[4], bl[4];
                uint32_t ao = (uint32_t)(offQ + (ks * 16) * AS + dtp * 16) * 2;
                ldsm4t(bh, kb + 18432 + ao);
                ldsm4t(bl, kb + 27648 + ao);
                mma_f16(o[dtp*2],   ah, bh);
                mma_f16(o[dtp*2],   ah, bl);
                mma_f16(o[dtp*2+1], ah, bh + 2);
                mma_f16(o[dtp*2+1], ah, bl + 2);
            }
        }
        __syncthreads();
    }

    // epilogue: normalize, write combined C as f16 (hi only)
    float inv0 = 1.f / l0, inv1 = 1.f / l1;
    int t0 = qt * 128 + wid * 16 + gid;
    #pragma unroll
    for (int nt = 0; nt < 8; nt++) {
        int col = h * HDIM + nt * 8 + 2 * tig;
        size_t o0 = (size_t)(b * TSEQ + t0) * EMB + col;
        size_t o1 = (size_t)(b * TSEQ + t0 + 8) * EMB + col;
        *(uint32_t*)(g_ch + o0) = pack_h2(o[nt][0] * inv0, o[nt][1] * inv0);
        *(uint32_t*)(g_ch + o1) = pack_h2(o[nt][2] * inv1, o[nt][3] * inv1);
    }
}

// ---------------------------------------------------------------------------
// Kernel 3: out = x + C @ Wo^T. grid=(32,16), 256 thr. 2-pass (C_hi only).
// KCHUNK=64: buffer = Ah[128x72] Bh[64x72] Bl (halves).
// ---------------------------------------------------------------------------
#define OP_BH   9216
#define OP_BL   13824
#define OP_BUFH 18432
#define OP_SMEM (2*OP_BUFH*2)    // 73728

__device__ __forceinline__ void op_stage(uint32_t sbuf, int m0, int n0, int k0, int tid) {
    #pragma unroll
    for (int j = 0; j < 4; j++) {           // A hi: 1024 cp
        int idx = j * 256 + tid;
        int r = idx >> 3, q = idx & 7;
        CP_ASYNC16(sbuf + (uint32_t)(r*SGS + q*8)*2,
                   g_ch + (size_t)(m0 + r)*EMB + k0 + q*8);
    }
    #pragma unroll
    for (int j = 0; j < 2; j++) {           // B hi: 512 cp (64 n-rows x 8)
        int idx = j * 256 + tid;
        int n = idx >> 3, q = idx & 7;
        CP_ASYNC16(sbuf + (uint32_t)(OP_BH + n*SGS + q*8)*2,
                   g_woh + (size_t)(n0 + n)*EMB + k0 + q*8);
    }
    #pragma unroll
    for (int j = 0; j < 2; j++) {           // B lo
        int idx = j * 256 + tid;
        int n = idx >> 3, q = idx & 7;
        CP_ASYNC16(sbuf + (uint32_t)(OP_BL + n*SGS + q*8)*2,
                   g_wol + (size_t)(n0 + n)*EMB + k0 + q*8);
    }
    CP_COMMIT();
}

__global__ __launch_bounds__(256, 2) void outproj_mma_kernel(
    const float* __restrict__ x, float* __restrict__ out)
{
    extern __shared__ __align__(16) char sm[];
    const uint32_t sb = smem_u32(sm);
    const int tid = threadIdx.x;
    const int lane = tid & 31, wid = tid >> 5;
    const int gid = lane >> 2, tig = lane & 3;
    const int warp_m = wid >> 1, warp_n = wid & 1;
    const int m0 = blockIdx.x * 128, n0 = blockIdx.y * 64;

    const int offA = ((lane & 7) + ((lane >> 3) & 1) * 8) * SGS + (lane >> 4) * 8;
    const int offB = ((lane & 7) + (lane >> 4) * 8) * SGS + ((lane >> 3) & 1) * 8;

    float acc[2][4][4];
    #pragma unroll
    for (int mt = 0; mt < 2; mt++)
        #pragma unroll
        for (int nt = 0; nt < 4; nt++)
            #pragma unroll
            for (int e = 0; e < 4; e++) acc[mt][nt][e] = 0.f;

    op_stage(sb, m0, n0, 0, tid);

    for (int ch = 0; ch < NCHUNK; ch++) {
        if (ch + 1 < NCHUNK) {
            op_stage(sb + ((ch + 1) & 1) * OP_BUFH * 2, m0, n0, (ch + 1) * KCHUNK, tid);
            CP_WAIT1();
        } else {
            CP_WAIT0();
        }
        __syncthreads();

        const uint32_t bb = sb + (ch & 1) * OP_BUFH * 2;
        #pragma unroll
        for (int ks = 0; ks < 4; ks++) {
            uint32_t ahf[2][4];
            #pragma unroll
            for (int mt = 0; mt < 2; mt++) {
                uint32_t ao = (uint32_t)(offA + (warp_m*32 + mt*16)*SGS + ks*16) * 2;
                ldsm4(ahf[mt], bb + ao);
            }
            #pragma unroll
            for (int ntp = 0; ntp < 2; ntp++) {
                uint32_t bhf[4], blf[4];
                uint32_t bo = (uint32_t)(offB + (warp_n*32 + ntp*16)*SGS + ks*16) * 2;
                ldsm4(bhf, bb + OP_BH*2 + bo);
                ldsm4(blf, bb + OP_BL*2 + bo);
                #pragma unroll
                for (int mt = 0; mt < 2; mt++) {
                    mma_f16(acc[mt][ntp*2],   ahf[mt], bhf);
                    mma_f16(acc[mt][ntp*2],   ahf[mt], blf);
                    mma_f16(acc[mt][ntp*2+1], ahf[mt], bhf + 2);
                    mma_f16(acc[mt][ntp*2+1], ahf[mt], blf + 2);
                }
            }
        }
        __syncthreads();
    }

    #pragma unroll
    for (int mt = 0; mt < 2; mt++)
        #pragma unroll
        for (int nt = 0; nt < 4; nt++) {
            int n = n0 + warp_n * 32 + nt * 8 + tig * 2;
            int m = m0 + warp_m * 32 + mt * 16 + gid;
            {
                size_t off = (size_t)m * EMB + n;
                float2 xv = *(const float2*)&x[off];
                *(float2*)&out[off] = make_float2(acc[mt][nt][0] + xv.x, acc[mt][nt][1] + xv.y);
            }
            {
                size_t off = (size_t)(m + 8) * EMB + n;
                float2 xv = *(const float2*)&x[off];
                *(float2*)&out[off] = make_float2(acc[mt][nt][2] + xv.x, acc[mt][nt][3] + xv.y);
            }
        }
}

extern "C" void kernel_launch(void* const* d_in, const int* in_sizes, int n_in,
                              void* d_out, int out_size)
{
    const float* x  = (const float*)d_in[0];
    const float* Wq = (const float*)d_in[1];
    const float* Wk = (const float*)d_in[2];
    const float* Wv = (const float*)d_in[3];
    const float* Wo = (const float*)d_in[4];
    float* out = (float*)d_out;

    cudaFuncSetAttribute(qkv_mma_kernel, cudaFuncAttributeMaxDynamicSharedMemorySize, QKV_SMEM);
    cudaFuncSetAttribute(attn_mma_kernel, cudaFuncAttributeMaxDynamicSharedMemorySize, ATTN_SMEM);
    cudaFuncSetAttribute(outproj_mma_kernel, cudaFuncAttributeMaxDynamicSharedMemorySize, OP_SMEM);

    prep_kernel<<<PREP_TOT / 256, 256>>>(x, Wq, Wk, Wv, Wo);

    dim3 g1(NTOK / 128, NHEAD, 3);
    qkv_mma_kernel<<<g1, 256, QKV_SMEM>>>();

    dim3 g2(TSEQ / 128, NHEAD, NBATCH);
    attn_mma_kernel<<<g2, 256, ATTN_SMEM>>>();

    dim3 g3(NTOK / 128, EMB / 64);
    outproj_mma_kernel<<<g3, 256, OP_SMEM>>>(x, out);
}

// round 14
// speedup vs baseline: 3.3247x; 1.1198x over previous
#include <cuda_runtime.h>
#include <cuda_fp16.h>
#include <math.h>
#include <stdint.h>

#define NBATCH 2
#define TSEQ   2048
#define EMB    1024
#define NHEAD  16
#define HDIM   64
#define NTOK   (NBATCH*TSEQ)   // 4096

// ---------------------------------------------------------------------------
// Persistent hi/lo half scratch (allocation-free)
// ---------------------------------------------------------------------------
__device__ __half g_xh[NTOK*EMB],  g_xl[NTOK*EMB];                 // x split
__device__ __half g_wh[3*NHEAD*EMB*HDIM], g_wl[3*NHEAD*EMB*HDIM]; // Wq|Wk|Wv split
__device__ __half g_woh[EMB*EMB], g_wol[EMB*EMB];                 // Wo split
__device__ __half g_qh[NBATCH*NHEAD*TSEQ*HDIM], g_ql[NBATCH*NHEAD*TSEQ*HDIM];
__device__ __half g_kh[NBATCH*NHEAD*TSEQ*HDIM], g_kl[NBATCH*NHEAD*TSEQ*HDIM];
__device__ __half g_vh[NBATCH*NHEAD*TSEQ*HDIM];
__device__ __half g_ch[NTOK*EMB];                                  // attn combined (f16 only)

// ===========================================================================
// Helpers
// ===========================================================================
__device__ __forceinline__ uint32_t smem_u32(const void* p) {
    uint32_t a;
    asm("{ .reg .u64 t; cvta.to.shared.u64 t, %1; cvt.u32.u64 %0, t; }" : "=r"(a) : "l"(p));
    return a;
}
#define CP_ASYNC16(dst, src) asm volatile("cp.async.cg.shared.global [%0], [%1], 16;" :: "r"(dst), "l"(src))
#define CP_COMMIT()          asm volatile("cp.async.commit_group;" ::: "memory")
#define CP_WAIT0()           asm volatile("cp.async.wait_group 0;" ::: "memory")
#define CP_WAIT1()           asm volatile("cp.async.wait_group 1;" ::: "memory")

__device__ __forceinline__ void mma_f16(float* d, const uint32_t* a, const uint32_t* b) {
    asm volatile("mma.sync.aligned.m16n8k16.row.col.f32.f16.f16.f32 "
        "{%0,%1,%2,%3}, {%4,%5,%6,%7}, {%8,%9}, {%0,%1,%2,%3};"
        : "+f"(d[0]), "+f"(d[1]), "+f"(d[2]), "+f"(d[3])
        : "r"(a[0]), "r"(a[1]), "r"(a[2]), "r"(a[3]), "r"(b[0]), "r"(b[1]));
}
__device__ __forceinline__ void ldsm4(uint32_t* r, uint32_t a) {
    asm volatile("ldmatrix.sync.aligned.m8n8.x4.shared.b16 {%0,%1,%2,%3}, [%4];"
        : "=r"(r[0]), "=r"(r[1]), "=r"(r[2]), "=r"(r[3]) : "r"(a));
}
__device__ __forceinline__ void ldsm4t(uint32_t* r, uint32_t a) {
    asm volatile("ldmatrix.sync.aligned.m8n8.x4.trans.shared.b16 {%0,%1,%2,%3}, [%4];"
        : "=r"(r[0]), "=r"(r[1]), "=r"(r[2]), "=r"(r[3]) : "r"(a));
}
__device__ __forceinline__ uint32_t pack_h2(float a, float b) {
    __half2 h = __floats2half2_rn(a, b);
    return *(uint32_t*)&h;
}
__device__ __forceinline__ void split_wr2(float a, float b, __half* ph, __half* pl) {
    __half ha = __float2half_rn(a), hb = __float2half_rn(b);
    __half la = __float2half_rn(a - __half2float(ha));
    __half lb = __float2half_rn(b - __half2float(hb));
    *(uint32_t*)ph = ((uint32_t)__half_as_ushort(hb) << 16) | (uint32_t)__half_as_ushort(ha);
    *(uint32_t*)pl = ((uint32_t)__half_as_ushort(lb) << 16) | (uint32_t)__half_as_ushort(la);
}
// exp2 on fma pipe (no MUFU); valid for y <= 0
__device__ __forceinline__ float exp2p(float y) {
    y = fmaxf(y, -126.f);
    float r = rintf(y);
    float f = y - r;
    float p = fmaf(f, 1.3333558146e-3f, 9.6181291076e-3f);
    p = fmaf(f, p, 5.5504108664e-2f);
    p = fmaf(f, p, 2.4022650696e-1f);
    p = fmaf(f, p, 6.9314718056e-1f);
    p = fmaf(f, p, 1.0f);
    int n = (int)r;
    return p * __int_as_float((n + 127) << 23);
}

#define KCHUNK 64
#define NCHUNK (EMB / KCHUNK)   // 16
#define QSC 0.18033688011112042f  // 0.125 * log2(e)
#define SGS 72                    // shared stride (halves)

// ---------------------------------------------------------------------------
// Kernel 0: prep — split x, Wq/Wk/Wv, Wo into hi/lo halves
// ---------------------------------------------------------------------------
#define PREP_NX2  (NTOK*EMB/2)
#define PREP_NW2  (NHEAD*EMB*HDIM/2)
#define PREP_NWO2 (EMB*EMB/2)
#define PREP_TOT  (PREP_NX2 + 3*PREP_NW2 + PREP_NWO2)

__device__ __forceinline__ void split2_store(const float* s, __half* h, __half* l, int i2) {
    float2 v = ((const float2*)s)[i2];
    __half2 hv = __floats2half2_rn(v.x, v.y);
    float2 hr = __half22float2(hv);
    __half2 lv = __floats2half2_rn(v.x - hr.x, v.y - hr.y);
    ((__half2*)h)[i2] = hv;
    ((__half2*)l)[i2] = lv;
}

__global__ __launch_bounds__(256) void prep_kernel(
    const float* __restrict__ x, const float* __restrict__ Wq,
    const float* __restrict__ Wk, const float* __restrict__ Wv,
    const float* __restrict__ Wo)
{
    int idx = blockIdx.x * 256 + threadIdx.x;
    if (idx < PREP_NX2) { split2_store(x, g_xh, g_xl, idx); return; }
    idx -= PREP_NX2;
    if (idx < PREP_NW2) { split2_store(Wq, g_wh, g_wl, idx); return; }
    idx -= PREP_NW2;
    if (idx < PREP_NW2) { split2_store(Wk, g_wh + NHEAD*EMB*HDIM, g_wl + NHEAD*EMB*HDIM, idx); return; }
    idx -= PREP_NW2;
    if (idx < PREP_NW2) { split2_store(Wv, g_wh + 2*NHEAD*EMB*HDIM, g_wl + 2*NHEAD*EMB*HDIM, idx); return; }
    idx -= PREP_NW2;
    if (idx < PREP_NWO2) split2_store(Wo, g_woh, g_wol, idx);
}

// ---------------------------------------------------------------------------
// Kernel 1: QKV projection. grid=(32,16,3), 256 thr, block 128x64, warp 32x32.
// Q,K: 3-pass; V: 2-pass (drop x_lo x W_hi). Pre-split operands.
// ---------------------------------------------------------------------------
#define QK_AL   9216
#define QK_BH   18432
#define QK_BL   23040
#define QK_BUFH 27648
#define QKV_SMEM (2*QK_BUFH*2)   // 110592 B

__device__ __forceinline__ void qkv_stage(uint32_t sbuf,
                                          const __half* wh, const __half* wl,
                                          int m0, int k0, int tid, bool need_alo) {
    #pragma unroll
    for (int j = 0; j < 4; j++) {           // A hi: 1024 cp
        int idx = j * 256 + tid;
        int r = idx >> 3, q = idx & 7;
        CP_ASYNC16(sbuf + (uint32_t)(r*SGS + q*8)*2,
                   g_xh + (size_t)(m0 + r)*EMB + k0 + q*8);
    }
    if (need_alo) {
        #pragma unroll
        for (int j = 0; j < 4; j++) {       // A lo
            int idx = j * 256 + tid;
            int r = idx >> 3, q = idx & 7;
            CP_ASYNC16(sbuf + (uint32_t)(QK_AL + r*SGS + q*8)*2,
                       g_xl + (size_t)(m0 + r)*EMB + k0 + q*8);
        }
    }
    #pragma unroll
    for (int j = 0; j < 2; j++) {           // B hi: 512 cp
        int idx = j * 256 + tid;
        int k = idx >> 3, q = idx & 7;
        CP_ASYNC16(sbuf + (uint32_t)(QK_BH + k*SGS + q*8)*2,
                   wh + (size_t)(k0 + k)*HDIM + q*8);
    }
    #pragma unroll
    for (int j = 0; j < 2; j++) {           // B lo
        int idx = j * 256 + tid;
        int k = idx >> 3, q = idx & 7;
        CP_ASYNC16(sbuf + (uint32_t)(QK_BL + k*SGS + q*8)*2,
                   wl + (size_t)(k0 + k)*HDIM + q*8);
    }
    CP_COMMIT();
}

__global__ __launch_bounds__(256, 2) void qkv_mma_kernel()
{
    extern __shared__ __align__(16) char sm[];
    const uint32_t sb = smem_u32(sm);
    const int tid = threadIdx.x;
    const int lane = tid & 31, wid = tid >> 5;
    const int gid = lane >> 2, tig = lane & 3;
    const int warp_m = wid >> 1, warp_n = wid & 1;
    const int m0 = blockIdx.x * 128, h = blockIdx.y, which = blockIdx.z;
    const bool three_pass = (which != 2);

    const __half* wh = g_wh + (size_t)(which*NHEAD + h)*EMB*HDIM;
    const __half* wl = g_wl + (size_t)(which*NHEAD + h)*EMB*HDIM;

    const int offA  = ((lane & 7) + ((lane >> 3) & 1) * 8) * SGS + (lane >> 4) * 8;
    const int offBt = ((lane & 7) + ((lane >> 3) & 1) * 8) * SGS + (lane >> 4) * 8;

    float acc[2][4][4];
    #pragma unroll
    for (int mt = 0; mt < 2; mt++)
        #pragma unroll
        for (int nt = 0; nt < 4; nt++)
            #pragma unroll
            for (int e = 0; e < 4; e++) acc[mt][nt][e] = 0.f;

    qkv_stage(sb, wh, wl, m0, 0, tid, three_pass);

    for (int ch = 0; ch < NCHUNK; ch++) {
        if (ch + 1 < NCHUNK) {
            qkv_stage(sb + ((ch + 1) & 1) * QK_BUFH * 2, wh, wl, m0, (ch + 1) * KCHUNK, tid, three_pass);
            CP_WAIT1();
        } else {
            CP_WAIT0();
        }
        __syncthreads();

        const uint32_t bb = sb + (ch & 1) * QK_BUFH * 2;
        #pragma unroll
        for (int ks = 0; ks < 4; ks++) {
            uint32_t ahf[2][4], alf[2][4];
            #pragma unroll
            for (int mt = 0; mt < 2; mt++) {
                uint32_t ao = (uint32_t)(offA + (warp_m*32 + mt*16)*SGS + ks*16) * 2;
                ldsm4(ahf[mt], bb + ao);
                if (three_pass) ldsm4(alf[mt], bb + QK_AL*2 + ao);
            }
            #pragma unroll
            for (int ntp = 0; ntp < 2; ntp++) {
                uint32_t bhf[4], blf[4];
                uint32_t bo = (uint32_t)(offBt + (ks*16)*SGS + warp_n*32 + ntp*16) * 2;
                ldsm4t(bhf, bb + QK_BH*2 + bo);
                ldsm4t(blf, bb + QK_BL*2 + bo);
                #pragma unroll
                for (int mt = 0; mt < 2; mt++) {
                    mma_f16(acc[mt][ntp*2],   ahf[mt], bhf);
                    mma_f16(acc[mt][ntp*2],   ahf[mt], blf);
                    if (three_pass) mma_f16(acc[mt][ntp*2], alf[mt], bhf);
                    mma_f16(acc[mt][ntp*2+1], ahf[mt], bhf + 2);
                    mma_f16(acc[mt][ntp*2+1], ahf[mt], blf + 2);
                    if (three_pass) mma_f16(acc[mt][ntp*2+1], alf[mt], bhf + 2);
                }
            }
        }
        __syncthreads();
    }

    // epilogue: split into hi/lo half arrays (Q pre-scaled by QSC; V hi-only)
    const float scale = (which == 0) ? QSC : 1.0f;

    #pragma unroll
    for (int mt = 0; mt < 2; mt++)
        #pragma unroll
        for (int nt = 0; nt < 4; nt++) {
            int n = warp_n * 32 + nt * 8 + 2 * tig;
            #pragma unroll
            for (int half = 0; half < 2; half++) {
                int m = m0 + warp_m * 32 + mt * 16 + gid + half * 8;
                int b = m >> 11, t = m & (TSEQ - 1);
                size_t o0 = ((size_t)((b * NHEAD + h) * TSEQ + t)) * HDIM + n;
                float v0 = acc[mt][nt][half*2]   * scale;
                float v1 = acc[mt][nt][half*2+1] * scale;
                if (which == 0)      split_wr2(v0, v1, g_qh + o0, g_ql + o0);
                else if (which == 1) split_wr2(v0, v1, g_kh + o0, g_kl + o0);
                else                 *(uint32_t*)(g_vh + o0) = pack_h2(v0, v1);
            }
        }
}

// ---------------------------------------------------------------------------
// Kernel 2: flash attention. grid=(16,16,2), 256 thr (8 warps x 16 rows).
// QK^T 3-pass; PV 1-pass (P_hi x V_hi). exp on fma pipe.
// Buffer (bytes): Kh@0 Kl@9216 Vh@18432 ; BUFB=27648; Q region @55296.
// ---------------------------------------------------------------------------
#define AS 72
#define AT_BUFB 27648
#define AT_QOFF 55296
#define ATTN_SMEM (AT_QOFF + 36864)   // 92160

__device__ __forceinline__ void attn_stage_kv(uint32_t sb,
    const __half* Kh, const __half* Kl, const __half* Vh,
    int kt, int tid)
{
    uint32_t bbuf = sb + (uint32_t)(kt & 1) * AT_BUFB;
    #pragma unroll
    for (int j = 0; j < 2; j++) {
        int idx = j * 256 + tid;           // 512 per array (64 rows x 8)
        int r = idx >> 3, q = idx & 7;
        uint32_t d = (uint32_t)(r * AS + q * 8) * 2;
        size_t s = (size_t)(kt * 64 + r) * HDIM + q * 8;
        CP_ASYNC16(bbuf + d,         Kh + s);
        CP_ASYNC16(bbuf + 9216 + d,  Kl + s);
        CP_ASYNC16(bbuf + 18432 + d, Vh + s);
    }
    CP_COMMIT();
}

__global__ __launch_bounds__(256) void attn_mma_kernel()
{
    extern __shared__ __align__(16) char sm[];
    const uint32_t sb = smem_u32(sm);
    const int tid = threadIdx.x;
    const int lane = tid & 31, wid = tid >> 5;
    const int gid = lane >> 2, tig = lane & 3;
    const int qt = blockIdx.x, h = blockIdx.y, b = blockIdx.z;
    const size_t base = (size_t)((b * NHEAD + h) * TSEQ) * HDIM;
    const __half* Qh = g_qh + base; const __half* Ql = g_ql + base;
    const __half* Kh = g_kh + base; const __half* Kl = g_kl + base;
    const __half* Vh = g_vh + base;

    const int offQ = ((lane & 7) + ((lane >> 3) & 1) * 8) * AS + (lane >> 4) * 8; // A & trans-B
    const int offK = ((lane & 7) + (lane >> 4) * 8) * AS + ((lane >> 3) & 1) * 8; // non-trans B

    // stage Q halves into Q region, first KV tile into buffer 0
    #pragma unroll
    for (int j = 0; j < 4; j++) {
        int idx = j * 256 + tid;           // 1024 per array (128 rows x 8)
        int r = idx >> 3, q = idx & 7;
        uint32_t d = (uint32_t)(r * AS + q * 8) * 2;
        size_t s = (size_t)(qt * 128 + r) * HDIM + q * 8;
        CP_ASYNC16(sb + AT_QOFF + d,         Qh + s);
        CP_ASYNC16(sb + AT_QOFF + 18432 + d, Ql + s);
    }
    CP_COMMIT();
    attn_stage_kv(sb, Kh, Kl, Vh, 0, tid);
    CP_WAIT0();
    __syncthreads();

    // extract resident Q fragments (already scaled by QSC at producer)
    uint32_t qf_h[4][4], qf_l[4][4];
    #pragma unroll
    for (int ks = 0; ks < 4; ks++) {
        uint32_t ao = (uint32_t)(offQ + (wid * 16) * AS + ks * 16) * 2;
        ldsm4(qf_h[ks], sb + AT_QOFF + ao);
        ldsm4(qf_l[ks], sb + AT_QOFF + 18432 + ao);
    }

    float o[8][4];
    #pragma unroll
    for (int nt = 0; nt < 8; nt++)
        #pragma unroll
        for (int e = 0; e < 4; e++) o[nt][e] = 0.f;
    float mr0 = -1e30f, mr1 = -1e30f, l0 = 0.f, l1 = 0.f;

    for (int kt = 0; kt < TSEQ / 64; kt++) {
        if (kt + 1 < TSEQ / 64) {
            attn_stage_kv(sb, Kh, Kl, Vh, kt + 1, tid);
            CP_WAIT1();
        } else {
            CP_WAIT0();
        }
        __syncthreads();

        const uint32_t kb = sb + (kt & 1) * AT_BUFB;

        // S = Q K^T (3-pass f16), log2 units
        float s[8][4];
        #pragma unroll
        for (int nt = 0; nt < 8; nt++)
            #pragma unroll
            for (int e = 0; e < 4; e++) s[nt][e] = 0.f;

        #pragma unroll
        for (int ks = 0; ks < 4; ks++) {
            #pragma unroll
            for (int ntp = 0; ntp < 4; ntp++) {
                uint32_t bh[4], bl[4];
                uint32_t ao = (uint32_t)(offK + (ntp * 16) * AS + ks * 16) * 2;
                ldsm4(bh, kb + ao);
                ldsm4(bl, kb + 9216 + ao);
                mma_f16(s[ntp*2],   qf_h[ks], bh);
                mma_f16(s[ntp*2],   qf_h[ks], bl);
                mma_f16(s[ntp*2],   qf_l[ks], bh);
                mma_f16(s[ntp*2+1], qf_h[ks], bh + 2);
                mma_f16(s[ntp*2+1], qf_h[ks], bl + 2);
                mma_f16(s[ntp*2+1], qf_l[ks], bh + 2);
            }
        }

        // online softmax (rows gid, gid+8)
        float tm0 = -1e30f, tm1 = -1e30f;
        #pragma unroll
        for (int nt = 0; nt < 8; nt++) {
            tm0 = fmaxf(tm0, fmaxf(s[nt][0], s[nt][1]));
            tm1 = fmaxf(tm1, fmaxf(s[nt][2], s[nt][3]));
        }
        tm0 = fmaxf(tm0, __shfl_xor_sync(0xffffffffu, tm0, 1));
        tm0 = fmaxf(tm0, __shfl_xor_sync(0xffffffffu, tm0, 2));
        tm1 = fmaxf(tm1, __shfl_xor_sync(0xffffffffu, tm1, 1));
        tm1 = fmaxf(tm1, __shfl_xor_sync(0xffffffffu, tm1, 2));
        float mn0 = fmaxf(mr0, tm0), mn1 = fmaxf(mr1, tm1);
        float al0 = exp2p(mr0 - mn0), al1 = exp2p(mr1 - mn1);
        mr0 = mn0; mr1 = mn1;

        float rs0 = 0.f, rs1 = 0.f;
        #pragma unroll
        for (int nt = 0; nt < 8; nt++) {
            s[nt][0] = exp2p(s[nt][0] - mn0);
            s[nt][1] = exp2p(s[nt][1] - mn0);
            s[nt][2] = exp2p(s[nt][2] - mn1);
            s[nt][3] = exp2p(s[nt][3] - mn1);
            rs0 += s[nt][0] + s[nt][1];
            rs1 += s[nt][2] + s[nt][3];
        }
        rs0 += __shfl_xor_sync(0xffffffffu, rs0, 1);
        rs0 += __shfl_xor_sync(0xffffffffu, rs0, 2);
        rs1 += __shfl_xor_sync(0xffffffffu, rs1, 1);
        rs1 += __shfl_xor_sync(0xffffffffu, rs1, 2);
        l0 = l0 * al0 + rs0;
        l1 = l1 * al1 + rs1;
        #pragma unroll
        for (int nt = 0; nt < 8; nt++) {
            o[nt][0] *= al0; o[nt][1] *= al0;
            o[nt][2] *= al1; o[nt][3] *= al1;
        }

        // O += P V (1-pass: P_hi x V_hi); P packed in registers
        #pragma unroll
        for (int ks = 0; ks < 4; ks++) {
            uint32_t ah[4];
            ah[0] = pack_h2(s[2*ks][0],   s[2*ks][1]);
            ah[1] = pack_h2(s[2*ks][2],   s[2*ks][3]);
            ah[2] = pack_h2(s[2*ks+1][0], s[2*ks+1][1]);
            ah[3] = pack_h2(s[2*ks+1][2], s[2*ks+1][3]);
            #pragma unroll
            for (int dtp = 0; dtp < 4; dtp++) {
                uint32_t bh[4];
                uint32_t ao = (uint32_t)(offQ + (ks * 16) * AS + dtp * 16) * 2;
                ldsm4t(bh, kb + 18432 + ao);
                mma_f16(o[dtp*2],   ah, bh);
                mma_f16(o[dtp*2+1], ah, bh + 2);
            }
        }
        __syncthreads();
    }

    // epilogue: normalize, write combined C as f16 (hi only)
    float inv0 = 1.f / l0, inv1 = 1.f / l1;
    int t0 = qt * 128 + wid * 16 + gid;
    #pragma unroll
    for (int nt = 0; nt < 8; nt++) {
        int col = h * HDIM + nt * 8 + 2 * tig;
        size_t o0 = (size_t)(b * TSEQ + t0) * EMB + col;
        size_t o1 = (size_t)(b * TSEQ + t0 + 8) * EMB + col;
        *(uint32_t*)(g_ch + o0) = pack_h2(o[nt][0] * inv0, o[nt][1] * inv0);
        *(uint32_t*)(g_ch + o1) = pack_h2(o[nt][2] * inv1, o[nt][3] * inv1);
    }
}

// ---------------------------------------------------------------------------
// Kernel 3: out = x + C @ Wo^T. grid=(32,8), 256 thr, block 128x128.
// Warp grid 2m x 4n, warp tile 64x32. 2-pass (C_hi x Wo_hi + C_hi x Wo_lo).
// Buffer (halves): A@0 (128x72), Bh@9216, Bl@18432; BUFH=27648.
// ---------------------------------------------------------------------------
#define OP_BH   9216
#define OP_BL   18432
#define OP_BUFH 27648
#define OP_SMEM (2*OP_BUFH*2)    // 110592

__device__ __forceinline__ void op_stage(uint32_t sbuf, int m0, int n0, int k0, int tid) {
    #pragma unroll
    for (int j = 0; j < 4; j++) {           // A: 1024 cp (128 rows x 8)
        int idx = j * 256 + tid;
        int r = idx >> 3, q = idx & 7;
        CP_ASYNC16(sbuf + (uint32_t)(r*SGS + q*8)*2,
                   g_ch + (size_t)(m0 + r)*EMB + k0 + q*8);
    }
    #pragma unroll
    for (int j = 0; j < 4; j++) {           // B hi: 1024 cp (128 n-rows x 8)
        int idx = j * 256 + tid;
        int r = idx >> 3, q = idx & 7;
        CP_ASYNC16(sbuf + (uint32_t)(OP_BH + r*SGS + q*8)*2,
                   g_woh + (size_t)(n0 + r)*EMB + k0 + q*8);
    }
    #pragma unroll
    for (int j = 0; j < 4; j++) {           // B lo
        int idx = j * 256 + tid;
        int r = idx >> 3, q = idx & 7;
        CP_ASYNC16(sbuf + (uint32_t)(OP_BL + r*SGS + q*8)*2,
                   g_wol + (size_t)(n0 + r)*EMB + k0 + q*8);
    }
    CP_COMMIT();
}

__global__ __launch_bounds__(256, 2) void outproj_mma_kernel(
    const float* __restrict__ x, float* __restrict__ out)
{
    extern __shared__ __align__(16) char sm[];
    const uint32_t sb = smem_u32(sm);
    const int tid = threadIdx.x;
    const int lane = tid & 31, wid = tid >> 5;
    const int gid = lane >> 2, tig = lane & 3;
    const int warp_m = wid >> 2;        // 0..1 (64 rows each)
    const int warp_n = wid & 3;         // 0..3 (32 cols each)
    const int m0 = blockIdx.x * 128, n0 = blockIdx.y * 128;

    const int offA = ((lane & 7) + ((lane >> 3) & 1) * 8) * SGS + (lane >> 4) * 8;
    const int offB = ((lane & 7) + (lane >> 4) * 8) * SGS + ((lane >> 3) & 1) * 8;

    float acc[4][4][4];                 // [mt 0..3][nt 0..3][4]
    #pragma unroll
    for (int mt = 0; mt < 4; mt++)
        #pragma unroll
        for (int nt = 0; nt < 4; nt++)
            #pragma unroll
            for (int e = 0; e < 4; e++) acc[mt][nt][e] = 0.f;

    op_stage(sb, m0, n0, 0, tid);

    for (int ch = 0; ch < NCHUNK; ch++) {
        if (ch + 1 < NCHUNK) {
            op_stage(sb + ((ch + 1) & 1) * OP_BUFH * 2, m0, n0, (ch + 1) * KCHUNK, tid);
            CP_WAIT1();
        } else {
            CP_WAIT0();
        }
        __syncthreads();

        const uint32_t bb = sb + (ch & 1) * OP_BUFH * 2;
        #pragma unroll
        for (int ks = 0; ks < 4; ks++) {
            uint32_t af[4][4];
            #pragma unroll
            for (int mt = 0; mt < 4; mt++) {
                uint32_t ao = (uint32_t)(offA + (warp_m*64 + mt*16)*SGS + ks*16) * 2;
                ldsm4(af[mt], bb + ao);
            }
            #pragma unroll
            for (int ntp = 0; ntp < 2; ntp++) {
                uint32_t bhf[4], blf[4];
                uint32_t bo = (uint32_t)(offB + (warp_n*32 + ntp*16)*SGS + ks*16) * 2;
                ldsm4(bhf, bb + OP_BH*2 + bo);
                ldsm4(blf, bb + OP_BL*2 + bo);
                #pragma unroll
                for (int mt = 0; mt < 4; mt++) {
                    mma_f16(acc[mt][ntp*2],   af[mt], bhf);
                    mma_f16(acc[mt][ntp*2],   af[mt], blf);
                    mma_f16(acc[mt][ntp*2+1], af[mt], bhf + 2);
                    mma_f16(acc[mt][ntp*2+1], af[mt], blf + 2);
                }
            }
        }
        __syncthreads();
    }

    #pragma unroll
    for (int mt = 0; mt < 4; mt++)
        #pragma unroll
        for (int nt = 0; nt < 4; nt++) {
            int n = n0 + warp_n * 32 + nt * 8 + tig * 2;
            int m = m0 + warp_m * 64 + mt * 16 + gid;
            {
                size_t off = (size_t)m * EMB + n;
                float2 xv = *(const float2*)&x[off];
                *(float2*)&out[off] = make_float2(acc[mt][nt][0] + xv.x, acc[mt][nt][1] + xv.y);
            }
            {
                size_t off = (size_t)(m + 8) * EMB + n;
                float2 xv = *(const float2*)&x[off];
                *(float2*)&out[off] = make_float2(acc[mt][nt][2] + xv.x, acc[mt][nt][3] + xv.y);
            }
        }
}

extern "C" void kernel_launch(void* const* d_in, const int* in_sizes, int n_in,
                              void* d_out, int out_size)
{
    const float* x  = (const float*)d_in[0];
    const float* Wq = (const float*)d_in[1];
    const float* Wk = (const float*)d_in[2];
    const float* Wv = (const float*)d_in[3];
    const float* Wo = (const float*)d_in[4];
    float* out = (float*)d_out;

    cudaFuncSetAttribute(qkv_mma_kernel, cudaFuncAttributeMaxDynamicSharedMemorySize, QKV_SMEM);
    cudaFuncSetAttribute(attn_mma_kernel, cudaFuncAttributeMaxDynamicSharedMemorySize, ATTN_SMEM);
    cudaFuncSetAttribute(outproj_mma_kernel, cudaFuncAttributeMaxDynamicSharedMemorySize, OP_SMEM);

    prep_kernel<<<PREP_TOT / 256, 256>>>(x, Wq, Wk, Wv, Wo);

    dim3 g1(NTOK / 128, NHEAD, 3);
    qkv_mma_kernel<<<g1, 256, QKV_SMEM>>>();

    dim3 g2(TSEQ / 128, NHEAD, NBATCH);
    attn_mma_kernel<<<g2, 256, ATTN_SMEM>>>();

    dim3 g3(NTOK / 128, EMB / 128);
    outproj_mma_kernel<<<g3, 256, OP_SMEM>>>(x, out);
}

// round 15
// speedup vs baseline: 3.3493x; 1.0074x over previous
#include <cuda_runtime.h>
#include <cuda_fp16.h>
#include <math.h>
#include <stdint.h>

#define NBATCH 2
#define TSEQ   2048
#define EMB    1024
#define NHEAD  16
#define HDIM   64
#define NTOK   (NBATCH*TSEQ)   // 4096

// ---------------------------------------------------------------------------
// Persistent hi/lo half scratch (allocation-free)
// ---------------------------------------------------------------------------
__device__ __half g_xh[NTOK*EMB],  g_xl[NTOK*EMB];                 // x split
__device__ __half g_wh[3*NHEAD*EMB*HDIM], g_wl[3*NHEAD*EMB*HDIM]; // Wq|Wk|Wv split
__device__ __half g_woh[EMB*EMB], g_wol[EMB*EMB];                 // Wo split
__device__ __half g_qh[NBATCH*NHEAD*TSEQ*HDIM], g_ql[NBATCH*NHEAD*TSEQ*HDIM];
__device__ __half g_kh[NBATCH*NHEAD*TSEQ*HDIM], g_kl[NBATCH*NHEAD*TSEQ*HDIM];
__device__ __half g_vh[NBATCH*NHEAD*TSEQ*HDIM];
__device__ __half g_ch[NTOK*EMB];                                  // attn combined (f16 only)

// ===========================================================================
// Helpers
// ===========================================================================
__device__ __forceinline__ uint32_t smem_u32(const void* p) {
    uint32_t a;
    asm("{ .reg .u64 t; cvta.to.shared.u64 t, %1; cvt.u32.u64 %0, t; }" : "=r"(a) : "l"(p));
    return a;
}
#define CP_ASYNC16(dst, src) asm volatile("cp.async.cg.shared.global [%0], [%1], 16;" :: "r"(dst), "l"(src))
#define CP_COMMIT()          asm volatile("cp.async.commit_group;" ::: "memory")
#define CP_WAIT0()           asm volatile("cp.async.wait_group 0;" ::: "memory")
#define CP_WAIT1()           asm volatile("cp.async.wait_group 1;" ::: "memory")

__device__ __forceinline__ void mma_f16(float* d, const uint32_t* a, const uint32_t* b) {
    asm volatile("mma.sync.aligned.m16n8k16.row.col.f32.f16.f16.f32 "
        "{%0,%1,%2,%3}, {%4,%5,%6,%7}, {%8,%9}, {%0,%1,%2,%3};"
        : "+f"(d[0]), "+f"(d[1]), "+f"(d[2]), "+f"(d[3])
        : "r"(a[0]), "r"(a[1]), "r"(a[2]), "r"(a[3]), "r"(b[0]), "r"(b[1]));
}
__device__ __forceinline__ void ldsm4(uint32_t* r, uint32_t a) {
    asm volatile("ldmatrix.sync.aligned.m8n8.x4.shared.b16 {%0,%1,%2,%3}, [%4];"
        : "=r"(r[0]), "=r"(r[1]), "=r"(r[2]), "=r"(r[3]) : "r"(a));
}
__device__ __forceinline__ void ldsm4t(uint32_t* r, uint32_t a) {
    asm volatile("ldmatrix.sync.aligned.m8n8.x4.trans.shared.b16 {%0,%1,%2,%3}, [%4];"
        : "=r"(r[0]), "=r"(r[1]), "=r"(r[2]), "=r"(r[3]) : "r"(a));
}
__device__ __forceinline__ uint32_t pack_h2(float a, float b) {
    __half2 h = __floats2half2_rn(a, b);
    return *(uint32_t*)&h;
}
__device__ __forceinline__ void split_wr2(float a, float b, __half* ph, __half* pl) {
    __half ha = __float2half_rn(a), hb = __float2half_rn(b);
    __half la = __float2half_rn(a - __half2float(ha));
    __half lb = __float2half_rn(b - __half2float(hb));
    *(uint32_t*)ph = ((uint32_t)__half_as_ushort(hb) << 16) | (uint32_t)__half_as_ushort(ha);
    *(uint32_t*)pl = ((uint32_t)__half_as_ushort(lb) << 16) | (uint32_t)__half_as_ushort(la);
}
// exp2 on fma pipe (no MUFU); valid for y <= 0
__device__ __forceinline__ float exp2p(float y) {
    y = fmaxf(y, -126.f);
    float r = rintf(y);
    float f = y - r;
    float p = fmaf(f, 1.3333558146e-3f, 9.6181291076e-3f);
    p = fmaf(f, p, 5.5504108664e-2f);
    p = fmaf(f, p, 2.4022650696e-1f);
    p = fmaf(f, p, 6.9314718056e-1f);
    p = fmaf(f, p, 1.0f);
    int n = (int)r;
    return p * __int_as_float((n + 127) << 23);
}

#define QSC 0.18033688011112042f  // 0.125 * log2(e)
#define SGS 72                    // shared stride (halves) for 64-wide k tiles

// ---------------------------------------------------------------------------
// Kernel 0: prep — split x, Wq/Wk/Wv, Wo into hi/lo halves
// ---------------------------------------------------------------------------
#define PREP_NX2  (NTOK*EMB/2)
#define PREP_NW2  (NHEAD*EMB*HDIM/2)
#define PREP_NWO2 (EMB*EMB/2)
#define PREP_TOT  (PREP_NX2 + 3*PREP_NW2 + PREP_NWO2)

__device__ __forceinline__ void split2_store(const float* s, __half* h, __half* l, int i2) {
    float2 v = ((const float2*)s)[i2];
    __half2 hv = __floats2half2_rn(v.x, v.y);
    float2 hr = __half22float2(hv);
    __half2 lv = __floats2half2_rn(v.x - hr.x, v.y - hr.y);
    ((__half2*)h)[i2] = hv;
    ((__half2*)l)[i2] = lv;
}

__global__ __launch_bounds__(256) void prep_kernel(
    const float* __restrict__ x, const float* __restrict__ Wq,
    const float* __restrict__ Wk, const float* __restrict__ Wv,
    const float* __restrict__ Wo)
{
    int idx = blockIdx.x * 256 + threadIdx.x;
    if (idx < PREP_NX2) { split2_store(x, g_xh, g_xl, idx); return; }
    idx -= PREP_NX2;
    if (idx < PREP_NW2) { split2_store(Wq, g_wh, g_wl, idx); return; }
    idx -= PREP_NW2;
    if (idx < PREP_NW2) { split2_store(Wk, g_wh + NHEAD*EMB*HDIM, g_wl + NHEAD*EMB*HDIM, idx); return; }
    idx -= PREP_NW2;
    if (idx < PREP_NW2) { split2_store(Wv, g_wh + 2*NHEAD*EMB*HDIM, g_wl + 2*NHEAD*EMB*HDIM, idx); return; }
    idx -= PREP_NW2;
    if (idx < PREP_NWO2) split2_store(Wo, g_woh, g_wol, idx);
}

// ---------------------------------------------------------------------------
// Kernel 1: FUSED QKV projection as [4096 x 1024] @ [1024 x 3072].
// grid=(32, 24), 256 thr, block 128x128, warp grid 2m x 4n (warp 64x32).
// N columns: 0-1023 Q (3-pass), 1024-2047 K (3-pass), 2048-3071 V (2-pass).
// KCHUNK=32, double buffer 2x37888 B -> 2 CTAs/SM.
// A stride 40 halves; B (k-major rows of 128 n) stride 136 halves.
// ---------------------------------------------------------------------------
#define FQ_KC   32
#define FQ_NCH  (EMB / FQ_KC)    // 32
#define BA_AL   10240            // byte offsets within buffer
#define BA_BH   20480
#define BA_BL   29184
#define FQ_BUFB 37888
#define QKV_SMEM (2 * FQ_BUFB)   // 75776 B

__device__ __forceinline__ void fqkv_stage(uint32_t sbuf,
    const __half* wbh, const __half* wbl,  // base at (which*16+h0)*EMB*HDIM
    int m0, int k0, int tid, bool need_alo)
{
    #pragma unroll
    for (int j = 0; j < 2; j++) {           // A hi: 512 cp (128 rows x 4)
        int idx = j * 256 + tid;
        int r = idx >> 2, q = idx & 3;
        CP_ASYNC16(sbuf + (uint32_t)(r*40 + q*8)*2,
                   g_xh + (size_t)(m0 + r)*EMB + k0 + q*8);
    }
    if (need_alo) {
        #pragma unroll
        for (int j = 0; j < 2; j++) {       // A lo
            int idx = j * 256 + tid;
            int r = idx >> 2, q = idx & 3;
            CP_ASYNC16(sbuf + BA_AL + (uint32_t)(r*40 + q*8)*2,
                       g_xl + (size_t)(m0 + r)*EMB + k0 + q*8);
        }
    }
    // B: 32 k-rows x 128 n (spanning 2 heads). 512 cp per array.
    #pragma unroll
    for (int j = 0; j < 2; j++) {
        int idx = j * 256 + tid;
        int k = idx >> 4, c = (idx & 15) * 8;          // c: 0..120 step 8
        size_t src = (size_t)(c >> 6) * (EMB*HDIM) + (size_t)(k0 + k)*HDIM + (c & 63);
        CP_ASYNC16(sbuf + BA_BH + (uint32_t)(k*136 + c)*2, wbh + src);
        CP_ASYNC16(sbuf + BA_BL + (uint32_t)(k*136 + c)*2, wbl + src);
    }
    CP_COMMIT();
}

__global__ __launch_bounds__(256, 2) void qkv_mma_kernel()
{
    extern __shared__ __align__(16) char sm[];
    const uint32_t sb = smem_u32(sm);
    const int tid = threadIdx.x;
    const int lane = tid & 31, wid = tid >> 5;
    const int gid = lane >> 2, tig = lane & 3;
    const int warp_m = wid >> 2;       // 0..1 (64 rows)
    const int warp_n = wid & 3;        // 0..3 (32 cols)
    const int m0 = blockIdx.x * 128;
    const int n0 = blockIdx.y * 128;
    const int which = n0 >> 10;
    const bool three_pass = (which != 2);

    const __half* wbh = g_wh + (size_t)(n0 >> 6) * (EMB*HDIM);
    const __half* wbl = g_wl + (size_t)(n0 >> 6) * (EMB*HDIM);

    const int offA  = ((lane & 7) + ((lane >> 3) & 1) * 8) * 40  + (lane >> 4) * 8;
    const int offBt = ((lane & 7) + ((lane >> 3) & 1) * 8) * 136 + (lane >> 4) * 8;

    float acc[4][4][4];
    #pragma unroll
    for (int mt = 0; mt < 4; mt++)
        #pragma unroll
        for (int nt = 0; nt < 4; nt++)
            #pragma unroll
            for (int e = 0; e < 4; e++) acc[mt][nt][e] = 0.f;

    fqkv_stage(sb, wbh, wbl, m0, 0, tid, three_pass);

    for (int ch = 0; ch < FQ_NCH; ch++) {
        if (ch + 1 < FQ_NCH) {
            fqkv_stage(sb + ((ch + 1) & 1) * FQ_BUFB, wbh, wbl, m0, (ch + 1) * FQ_KC, tid, three_pass);
            CP_WAIT1();
        } else {
            CP_WAIT0();
        }
        __syncthreads();

        const uint32_t bb = sb + (ch & 1) * FQ_BUFB;
        #pragma unroll
        for (int ks = 0; ks < 2; ks++) {
            uint32_t ahf[4][4], alf[4][4];
            #pragma unroll
            for (int mt = 0; mt < 4; mt++) {
                uint32_t ao = (uint32_t)(offA + (warp_m*64 + mt*16)*40 + ks*16) * 2;
                ldsm4(ahf[mt], bb + ao);
                if (three_pass) ldsm4(alf[mt], bb + BA_AL + ao);
            }
            #pragma unroll
            for (int ntp = 0; ntp < 2; ntp++) {
                uint32_t bhf[4], blf[4];
                uint32_t bo = (uint32_t)(offBt + (ks*16)*136 + warp_n*32 + ntp*16) * 2;
                ldsm4t(bhf, bb + BA_BH + bo);
                ldsm4t(blf, bb + BA_BL + bo);
                #pragma unroll
                for (int mt = 0; mt < 4; mt++) {
                    mma_f16(acc[mt][ntp*2],   ahf[mt], bhf);
                    mma_f16(acc[mt][ntp*2],   ahf[mt], blf);
                    if (three_pass) mma_f16(acc[mt][ntp*2], alf[mt], bhf);
                    mma_f16(acc[mt][ntp*2+1], ahf[mt], bhf + 2);
                    mma_f16(acc[mt][ntp*2+1], ahf[mt], blf + 2);
                    if (three_pass) mma_f16(acc[mt][ntp*2+1], alf[mt], bhf + 2);
                }
            }
        }
        __syncthreads();
    }

    // epilogue: decode (which, h, d) from global column; Q scaled by QSC
    const float scale = (which == 0) ? QSC : 1.0f;
    #pragma unroll
    for (int mt = 0; mt < 4; mt++)
        #pragma unroll
        for (int nt = 0; nt < 4; nt++) {
            int ng = n0 + warp_n * 32 + nt * 8 + 2 * tig;
            int hh = (ng >> 6) & 15, d = ng & 63;
            #pragma unroll
            for (int half = 0; half < 2; half++) {
                int m = m0 + warp_m * 64 + mt * 16 + gid + half * 8;
                int b = m >> 11, t = m & (TSEQ - 1);
                size_t o0 = ((size_t)((b * NHEAD + hh) * TSEQ + t)) * HDIM + d;
                float v0 = acc[mt][nt][half*2]   * scale;
                float v1 = acc[mt][nt][half*2+1] * scale;
                if (which == 0)      split_wr2(v0, v1, g_qh + o0, g_ql + o0);
                else if (which == 1) split_wr2(v0, v1, g_kh + o0, g_kl + o0);
                else                 *(uint32_t*)(g_vh + o0) = pack_h2(v0, v1);
            }
        }
}

// ---------------------------------------------------------------------------
// Kernel 2: flash attention. grid=(16,16,2), 256 thr (8 warps x 16 rows).
// QK^T 3-pass; PV 1-pass (P_hi x V_hi). exp on fma pipe.
// Buffer (bytes): Kh@0 Kl@9216 Vh@18432 ; BUFB=27648; Q region @55296.
// ---------------------------------------------------------------------------
#define AS 72
#define AT_BUFB 27648
#define AT_QOFF 55296
#define ATTN_SMEM (AT_QOFF + 36864)   // 92160

__device__ __forceinline__ void attn_stage_kv(uint32_t sb,
    const __half* Kh, const __half* Kl, const __half* Vh,
    int kt, int tid)
{
    uint32_t bbuf = sb + (uint32_t)(kt & 1) * AT_BUFB;
    #pragma unroll
    for (int j = 0; j < 2; j++) {
        int idx = j * 256 + tid;           // 512 per array (64 rows x 8)
        int r = idx >> 3, q = idx & 7;
        uint32_t d = (uint32_t)(r * AS + q * 8) * 2;
        size_t s = (size_t)(kt * 64 + r) * HDIM + q * 8;
        CP_ASYNC16(bbuf + d,         Kh + s);
        CP_ASYNC16(bbuf + 9216 + d,  Kl + s);
        CP_ASYNC16(bbuf + 18432 + d, Vh + s);
    }
    CP_COMMIT();
}

__global__ __launch_bounds__(256) void attn_mma_kernel()
{
    extern __shared__ __align__(16) char sm[];
    const uint32_t sb = smem_u32(sm);
    const int tid = threadIdx.x;
    const int lane = tid & 31, wid = tid >> 5;
    const int gid = lane >> 2, tig = lane & 3;
    const int qt = blockIdx.x, h = blockIdx.y, b = blockIdx.z;
    const size_t base = (size_t)((b * NHEAD + h) * TSEQ) * HDIM;
    const __half* Qh = g_qh + base; const __half* Ql = g_ql + base;
    const __half* Kh = g_kh + base; const __half* Kl = g_kl + base;
    const __half* Vh = g_vh + base;

    const int offQ = ((lane & 7) + ((lane >> 3) & 1) * 8) * AS + (lane >> 4) * 8; // A & trans-B
    const int offK = ((lane & 7) + (lane >> 4) * 8) * AS + ((lane >> 3) & 1) * 8; // non-trans B

    // stage Q halves into Q region, first KV tile into buffer 0
    #pragma unroll
    for (int j = 0; j < 4; j++) {
        int idx = j * 256 + tid;           // 1024 per array (128 rows x 8)
        int r = idx >> 3, q = idx & 7;
        uint32_t d = (uint32_t)(r * AS + q * 8) * 2;
        size_t s = (size_t)(qt * 128 + r) * HDIM + q * 8;
        CP_ASYNC16(sb + AT_QOFF + d,         Qh + s);
        CP_ASYNC16(sb + AT_QOFF + 18432 + d, Ql + s);
    }
    CP_COMMIT();
    attn_stage_kv(sb, Kh, Kl, Vh, 0, tid);
    CP_WAIT0();
    __syncthreads();

    // extract resident Q fragments (already scaled by QSC at producer)
    uint32_t qf_h[4][4], qf_l[4][4];
    #pragma unroll
    for (int ks = 0; ks < 4; ks++) {
        uint32_t ao = (uint32_t)(offQ + (wid * 16) * AS + ks * 16) * 2;
        ldsm4(qf_h[ks], sb + AT_QOFF + ao);
        ldsm4(qf_l[ks], sb + AT_QOFF + 18432 + ao);
    }

    float o[8][4];
    #pragma unroll
    for (int nt = 0; nt < 8; nt++)
        #pragma unroll
        for (int e = 0; e < 4; e++) o[nt][e] = 0.f;
    float mr0 = -1e30f, mr1 = -1e30f, l0 = 0.f, l1 = 0.f;

    for (int kt = 0; kt < TSEQ / 64; kt++) {
        if (kt + 1 < TSEQ / 64) {
            attn_stage_kv(sb, Kh, Kl, Vh, kt + 1, tid);
            CP_WAIT1();
        } else {
            CP_WAIT0();
        }
        __syncthreads();

        const uint32_t kb = sb + (kt & 1) * AT_BUFB;

        // S = Q K^T (3-pass f16), log2 units
        float s[8][4];
        #pragma unroll
        for (int nt = 0; nt < 8; nt++)
            #pragma unroll
            for (int e = 0; e < 4; e++) s[nt][e] = 0.f;

        #pragma unroll
        for (int ks = 0; ks < 4; ks++) {
            #pragma unroll
            for (int ntp = 0; ntp < 4; ntp++) {
                uint32_t bh[4], bl[4];
                uint32_t ao = (uint32_t)(offK + (ntp * 16) * AS + ks * 16) * 2;
                ldsm4(bh, kb + ao);
                ldsm4(bl, kb + 9216 + ao);
                mma_f16(s[ntp*2],   qf_h[ks], bh);
                mma_f16(s[ntp*2],   qf_h[ks], bl);
                mma_f16(s[ntp*2],   qf_l[ks], bh);
                mma_f16(s[ntp*2+1], qf_h[ks], bh + 2);
                mma_f16(s[ntp*2+1], qf_h[ks], bl + 2);
                mma_f16(s[ntp*2+1], qf_l[ks], bh + 2);
            }
        }

        // online softmax (rows gid, gid+8)
        float tm0 = -1e30f, tm1 = -1e30f;
        #pragma unroll
        for (int nt = 0; nt < 8; nt++) {
            tm0 = fmaxf(tm0, fmaxf(s[nt][0], s[nt][1]));
            tm1 = fmaxf(tm1, fmaxf(s[nt][2], s[nt][3]));
        }
        tm0 = fmaxf(tm0, __shfl_xor_sync(0xffffffffu, tm0, 1));
        tm0 = fmaxf(tm0, __shfl_xor_sync(0xffffffffu, tm0, 2));
        tm1 = fmaxf(tm1, __shfl_xor_sync(0xffffffffu, tm1, 1));
        tm1 = fmaxf(tm1, __shfl_xor_sync(0xffffffffu, tm1, 2));
        float mn0 = fmaxf(mr0, tm0), mn1 = fmaxf(mr1, tm1);
        float al0 = exp2p(mr0 - mn0), al1 = exp2p(mr1 - mn1);
        mr0 = mn0; mr1 = mn1;

        float rs0 = 0.f, rs1 = 0.f;
        #pragma unroll
        for (int nt = 0; nt < 8; nt++) {
            s[nt][0] = exp2p(s[nt][0] - mn0);
            s[nt][1] = exp2p(s[nt][1] - mn0);
            s[nt][2] = exp2p(s[nt][2] - mn1);
            s[nt][3] = exp2p(s[nt][3] - mn1);
            rs0 += s[nt][0] + s[nt][1];
            rs1 += s[nt][2] + s[nt][3];
        }
        rs0 += __shfl_xor_sync(0xffffffffu, rs0, 1);
        rs0 += __shfl_xor_sync(0xffffffffu, rs0, 2);
        rs1 += __shfl_xor_sync(0xffffffffu, rs1, 1);
        rs1 += __shfl_xor_sync(0xffffffffu, rs1, 2);
        l0 = l0 * al0 + rs0;
        l1 = l1 * al1 + rs1;
        #pragma unroll
        for (int nt = 0; nt < 8; nt++) {
            o[nt][0] *= al0; o[nt][1] *= al0;
            o[nt][2] *= al1; o[nt][3] *= al1;
        }

        // O += P V (1-pass: P_hi x V_hi); P packed in registers
        #pragma unroll
        for (int ks = 0; ks < 4; ks++) {
            uint32_t ah[4];
            ah[0] = pack_h2(s[2*ks][0],   s[2*ks][1]);
            ah[1] = pack_h2(s[2*ks][2],   s[2*ks][3]);
            ah[2] = pack_h2(s[2*ks+1][0], s[2*ks+1][1]);
            ah[3] = pack_h2(s[2*ks+1][2], s[2*ks+1][3]);
            #pragma unroll
            for (int dtp = 0; dtp < 4; dtp++) {
                uint32_t bh[4];
                uint32_t ao = (uint32_t)(offQ + (ks * 16) * AS + dtp * 16) * 2;
                ldsm4t(bh, kb + 18432 + ao);
                mma_f16(o[dtp*2],   ah, bh);
                mma_f16(o[dtp*2+1], ah, bh + 2);
            }
        }
        __syncthreads();
    }

    // epilogue: normalize, write combined C as f16 (hi only)
    float inv0 = 1.f / l0, inv1 = 1.f / l1;
    int t0 = qt * 128 + wid * 16 + gid;
    #pragma unroll
    for (int nt = 0; nt < 8; nt++) {
        int col = h * HDIM + nt * 8 + 2 * tig;
        size_t o0 = (size_t)(b * TSEQ + t0) * EMB + col;
        size_t o1 = (size_t)(b * TSEQ + t0 + 8) * EMB + col;
        *(uint32_t*)(g_ch + o0) = pack_h2(o[nt][0] * inv0, o[nt][1] * inv0);
        *(uint32_t*)(g_ch + o1) = pack_h2(o[nt][2] * inv1, o[nt][3] * inv1);
    }
}

// ---------------------------------------------------------------------------
// Kernel 3: out = x + C @ Wo^T. grid=(32,8), 256 thr, block 128x128.
// Warp grid 2m x 4n, warp tile 64x32. 2-pass (C_hi x Wo_hi + C_hi x Wo_lo).
// Buffer (halves): A@0 (128x72), Bh@9216, Bl@18432; BUFH=27648.
// ---------------------------------------------------------------------------
#define OP_KC   64
#define OP_NCH  (EMB / OP_KC)    // 16
#define OP_BH   9216
#define OP_BL   18432
#define OP_BUFH 27648
#define OP_SMEM (2*OP_BUFH*2)    // 110592

__device__ __forceinline__ void op_stage(uint32_t sbuf, int m0, int n0, int k0, int tid) {
    #pragma unroll
    for (int j = 0; j < 4; j++) {           // A: 1024 cp (128 rows x 8)
        int idx = j * 256 + tid;
        int r = idx >> 3, q = idx & 7;
        CP_ASYNC16(sbuf + (uint32_t)(r*SGS + q*8)*2,
                   g_ch + (size_t)(m0 + r)*EMB + k0 + q*8);
    }
    #pragma unroll
    for (int j = 0; j < 4; j++) {           // B hi: 1024 cp (128 n-rows x 8)
        int idx = j * 256 + tid;
        int r = idx >> 3, q = idx & 7;
        CP_ASYNC16(sbuf + (uint32_t)(OP_BH + r*SGS + q*8)*2,
                   g_woh + (size_t)(n0 + r)*EMB + k0 + q*8);
    }
    #pragma unroll
    for (int j = 0; j < 4; j++) {           // B lo
        int idx = j * 256 + tid;
        int r = idx >> 3, q = idx & 7;
        CP_ASYNC16(sbuf + (uint32_t)(OP_BL + r*SGS + q*8)*2,
                   g_wol + (size_t)(n0 + r)*EMB + k0 + q*8);
    }
    CP_COMMIT();
}

__global__ __launch_bounds__(256, 2) void outproj_mma_kernel(
    const float* __restrict__ x, float* __restrict__ out)
{
    extern __shared__ __align__(16) char sm[];
    const uint32_t sb = smem_u32(sm);
    const int tid = threadIdx.x;
    const int lane = tid & 31, wid = tid >> 5;
    const int gid = lane >> 2, tig = lane & 3;
    const int warp_m = wid >> 2;        // 0..1 (64 rows each)
    const int warp_n = wid & 3;         // 0..3 (32 cols each)
    const int m0 = blockIdx.x * 128, n0 = blockIdx.y * 128;

    const int offA = ((lane & 7) + ((lane >> 3) & 1) * 8) * SGS + (lane >> 4) * 8;
    const int offB = ((lane & 7) + (lane >> 4) * 8) * SGS + ((lane >> 3) & 1) * 8;

    float acc[4][4][4];
    #pragma unroll
    for (int mt = 0; mt < 4; mt++)
        #pragma unroll
        for (int nt = 0; nt < 4; nt++)
            #pragma unroll
            for (int e = 0; e < 4; e++) acc[mt][nt][e] = 0.f;

    op_stage(sb, m0, n0, 0, tid);

    for (int ch = 0; ch < OP_NCH; ch++) {
        if (ch + 1 < OP_NCH) {
            op_stage(sb + ((ch + 1) & 1) * OP_BUFH * 2, m0, n0, (ch + 1) * OP_KC, tid);
            CP_WAIT1();
        } else {
            CP_WAIT0();
        }
        __syncthreads();

        const uint32_t bb = sb + (ch & 1) * OP_BUFH * 2;
        #pragma unroll
        for (int ks = 0; ks < 4; ks++) {
            uint32_t af[4][4];
            #pragma unroll
            for (int mt = 0; mt < 4; mt++) {
                uint32_t ao = (uint32_t)(offA + (warp_m*64 + mt*16)*SGS + ks*16) * 2;
                ldsm4(af[mt], bb + ao);
            }
            #pragma unroll
            for (int ntp = 0; ntp < 2; ntp++) {
                uint32_t bhf[4], blf[4];
                uint32_t bo = (uint32_t)(offB + (warp_n*32 + ntp*16)*SGS + ks*16) * 2;
                ldsm4(bhf, bb + OP_BH*2 + bo);
                ldsm4(blf, bb + OP_BL*2 + bo);
                #pragma unroll
                for (int mt = 0; mt < 4; mt++) {
                    mma_f16(acc[mt][ntp*2],   af[mt], bhf);
                    mma_f16(acc[mt][ntp*2],   af[mt], blf);
                    mma_f16(acc[mt][ntp*2+1], af[mt], bhf + 2);
                    mma_f16(acc[mt][ntp*2+1], af[mt], blf + 2);
                }
            }
        }
        __syncthreads();
    }

    #pragma unroll
    for (int mt = 0; mt < 4; mt++)
        #pragma unroll
        for (int nt = 0; nt < 4; nt++) {
            int n = n0 + warp_n * 32 + nt * 8 + tig * 2;
            int m = m0 + warp_m * 64 + mt * 16 + gid;
            {
                size_t off = (size_t)m * EMB + n;
                float2 xv = *(const float2*)&x[off];
                *(float2*)&out[off] = make_float2(acc[mt][nt][0] + xv.x, acc[mt][nt][1] + xv.y);
            }
            {
                size_t off = (size_t)(m + 8) * EMB + n;
                float2 xv = *(const float2*)&x[off];
                *(float2*)&out[off] = make_float2(acc[mt][nt][2] + xv.x, acc[mt][nt][3] + xv.y);
            }
        }
}

extern "C" void kernel_launch(void* const* d_in, const int* in_sizes, int n_in,
                              void* d_out, int out_size)
{
    const float* x  = (const float*)d_in[0];
    const float* Wq = (const float*)d_in[1];
    const float* Wk = (const float*)d_in[2];
    const float* Wv = (const float*)d_in[3];
    const float* Wo = (const float*)d_in[4];
    float* out = (float*)d_out;

    cudaFuncSetAttribute(qkv_mma_kernel, cudaFuncAttributeMaxDynamicSharedMemorySize, QKV_SMEM);
    cudaFuncSetAttribute(attn_mma_kernel, cudaFuncAttributeMaxDynamicSharedMemorySize, ATTN_SMEM);
    cudaFuncSetAttribute(outproj_mma_kernel, cudaFuncAttributeMaxDynamicSharedMemorySize, OP_SMEM);

    prep_kernel<<<PREP_TOT / 256, 256>>>(x, Wq, Wk, Wv, Wo);

    dim3 g1(NTOK / 128, 3 * EMB / 128);   // (32, 24)
    qkv_mma_kernel<<<g1, 256, QKV_SMEM>>>();

    dim3 g2(TSEQ / 128, NHEAD, NBATCH);
    attn_mma_kernel<<<g2, 256, ATTN_SMEM>>>();

    dim3 g3(NTOK / 128, EMB / 128);
    outproj_mma_kernel<<<g3, 256, OP_SMEM>>>(x, out);
}

// round 16
// speedup vs baseline: 3.6962x; 1.1036x over previous
#include <cuda_runtime.h>
#include <cuda_fp16.h>
#include <math.h>
#include <stdint.h>

#define NBATCH 2
#define TSEQ   2048
#define EMB    1024
#define NHEAD  16
#define HDIM   64
#define NTOK   (NBATCH*TSEQ)   // 4096

// ---------------------------------------------------------------------------
// Persistent hi/lo half scratch (allocation-free)
// ---------------------------------------------------------------------------
__device__ __half g_xh[NTOK*EMB],  g_xl[NTOK*EMB];                 // x split
__device__ __half g_wh[3*NHEAD*EMB*HDIM], g_wl[3*NHEAD*EMB*HDIM]; // Wq|Wk|Wv split
__device__ __half g_woh[EMB*EMB], g_wol[EMB*EMB];                 // Wo split
__device__ __half g_qh[NBATCH*NHEAD*TSEQ*HDIM], g_ql[NBATCH*NHEAD*TSEQ*HDIM];
__device__ __half g_kh[NBATCH*NHEAD*TSEQ*HDIM], g_kl[NBATCH*NHEAD*TSEQ*HDIM];
__device__ __half g_vh[NBATCH*NHEAD*TSEQ*HDIM];
__device__ __half g_ch[NTOK*EMB];                                  // attn combined (f16 only)

// ===========================================================================
// Helpers
// ===========================================================================
__device__ __forceinline__ uint32_t smem_u32(const void* p) {
    uint32_t a;
    asm("{ .reg .u64 t; cvta.to.shared.u64 t, %1; cvt.u32.u64 %0, t; }" : "=r"(a) : "l"(p));
    return a;
}
#define CP_ASYNC16(dst, src) asm volatile("cp.async.cg.shared.global [%0], [%1], 16;" :: "r"(dst), "l"(src))
#define CP_COMMIT()          asm volatile("cp.async.commit_group;" ::: "memory")
#define CP_WAIT0()           asm volatile("cp.async.wait_group 0;" ::: "memory")
#define CP_WAIT1()           asm volatile("cp.async.wait_group 1;" ::: "memory")

__device__ __forceinline__ void mma_f16(float* d, const uint32_t* a, const uint32_t* b) {
    asm volatile("mma.sync.aligned.m16n8k16.row.col.f32.f16.f16.f32 "
        "{%0,%1,%2,%3}, {%4,%5,%6,%7}, {%8,%9}, {%0,%1,%2,%3};"
        : "+f"(d[0]), "+f"(d[1]), "+f"(d[2]), "+f"(d[3])
        : "r"(a[0]), "r"(a[1]), "r"(a[2]), "r"(a[3]), "r"(b[0]), "r"(b[1]));
}
__device__ __forceinline__ void ldsm4(uint32_t* r, uint32_t a) {
    asm volatile("ldmatrix.sync.aligned.m8n8.x4.shared.b16 {%0,%1,%2,%3}, [%4];"
        : "=r"(r[0]), "=r"(r[1]), "=r"(r[2]), "=r"(r[3]) : "r"(a));
}
__device__ __forceinline__ void ldsm4t(uint32_t* r, uint32_t a) {
    asm volatile("ldmatrix.sync.aligned.m8n8.x4.trans.shared.b16 {%0,%1,%2,%3}, [%4];"
        : "=r"(r[0]), "=r"(r[1]), "=r"(r[2]), "=r"(r[3]) : "r"(a));
}
__device__ __forceinline__ uint32_t pack_h2(float a, float b) {
    __half2 h = __floats2half2_rn(a, b);
    return *(uint32_t*)&h;
}
__device__ __forceinline__ void split_wr2(float a, float b, __half* ph, __half* pl) {
    __half ha = __float2half_rn(a), hb = __float2half_rn(b);
    __half la = __float2half_rn(a - __half2float(ha));
    __half lb = __float2half_rn(b - __half2float(hb));
    *(uint32_t*)ph = ((uint32_t)__half_as_ushort(hb) << 16) | (uint32_t)__half_as_ushort(ha);
    *(uint32_t*)pl = ((uint32_t)__half_as_ushort(lb) << 16) | (uint32_t)__half_as_ushort(la);
}
// exp2 on fma pipe (no MUFU); valid for y <= 0
__device__ __forceinline__ float exp2p(float y) {
    y = fmaxf(y, -126.f);
    float r = rintf(y);
    float f = y - r;
    float p = fmaf(f, 1.3333558146e-3f, 9.6181291076e-3f);
    p = fmaf(f, p, 5.5504108664e-2f);
    p = fmaf(f, p, 2.4022650696e-1f);
    p = fmaf(f, p, 6.9314718056e-1f);
    p = fmaf(f, p, 1.0f);
    int n = (int)r;
    return p * __int_as_float((n + 127) << 23);
}

#define QSC 0.18033688011112042f  // 0.125 * log2(e)
#define SGS 72                    // shared stride (halves) for 64-wide k tiles

// ---------------------------------------------------------------------------
// Kernel 0: prep — split x, Wq/Wk/Wv, Wo into hi/lo halves
// ---------------------------------------------------------------------------
#define PREP_NX2  (NTOK*EMB/2)
#define PREP_NW2  (NHEAD*EMB*HDIM/2)
#define PREP_NWO2 (EMB*EMB/2)
#define PREP_TOT  (PREP_NX2 + 3*PREP_NW2 + PREP_NWO2)

__device__ __forceinline__ void split2_store(const float* s, __half* h, __half* l, int i2) {
    float2 v = ((const float2*)s)[i2];
    __half2 hv = __floats2half2_rn(v.x, v.y);
    float2 hr = __half22float2(hv);
    __half2 lv = __floats2half2_rn(v.x - hr.x, v.y - hr.y);
    ((__half2*)h)[i2] = hv;
    ((__half2*)l)[i2] = lv;
}

__global__ __launch_bounds__(256) void prep_kernel(
    const float* __restrict__ x, const float* __restrict__ Wq,
    const float* __restrict__ Wk, const float* __restrict__ Wv,
    const float* __restrict__ Wo)
{
    int idx = blockIdx.x * 256 + threadIdx.x;
    if (idx < PREP_NX2) { split2_store(x, g_xh, g_xl, idx); return; }
    idx -= PREP_NX2;
    if (idx < PREP_NW2) { split2_store(Wq, g_wh, g_wl, idx); return; }
    idx -= PREP_NW2;
    if (idx < PREP_NW2) { split2_store(Wk, g_wh + NHEAD*EMB*HDIM, g_wl + NHEAD*EMB*HDIM, idx); return; }
    idx -= PREP_NW2;
    if (idx < PREP_NW2) { split2_store(Wv, g_wh + 2*NHEAD*EMB*HDIM, g_wl + 2*NHEAD*EMB*HDIM, idx); return; }
    idx -= PREP_NW2;
    if (idx < PREP_NWO2) split2_store(Wo, g_woh, g_wol, idx);
}

// ---------------------------------------------------------------------------
// Kernel 1: FUSED QKV projection [4096 x 1024] @ [1024 x 3072].
// grid=(32,24), 256 thr, block 128x128, warp 64x32. 3-stage ring, 1 sync/chunk.
// ---------------------------------------------------------------------------
#define FQ_KC   32
#define FQ_NCH  (EMB / FQ_KC)    // 32
#define BA_AL   10240            // byte offsets within buffer
#define BA_BH   20480
#define BA_BL   29184
#define FQ_BUFB 37888
#define QKV_SMEM (3 * FQ_BUFB)   // 113664 B

__device__ __forceinline__ void fqkv_stage(uint32_t sbuf,
    const __half* wbh, const __half* wbl,
    int m0, int k0, int tid, bool need_alo)
{
    #pragma unroll
    for (int j = 0; j < 2; j++) {           // A hi: 512 cp (128 rows x 4)
        int idx = j * 256 + tid;
        int r = idx >> 2, q = idx & 3;
        CP_ASYNC16(sbuf + (uint32_t)(r*40 + q*8)*2,
                   g_xh + (size_t)(m0 + r)*EMB + k0 + q*8);
    }
    if (need_alo) {
        #pragma unroll
        for (int j = 0; j < 2; j++) {       // A lo
            int idx = j * 256 + tid;
            int r = idx >> 2, q = idx & 3;
            CP_ASYNC16(sbuf + BA_AL + (uint32_t)(r*40 + q*8)*2,
                       g_xl + (size_t)(m0 + r)*EMB + k0 + q*8);
        }
    }
    #pragma unroll
    for (int j = 0; j < 2; j++) {           // B: 32 k-rows x 128 n
        int idx = j * 256 + tid;
        int k = idx >> 4, c = (idx & 15) * 8;
        size_t src = (size_t)(c >> 6) * (EMB*HDIM) + (size_t)(k0 + k)*HDIM + (c & 63);
        CP_ASYNC16(sbuf + BA_BH + (uint32_t)(k*136 + c)*2, wbh + src);
        CP_ASYNC16(sbuf + BA_BL + (uint32_t)(k*136 + c)*2, wbl + src);
    }
    CP_COMMIT();
}

__global__ __launch_bounds__(256, 2) void qkv_mma_kernel()
{
    extern __shared__ __align__(16) char sm[];
    const uint32_t sb = smem_u32(sm);
    const int tid = threadIdx.x;
    const int lane = tid & 31, wid = tid >> 5;
    const int gid = lane >> 2, tig = lane & 3;
    const int warp_m = wid >> 2;       // 0..1 (64 rows)
    const int warp_n = wid & 3;        // 0..3 (32 cols)
    const int m0 = blockIdx.x * 128;
    const int n0 = blockIdx.y * 128;
    const int which = n0 >> 10;
    const bool three_pass = (which != 2);

    const __half* wbh = g_wh + (size_t)(n0 >> 6) * (EMB*HDIM);
    const __half* wbl = g_wl + (size_t)(n0 >> 6) * (EMB*HDIM);

    const int offA  = ((lane & 7) + ((lane >> 3) & 1) * 8) * 40  + (lane >> 4) * 8;
    const int offBt = ((lane & 7) + ((lane >> 3) & 1) * 8) * 136 + (lane >> 4) * 8;

    float acc[4][4][4];
    #pragma unroll
    for (int mt = 0; mt < 4; mt++)
        #pragma unroll
        for (int nt = 0; nt < 4; nt++)
            #pragma unroll
            for (int e = 0; e < 4; e++) acc[mt][nt][e] = 0.f;

    fqkv_stage(sb, wbh, wbl, m0, 0, tid, three_pass);
    fqkv_stage(sb + FQ_BUFB, wbh, wbl, m0, FQ_KC, tid, three_pass);

    for (int ch = 0; ch < FQ_NCH; ch++) {
        if (ch + 1 < FQ_NCH) CP_WAIT1(); else CP_WAIT0();
        __syncthreads();
        if (ch + 2 < FQ_NCH)
            fqkv_stage(sb + ((ch + 2) % 3) * FQ_BUFB, wbh, wbl, m0, (ch + 2) * FQ_KC, tid, three_pass);

        const uint32_t bb = sb + (ch % 3) * FQ_BUFB;
        #pragma unroll
        for (int ks = 0; ks < 2; ks++) {
            uint32_t ahf[4][4], alf[4][4];
            #pragma unroll
            for (int mt = 0; mt < 4; mt++) {
                uint32_t ao = (uint32_t)(offA + (warp_m*64 + mt*16)*40 + ks*16) * 2;
                ldsm4(ahf[mt], bb + ao);
                if (three_pass) ldsm4(alf[mt], bb + BA_AL + ao);
            }
            #pragma unroll
            for (int ntp = 0; ntp < 2; ntp++) {
                uint32_t bhf[4], blf[4];
                uint32_t bo = (uint32_t)(offBt + (ks*16)*136 + warp_n*32 + ntp*16) * 2;
                ldsm4t(bhf, bb + BA_BH + bo);
                ldsm4t(blf, bb + BA_BL + bo);
                #pragma unroll
                for (int mt = 0; mt < 4; mt++) {
                    mma_f16(acc[mt][ntp*2],   ahf[mt], bhf);
                    mma_f16(acc[mt][ntp*2],   ahf[mt], blf);
                    if (three_pass) mma_f16(acc[mt][ntp*2], alf[mt], bhf);
                    mma_f16(acc[mt][ntp*2+1], ahf[mt], bhf + 2);
                    mma_f16(acc[mt][ntp*2+1], ahf[mt], blf + 2);
                    if (three_pass) mma_f16(acc[mt][ntp*2+1], alf[mt], bhf + 2);
                }
            }
        }
    }

    // epilogue: decode (which, h, d) from global column; Q scaled by QSC
    const float scale = (which == 0) ? QSC : 1.0f;
    #pragma unroll
    for (int mt = 0; mt < 4; mt++)
        #pragma unroll
        for (int nt = 0; nt < 4; nt++) {
            int ng = n0 + warp_n * 32 + nt * 8 + 2 * tig;
            int hh = (ng >> 6) & 15, d = ng & 63;
            #pragma unroll
            for (int half = 0; half < 2; half++) {
                int m = m0 + warp_m * 64 + mt * 16 + gid + half * 8;
                int b = m >> 11, t = m & (TSEQ - 1);
                size_t o0 = ((size_t)((b * NHEAD + hh) * TSEQ + t)) * HDIM + d;
                float v0 = acc[mt][nt][half*2]   * scale;
                float v1 = acc[mt][nt][half*2+1] * scale;
                if (which == 0)      split_wr2(v0, v1, g_qh + o0, g_ql + o0);
                else if (which == 1) split_wr2(v0, v1, g_kh + o0, g_kl + o0);
                else                 *(uint32_t*)(g_vh + o0) = pack_h2(v0, v1);
            }
        }
}

// ---------------------------------------------------------------------------
// Kernel 2: flash attention. grid=(16,16,2), 256 thr (8 warps x 16 rows).
// QK^T 3-pass; PV 1-pass. 3-stage KV ring (1 sync/tile), 2 CTAs/SM.
// Buffer (bytes): Kh@0 Kl@9216 Vh@18432; BUFB=27648; 3 buffers = 82944.
// Q staged transiently in buffers 0..1 region, extracted to regs pre-loop.
// ---------------------------------------------------------------------------
#define AS 72
#define AT_BUFB 27648
#define ATTN_SMEM (3 * AT_BUFB)   // 82944

__device__ __forceinline__ void attn_stage_kv(uint32_t sb,
    const __half* Kh, const __half* Kl, const __half* Vh,
    int kt, int tid)
{
    uint32_t bbuf = sb + (uint32_t)(kt % 3) * AT_BUFB;
    #pragma unroll
    for (int j = 0; j < 2; j++) {
        int idx = j * 256 + tid;           // 512 per array (64 rows x 8)
        int r = idx >> 3, q = idx & 7;
        uint32_t d = (uint32_t)(r * AS + q * 8) * 2;
        size_t s = (size_t)(kt * 64 + r) * HDIM + q * 8;
        CP_ASYNC16(bbuf + d,         Kh + s);
        CP_ASYNC16(bbuf + 9216 + d,  Kl + s);
        CP_ASYNC16(bbuf + 18432 + d, Vh + s);
    }
    CP_COMMIT();
}

__global__ __launch_bounds__(256, 2) void attn_mma_kernel()
{
    extern __shared__ __align__(16) char sm[];
    const uint32_t sb = smem_u32(sm);
    const int tid = threadIdx.x;
    const int lane = tid & 31, wid = tid >> 5;
    const int gid = lane >> 2, tig = lane & 3;
    const int qt = blockIdx.x, h = blockIdx.y, b = blockIdx.z;
    const size_t base = (size_t)((b * NHEAD + h) * TSEQ) * HDIM;
    const __half* Qh = g_qh + base; const __half* Ql = g_ql + base;
    const __half* Kh = g_kh + base; const __half* Kl = g_kl + base;
    const __half* Vh = g_vh + base;

    const int offQ = ((lane & 7) + ((lane >> 3) & 1) * 8) * AS + (lane >> 4) * 8; // A & trans-B
    const int offK = ((lane & 7) + (lane >> 4) * 8) * AS + ((lane >> 3) & 1) * 8; // non-trans B

    // prologue: stage Q halves into buffer region (Qh@0, Ql@18432), extract, recycle
    #pragma unroll
    for (int j = 0; j < 4; j++) {
        int idx = j * 256 + tid;           // 1024 per array (128 rows x 8)
        int r = idx >> 3, q = idx & 7;
        uint32_t d = (uint32_t)(r * AS + q * 8) * 2;
        size_t s = (size_t)(qt * 128 + r) * HDIM + q * 8;
        CP_ASYNC16(sb + d,         Qh + s);
        CP_ASYNC16(sb + 18432 + d, Ql + s);
    }
    CP_COMMIT();
    CP_WAIT0();
    __syncthreads();

    uint32_t qf_h[4][4], qf_l[4][4];
    #pragma unroll
    for (int ks = 0; ks < 4; ks++) {
        uint32_t ao = (uint32_t)(offQ + (wid * 16) * AS + ks * 16) * 2;
        ldsm4(qf_h[ks], sb + ao);
        ldsm4(qf_l[ks], sb + 18432 + ao);
    }
    __syncthreads();   // all warps done reading Q region; buffers reusable

    attn_stage_kv(sb, Kh, Kl, Vh, 0, tid);
    attn_stage_kv(sb, Kh, Kl, Vh, 1, tid);

    float o[8][4];
    #pragma unroll
    for (int nt = 0; nt < 8; nt++)
        #pragma unroll
        for (int e = 0; e < 4; e++) o[nt][e] = 0.f;
    float mr0 = -1e30f, mr1 = -1e30f, l0 = 0.f, l1 = 0.f;

    const int NT = TSEQ / 64;   // 32
    for (int kt = 0; kt < NT; kt++) {
        if (kt + 1 < NT) CP_WAIT1(); else CP_WAIT0();
        __syncthreads();
        if (kt + 2 < NT) attn_stage_kv(sb, Kh, Kl, Vh, kt + 2, tid);

        const uint32_t kb = sb + (uint32_t)(kt % 3) * AT_BUFB;

        // S = Q K^T (3-pass f16), log2 units
        float s[8][4];
        #pragma unroll
        for (int nt = 0; nt < 8; nt++)
            #pragma unroll
            for (int e = 0; e < 4; e++) s[nt][e] = 0.f;

        #pragma unroll
        for (int ks = 0; ks < 4; ks++) {
            #pragma unroll
            for (int ntp = 0; ntp < 4; ntp++) {
                uint32_t bh[4], bl[4];
                uint32_t ao = (uint32_t)(offK + (ntp * 16) * AS + ks * 16) * 2;
                ldsm4(bh, kb + ao);
                ldsm4(bl, kb + 9216 + ao);
                mma_f16(s[ntp*2],   qf_h[ks], bh);
                mma_f16(s[ntp*2],   qf_h[ks], bl);
                mma_f16(s[ntp*2],   qf_l[ks], bh);
                mma_f16(s[ntp*2+1], qf_h[ks], bh + 2);
                mma_f16(s[ntp*2+1], qf_h[ks], bl + 2);
                mma_f16(s[ntp*2+1], qf_l[ks], bh + 2);
            }
        }

        // online softmax (rows gid, gid+8)
        float tm0 = -1e30f, tm1 = -1e30f;
        #pragma unroll
        for (int nt = 0; nt < 8; nt++) {
            tm0 = fmaxf(tm0, fmaxf(s[nt][0], s[nt][1]));
            tm1 = fmaxf(tm1, fmaxf(s[nt][2], s[nt][3]));
        }
        tm0 = fmaxf(tm0, __shfl_xor_sync(0xffffffffu, tm0, 1));
        tm0 = fmaxf(tm0, __shfl_xor_sync(0xffffffffu, tm0, 2));
        tm1 = fmaxf(tm1, __shfl_xor_sync(0xffffffffu, tm1, 1));
        tm1 = fmaxf(tm1, __shfl_xor_sync(0xffffffffu, tm1, 2));
        float mn0 = fmaxf(mr0, tm0), mn1 = fmaxf(mr1, tm1);
        float al0 = exp2p(mr0 - mn0), al1 = exp2p(mr1 - mn1);
        mr0 = mn0; mr1 = mn1;

        float rs0 = 0.f, rs1 = 0.f;
        #pragma unroll
        for (int nt = 0; nt < 8; nt++) {
            s[nt][0] = exp2p(s[nt][0] - mn0);
            s[nt][1] = exp2p(s[nt][1] - mn0);
            s[nt][2] = exp2p(s[nt][2] - mn1);
            s[nt][3] = exp2p(s[nt][3] - mn1);
            rs0 += s[nt][0] + s[nt][1];
            rs1 += s[nt][2] + s[nt][3];
        }
        rs0 += __shfl_xor_sync(0xffffffffu, rs0, 1);
        rs0 += __shfl_xor_sync(0xffffffffu, rs0, 2);
        rs1 += __shfl_xor_sync(0xffffffffu, rs1, 1);
        rs1 += __shfl_xor_sync(0xffffffffu, rs1, 2);
        l0 = l0 * al0 + rs0;
        l1 = l1 * al1 + rs1;
        #pragma unroll
        for (int nt = 0; nt < 8; nt++) {
            o[nt][0] *= al0; o[nt][1] *= al0;
            o[nt][2] *= al1; o[nt][3] *= al1;
        }

        // O += P V (1-pass: P_hi x V_hi); P packed in registers
        #pragma unroll
        for (int ks = 0; ks < 4; ks++) {
            uint32_t ah[4];
            ah[0] = pack_h2(s[2*ks][0],   s[2*ks][1]);
            ah[1] = pack_h2(s[2*ks][2],   s[2*ks][3]);
            ah[2] = pack_h2(s[2*ks+1][0], s[2*ks+1][1]);
            ah[3] = pack_h2(s[2*ks+1][2], s[2*ks+1][3]);
            #pragma unroll
            for (int dtp = 0; dtp < 4; dtp++) {
                uint32_t bh[4];
                uint32_t ao = (uint32_t)(offQ + (ks * 16) * AS + dtp * 16) * 2;
                ldsm4t(bh, kb + 18432 + ao);
                mma_f16(o[dtp*2],   ah, bh);
                mma_f16(o[dtp*2+1], ah, bh + 2);
            }
        }
    }

    // epilogue: normalize, write combined C as f16 (hi only)
    float inv0 = 1.f / l0, inv1 = 1.f / l1;
    int t0 = qt * 128 + wid * 16 + gid;
    #pragma unroll
    for (int nt = 0; nt < 8; nt++) {
        int col = h * HDIM + nt * 8 + 2 * tig;
        size_t o0 = (size_t)(b * TSEQ + t0) * EMB + col;
        size_t o1 = (size_t)(b * TSEQ + t0 + 8) * EMB + col;
        *(uint32_t*)(g_ch + o0) = pack_h2(o[nt][0] * inv0, o[nt][1] * inv0);
        *(uint32_t*)(g_ch + o1) = pack_h2(o[nt][2] * inv1, o[nt][3] * inv1);
    }
}

// ---------------------------------------------------------------------------
// Kernel 3: out = x + C @ Wo^T. grid=(32,8), 256 thr, block 128x128.
// Warp 64x32. 2-pass (C_hi x Wo_hi + C_hi x Wo_lo). Unchanged from R15.
// ---------------------------------------------------------------------------
#define OP_KC   64
#define OP_NCH  (EMB / OP_KC)    // 16
#define OP_BH   9216
#define OP_BL   18432
#define OP_BUFH 27648
#define OP_SMEM (2*OP_BUFH*2)    // 110592

__device__ __forceinline__ void op_stage(uint32_t sbuf, int m0, int n0, int k0, int tid) {
    #pragma unroll
    for (int j = 0; j < 4; j++) {           // A: 1024 cp (128 rows x 8)
        int idx = j * 256 + tid;
        int r = idx >> 3, q = idx & 7;
        CP_ASYNC16(sbuf + (uint32_t)(r*SGS + q*8)*2,
                   g_ch + (size_t)(m0 + r)*EMB + k0 + q*8);
    }
    #pragma unroll
    for (int j = 0; j < 4; j++) {           // B hi: 1024 cp (128 n-rows x 8)
        int idx = j * 256 + tid;
        int r = idx >> 3, q = idx & 7;
        CP_ASYNC16(sbuf + (uint32_t)(OP_BH + r*SGS + q*8)*2,
                   g_woh + (size_t)(n0 + r)*EMB + k0 + q*8);
    }
    #pragma unroll
    for (int j = 0; j < 4; j++) {           // B lo
        int idx = j * 256 + tid;
        int r = idx >> 3, q = idx & 7;
        CP_ASYNC16(sbuf + (uint32_t)(OP_BL + r*SGS + q*8)*2,
                   g_wol + (size_t)(n0 + r)*EMB + k0 + q*8);
    }
    CP_COMMIT();
}

__global__ __launch_bounds__(256, 2) void outproj_mma_kernel(
    const float* __restrict__ x, float* __restrict__ out)
{
    extern __shared__ __align__(16) char sm[];
    const uint32_t sb = smem_u32(sm);
    const int tid = threadIdx.x;
    const int lane = tid & 31, wid = tid >> 5;
    const int gid = lane >> 2, tig = lane & 3;
    const int warp_m = wid >> 2;
    const int warp_n = wid & 3;
    const int m0 = blockIdx.x * 128, n0 = blockIdx.y * 128;

    const int offA = ((lane & 7) + ((lane >> 3) & 1) * 8) * SGS + (lane >> 4) * 8;
    const int offB = ((lane & 7) + (lane >> 4) * 8) * SGS + ((lane >> 3) & 1) * 8;

    float acc[4][4][4];
    #pragma unroll
    for (int mt = 0; mt < 4; mt++)
        #pragma unroll
        for (int nt = 0; nt < 4; nt++)
            #pragma unroll
            for (int e = 0; e < 4; e++) acc[mt][nt][e] = 0.f;

    op_stage(sb, m0, n0, 0, tid);

    for (int ch = 0; ch < OP_NCH; ch++) {
        if (ch + 1 < OP_NCH) {
            op_stage(sb + ((ch + 1) & 1) * OP_BUFH * 2, m0, n0, (ch + 1) * OP_KC, tid);
            CP_WAIT1();
        } else {
            CP_WAIT0();
        }
        __syncthreads();

        const uint32_t bb = sb + (ch & 1) * OP_BUFH * 2;
        #pragma unroll
        for (int ks = 0; ks < 4; ks++) {
            uint32_t af[4][4];
            #pragma unroll
            for (int mt = 0; mt < 4; mt++) {
                uint32_t ao = (uint32_t)(offA + (warp_m*64 + mt*16)*SGS + ks*16) * 2;
                ldsm4(af[mt], bb + ao);
            }
            #pragma unroll
            for (int ntp = 0; ntp < 2; ntp++) {
                uint32_t bhf[4], blf[4];
                uint32_t bo = (uint32_t)(offB + (warp_n*32 + ntp*16)*SGS + ks*16) * 2;
                ldsm4(bhf, bb + OP_BH*2 + bo);
                ldsm4(blf, bb + OP_BL*2 + bo);
                #pragma unroll
                for (int mt = 0; mt < 4; mt++) {
                    mma_f16(acc[mt][ntp*2],   af[mt], bhf);
                    mma_f16(acc[mt][ntp*2],   af[mt], blf);
                    mma_f16(acc[mt][ntp*2+1], af[mt], bhf + 2);
                    mma_f16(acc[mt][ntp*2+1], af[mt], blf + 2);
                }
            }
        }
        __syncthreads();
    }

    #pragma unroll
    for (int mt = 0; mt < 4; mt++)
        #pragma unroll
        for (int nt = 0; nt < 4; nt++) {
            int n = n0 + warp_n * 32 + nt * 8 + tig * 2;
            int m = m0 + warp_m * 64 + mt * 16 + gid;
            {
                size_t off = (size_t)m * EMB + n;
                float2 xv = *(const float2*)&x[off];
                *(float2*)&out[off] = make_float2(acc[mt][nt][0] + xv.x, acc[mt][nt][1] + xv.y);
            }
            {
                size_t off = (size_t)(m + 8) * EMB + n;
                float2 xv = *(const float2*)&x[off];
                *(float2*)&out[off] = make_float2(acc[mt][nt][2] + xv.x, acc[mt][nt][3] + xv.y);
            }
        }
}

extern "C" void kernel_launch(void* const* d_in, const int* in_sizes, int n_in,
                              void* d_out, int out_size)
{
    const float* x  = (const float*)d_in[0];
    const float* Wq = (const float*)d_in[1];
    const float* Wk = (const float*)d_in[2];
    const float* Wv = (const float*)d_in[3];
    const float* Wo = (const float*)d_in[4];
    float* out = (float*)d_out;

    cudaFuncSetAttribute(qkv_mma_kernel, cudaFuncAttributeMaxDynamicSharedMemorySize, QKV_SMEM);
    cudaFuncSetAttribute(attn_mma_kernel, cudaFuncAttributeMaxDynamicSharedMemorySize, ATTN_SMEM);
    cudaFuncSetAttribute(outproj_mma_kernel, cudaFuncAttributeMaxDynamicSharedMemorySize, OP_SMEM);

    prep_kernel<<<PREP_TOT / 256, 256>>>(x, Wq, Wk, Wv, Wo);

    dim3 g1(NTOK / 128, 3 * EMB / 128);   // (32, 24)
    qkv_mma_kernel<<<g1, 256, QKV_SMEM>>>();

    dim3 g2(TSEQ / 128, NHEAD, NBATCH);
    attn_mma_kernel<<<g2, 256, ATTN_SMEM>>>();

    dim3 g3(NTOK / 128, EMB / 128);
    outproj_mma_kernel<<<g3, 256, OP_SMEM>>>(x, out);
}